// round 4
// baseline (speedup 1.0000x reference)
#include <cuda_runtime.h>
#include <math.h>

#define NV 16

// ---------------- device scratch ----------------
__device__ float g_avg[512 * 16];      // mean over batch (SEQ, NV)
__device__ float g_pm[240];            // parent_mask [v][p]
__device__ float g_hp[16];             // has_parents per v
__device__ float g_part[240 * 16];     // pair partial sums [pair][chunk]

// packed f32x2 FMA
union F2U { float2 f; unsigned long long u; };
__device__ __forceinline__ float2 ffma2(float2 a, float2 b, float2 c) {
    F2U au, bu, cu, du;
    au.f = a; bu.f = b; cu.f = c;
    asm("fma.rn.f32x2 %0, %1, %2, %3;" : "=l"(du.u) : "l"(au.u), "l"(bu.u), "l"(cu.u));
    return du.f;
}

// ---------------- Kernel A1: avg over batch ----------------
__global__ void k_avg(const float* __restrict__ data) {
    int t = blockIdx.x * 64 + threadIdx.x;   // 2048 float4 slots
    float4 s = make_float4(0.f, 0.f, 0.f, 0.f);
#pragma unroll
    for (int b = 0; b < 16; b++) {
        float4 v = *(const float4*)(data + b * 8192 + t * 4);
        s.x += v.x; s.y += v.y; s.z += v.z; s.w += v.w;
    }
    s.x *= (1.f/16.f); s.y *= (1.f/16.f); s.z *= (1.f/16.f); s.w *= (1.f/16.f);
    *(float4*)(g_avg + t * 4) = s;
}

// ---------------- Kernel A2: cov -> corr -> MLP -> adj -> masks ----------------
__global__ void __launch_bounds__(1024) k_adj(
    const float* __restrict__ Ws1, const float* __restrict__ bs1,
    const float* __restrict__ Ws2, const float* __restrict__ bs2,
    const float* __restrict__ Ws3, const float* __restrict__ bs3,
    float* __restrict__ out_adj)
{
    __shared__ float av[8192];
    __shared__ float scratch[1024];
    __shared__ float cm[16];
    __shared__ float covs[256];
    __shared__ float corr_s[256];
    __shared__ float h1s[256];
    __shared__ float h2s[128];
    __shared__ float adj_s[256];
    __shared__ float pms[240];

    int tid = threadIdx.x;
    for (int i = tid; i < 2048; i += 1024)
        *(float4*)(av + i * 4) = *(const float4*)(g_avg + i * 4);
    __syncthreads();

    if (tid < 512) {
        int j = tid & 15, part = tid >> 4;
        float s = 0.f;
        for (int r = 0; r < 16; r++) s += av[(part * 16 + r) * 16 + j];
        scratch[tid] = s;
    }
    __syncthreads();
    if (tid < 16) {
        float s = 0.f;
        for (int part = 0; part < 32; part++) s += scratch[part * 16 + tid];
        cm[tid] = s * (1.f / 512.f);
    }
    __syncthreads();

    {
        int pair = tid >> 2, q = tid & 3;
        int i = pair >> 4, j = pair & 15;
        float ci = cm[i], cj = cm[j];
        float s = 0.f;
        for (int r = q * 128; r < q * 128 + 128; r++)
            s += (av[r * 16 + i] - ci) * (av[r * 16 + j] - cj);
        scratch[tid] = s;
    }
    __syncthreads();
    if (tid < 256)
        covs[tid] = scratch[tid*4] + scratch[tid*4+1] + scratch[tid*4+2] + scratch[tid*4+3];
    __syncthreads();
    if (tid < 256) {
        int i = tid >> 4, j = tid & 15;
        float si = sqrtf(fmaxf(covs[i * 16 + i], 0.f));
        float sj = sqrtf(fmaxf(covs[j * 16 + j], 0.f));
        float denom = si * sj;
        float c = denom > 0.f ? covs[tid] / denom : 0.f;
        c = fabsf(c);
        if (i == j) c = 0.f;
        corr_s[tid] = c;
    }
    __syncthreads();

    {
        int o = tid & 255, q = tid >> 8;
        float s = 0.f;
        for (int k = q * 64; k < q * 64 + 64; k++) s = fmaf(corr_s[k], Ws1[k * 256 + o], s);
        scratch[q * 256 + o] = s;
    }
    __syncthreads();
    if (tid < 256)
        h1s[tid] = fmaxf(scratch[tid] + scratch[256 + tid] + scratch[512 + tid] + scratch[768 + tid] + bs1[tid], 0.f);
    __syncthreads();

    {
        int o = tid & 127, q = tid >> 7;
        float s = 0.f;
        for (int k = q * 32; k < q * 32 + 32; k++) s = fmaf(h1s[k], Ws2[k * 128 + o], s);
        scratch[q * 128 + o] = s;
    }
    __syncthreads();
    if (tid < 128) {
        float s = bs2[tid];
        for (int q = 0; q < 8; q++) s += scratch[q * 128 + tid];
        h2s[tid] = fmaxf(s, 0.f);
    }
    __syncthreads();

    {
        int o = tid & 255, q = tid >> 8;
        float s = 0.f;
        for (int k = q * 32; k < q * 32 + 32; k++) s = fmaf(h2s[k], Ws3[k * 256 + o], s);
        scratch[q * 256 + o] = s;
    }
    __syncthreads();
    if (tid < 256) {
        float logit = scratch[tid] + scratch[256 + tid] + scratch[512 + tid] + scratch[768 + tid] + bs3[tid];
        float a = 1.f / (1.f + expf(-logit));
        int i = tid >> 4, j = tid & 15;
        float val = (j > i) ? a : 0.f;
        adj_s[tid] = val;
        out_adj[tid] = val;
    }
    __syncthreads();
    if (tid < 240) {
        int v = tid / 15, p = tid - v * 15;
        int g = p + (p >= v ? 1 : 0);
        float m = (adj_s[g * 16 + v] > 0.5f) ? 1.f : 0.f;
        pms[tid] = m;
        g_pm[tid] = m;
    }
    __syncthreads();
    if (tid < 16) {
        float s = 0.f;
        for (int p = 0; p < 15; p++) s += pms[tid * 15 + p];
        g_hp[tid] = (s > 0.f) ? 1.f : 0.f;
    }
}

// ---------------- Kernel B: mechanism MLP (sample-pair packed FFMA2) ----------------
// grid (32,16), 256 thr (8 warps). Warp does 4 samples/iter, 8 iters (block: 256 samples).
// Pack dim = 2 samples; weights duplicated (w,w) in smem once.
// smem floats:
//   W1d  float2[15*128]  @0      (3840 f)
//   W2d  float2[128*64]  @3840   (16384 f)
//   b1d  float2[128]     @20224  (256 f)
//   b2d  float2[64]      @20480  (128 f)
//   w3d  float2[64]      @20608  (128 f)
//   pms  [16]            @20736
//   raw  [8w][64]        @20752  (512 f)
//   inX  float2[8w][32]  @21264  (512 f)   inX[p][sp]
//   h1t  float2[8w][256] @21776  (4096 f)  h1t[sp][c]
// total 25872 floats = 103488 B
__global__ void __launch_bounds__(256, 2) k_mech(
    const float* __restrict__ data,
    const float* __restrict__ Wm1, const float* __restrict__ bm1,
    const float* __restrict__ Wm2, const float* __restrict__ bm2,
    const float* __restrict__ Wm3, const float* __restrict__ bm3,
    float* __restrict__ out_pred)
{
    extern __shared__ float sm[];
    const int v = blockIdx.y;
    float2* W1d = (float2*)(sm);
    float2* W2d = (float2*)(sm + 3840);
    float2* b1d = (float2*)(sm + 20224);
    float2* b2d = (float2*)(sm + 20480);
    float2* w3d = (float2*)(sm + 20608);
    float*  pms = sm + 20736;
    float*  raw = sm + 20752;
    float2* inX = (float2*)(sm + 21264);
    float2* h1t = (float2*)(sm + 21776);

    int tid = threadIdx.x;
    // duplicated weight build
    for (int t = tid; t < 1920; t += 256) {
        float w = Wm1[v * 1920 + t];
        W1d[t] = make_float2(w, w);
    }
    for (int t = tid; t < 2048; t += 256) {
        float4 w4 = *(const float4*)(Wm2 + v * 8192 + t * 4);
        W2d[t * 4 + 0] = make_float2(w4.x, w4.x);
        W2d[t * 4 + 1] = make_float2(w4.y, w4.y);
        W2d[t * 4 + 2] = make_float2(w4.z, w4.z);
        W2d[t * 4 + 3] = make_float2(w4.w, w4.w);
    }
    if (tid < 128) { float b = bm1[v * 128 + tid]; b1d[tid] = make_float2(b, b); }
    if (tid < 64) {
        float b = bm2[v * 64 + tid]; b2d[tid] = make_float2(b, b);
        float w = Wm3[v * 64 + tid]; w3d[tid] = make_float2(w, w);
    }
    if (tid < 15) pms[tid] = g_pm[v * 15 + tid];
    float hp = g_hp[v];
    float b3 = bm3[v];
    __syncthreads();

    int w = tid >> 5, lane = tid & 31;
    float*  rawW = raw + w * 64;     // [4s][16]
    float2* inXW = inX + w * 32;     // [p][sp]
    float2* h1tW = h1t + w * 256;    // [sp][c]

    // hoisted per-lane weights for h3
    float4 w3q = *(float4*)(w3d + 2 * lane);     // (w_k0,w_k0,w_k1,w_k1)
    float2 w3a = make_float2(w3q.x, w3q.y);
    float2 w3b = make_float2(w3q.z, w3q.w);
    float4 b2q = *(float4*)(b2d + 2 * lane);
    float2 b2a = make_float2(b2q.x, b2q.y);
    float2 b2b = make_float2(b2q.z, b2q.w);

    for (int it = 0; it < 8; it++) {
        int base = blockIdx.x * 256 + it * 32 + w * 4;
        if (lane < 16) {    // 4 sample rows
            int s = lane >> 2, q = lane & 3;
            float4 rv = *(const float4*)(data + (base + s) * 16 + q * 4);
            *(float4*)(rawW + s * 16 + q * 4) = rv;
        }
        __syncwarp();
        if (lane < 30) {    // inX[p][sp] = (x[2sp][g]*pm, x[2sp+1][g]*pm)
            int p = lane >> 1, sp = lane & 1;
            int g = p + (p >= v ? 1 : 0);
            float pm = pms[p];
            float x0 = rawW[(2 * sp) * 16 + g] * pm;
            float x1 = rawW[(2 * sp + 1) * 16 + g] * pm;
            inXW[p * 2 + sp] = make_float2(x0, x1);
        }
        __syncwarp();

        // ---- h1: lane owns c in {L, L+32, L+64, L+96} x 2 sample-pairs
        float2 acc[4][2];
#pragma unroll
        for (int m = 0; m < 4; m++) {
            float2 b = b1d[lane + 32 * m];
            acc[m][0] = b; acc[m][1] = b;
        }
#pragma unroll
        for (int p = 0; p < 15; p++) {
            float4 xq = *(float4*)(inXW + p * 2);    // both sample-pairs, broadcast
            float2 x0 = make_float2(xq.x, xq.y);
            float2 x1 = make_float2(xq.z, xq.w);
            const float2* wr = W1d + p * 128;
#pragma unroll
            for (int m = 0; m < 4; m++) {
                float2 wd = wr[lane + 32 * m];
                acc[m][0] = ffma2(wd, x0, acc[m][0]);
                acc[m][1] = ffma2(wd, x1, acc[m][1]);
            }
        }
#pragma unroll
        for (int m = 0; m < 4; m++) {
            int c = lane + 32 * m;
            float2 r0 = make_float2(fmaxf(acc[m][0].x, 0.f), fmaxf(acc[m][0].y, 0.f));
            float2 r1 = make_float2(fmaxf(acc[m][1].x, 0.f), fmaxf(acc[m][1].y, 0.f));
            h1tW[c] = r0;             // sp0 row
            h1tW[128 + c] = r1;       // sp1 row
        }
        __syncwarp();

        // ---- h2: lane owns k = 2L, 2L+1 ; both sample-pairs
        float2 a0[2], a1[2];
        a0[0] = b2a; a0[1] = b2a;
        a1[0] = b2b; a1[1] = b2b;
#pragma unroll 4
        for (int j0 = 0; j0 < 128; j0 += 4) {
            // weights: W2d[j][2L..2L+1] for 4 j
            float4 wq0 = *(float4*)(W2d + (j0 + 0) * 64 + 2 * lane);
            float4 wq1 = *(float4*)(W2d + (j0 + 1) * 64 + 2 * lane);
            float4 wq2 = *(float4*)(W2d + (j0 + 2) * 64 + 2 * lane);
            float4 wq3 = *(float4*)(W2d + (j0 + 3) * 64 + 2 * lane);
            // activations: h1t[sp][j0..j0+3] (broadcast)
            float4 hA = *(float4*)(h1tW + j0);           // sp0: j0,j0+1
            float4 hB = *(float4*)(h1tW + j0 + 2);       // sp0: j0+2,j0+3
            float4 hC = *(float4*)(h1tW + 128 + j0);     // sp1: j0,j0+1
            float4 hD = *(float4*)(h1tW + 128 + j0 + 2); // sp1: j0+2,j0+3
            float2 h0s0 = make_float2(hA.x, hA.y), h1s0 = make_float2(hA.z, hA.w);
            float2 h2s0 = make_float2(hB.x, hB.y), h3s0 = make_float2(hB.z, hB.w);
            float2 h0s1 = make_float2(hC.x, hC.y), h1s1 = make_float2(hC.z, hC.w);
            float2 h2s1 = make_float2(hD.x, hD.y), h3s1 = make_float2(hD.z, hD.w);
            a0[0] = ffma2(make_float2(wq0.x, wq0.y), h0s0, a0[0]);
            a1[0] = ffma2(make_float2(wq0.z, wq0.w), h0s0, a1[0]);
            a0[1] = ffma2(make_float2(wq0.x, wq0.y), h0s1, a0[1]);
            a1[1] = ffma2(make_float2(wq0.z, wq0.w), h0s1, a1[1]);
            a0[0] = ffma2(make_float2(wq1.x, wq1.y), h1s0, a0[0]);
            a1[0] = ffma2(make_float2(wq1.z, wq1.w), h1s0, a1[0]);
            a0[1] = ffma2(make_float2(wq1.x, wq1.y), h1s1, a0[1]);
            a1[1] = ffma2(make_float2(wq1.z, wq1.w), h1s1, a1[1]);
            a0[0] = ffma2(make_float2(wq2.x, wq2.y), h2s0, a0[0]);
            a1[0] = ffma2(make_float2(wq2.z, wq2.w), h2s0, a1[0]);
            a0[1] = ffma2(make_float2(wq2.x, wq2.y), h2s1, a0[1]);
            a1[1] = ffma2(make_float2(wq2.z, wq2.w), h2s1, a1[1]);
            a0[0] = ffma2(make_float2(wq3.x, wq3.y), h3s0, a0[0]);
            a1[0] = ffma2(make_float2(wq3.z, wq3.w), h3s0, a1[0]);
            a0[1] = ffma2(make_float2(wq3.x, wq3.y), h3s1, a0[1]);
            a1[1] = ffma2(make_float2(wq3.z, wq3.w), h3s1, a1[1]);
        }

        // ---- h3: relu, dot w3, reduce over lanes (k)
        float2 part[2];
#pragma unroll
        for (int sp = 0; sp < 2; sp++) {
            float2 r0 = make_float2(fmaxf(a0[sp].x, 0.f), fmaxf(a0[sp].y, 0.f));
            float2 r1 = make_float2(fmaxf(a1[sp].x, 0.f), fmaxf(a1[sp].y, 0.f));
            float2 t = ffma2(r0, w3a, make_float2(0.f, 0.f));
            part[sp] = ffma2(r1, w3b, t);
        }
#pragma unroll
        for (int off = 1; off < 32; off <<= 1) {
            part[0].x += __shfl_xor_sync(0xffffffffu, part[0].x, off);
            part[0].y += __shfl_xor_sync(0xffffffffu, part[0].y, off);
            part[1].x += __shfl_xor_sync(0xffffffffu, part[1].x, off);
            part[1].y += __shfl_xor_sync(0xffffffffu, part[1].y, off);
        }
        if (lane == 0) {
            float vals[4] = { part[0].x, part[0].y, part[1].x, part[1].y };
#pragma unroll
            for (int s = 0; s < 4; s++) {
                float pred = (hp > 0.f) ? (vals[s] + b3) : rawW[s * 16 + v];
                out_pred[(base + s) * 16 + v] = pred;
            }
        }
        __syncwarp();
    }
}

// ---------------- Kernel C: pair scorer (warp-per-pair, lane-per-sample) ----------------
// grid (30 pair-groups, 16 chunks of 512 samples), 256 threads.
__global__ void __launch_bounds__(256) k_pairs(
    const float* __restrict__ data,
    const float* __restrict__ Wt1, const float* __restrict__ bt1,
    const float* __restrict__ Wt2, const float* __restrict__ bt2)
{
    __shared__ float rows[512 * 17];        // padded, conflict-free column reads
    __shared__ float wsm[8][16][8];         // [pairLocal][c2][wa0,wa1,wb0,wb1,b0,b1,w20,w21]
    int tid = threadIdx.x;
    int pg = blockIdx.x, chunk = blockIdx.y;
    int sbase = chunk * 512;
    for (int t = tid; t < 8192; t += 256) {
        int s = t >> 4, j = t & 15;
        rows[s * 17 + j] = data[(sbase + s) * 16 + j];
    }
    {   // weight staging: 8 pairs x 32 channels
        int pl = tid >> 5, c = tid & 31;
        int p = pg * 8 + pl;
        int c2 = c >> 1, o = c & 1;
        wsm[pl][c2][0 + o] = Wt1[p * 64 + c];
        wsm[pl][c2][2 + o] = Wt1[p * 64 + 32 + c];
        wsm[pl][c2][4 + o] = bt1[p * 32 + c];
        wsm[pl][c2][6 + o] = Wt2[p * 32 + c];
    }
    __syncthreads();

    int wl = tid >> 5, lane = tid & 31;
    int p = pg * 8 + wl;
    int pi = p / 15, r = p - pi * 15;
    int pj = r + (r >= pi ? 1 : 0);
    float b2v = bt2[p];
    float accs = 0.f;

#pragma unroll
    for (int win = 0; win < 4; win++) {
        int s0 = win * 128 + lane;
        float2 xi[4], xj[4];
#pragma unroll
        for (int m = 0; m < 4; m++) {
            float a = rows[(s0 + m * 32) * 17 + pi];
            float b = rows[(s0 + m * 32) * 17 + pj];
            xi[m] = make_float2(a, a);
            xj[m] = make_float2(b, b);
        }
        float2 sv[4];
#pragma unroll
        for (int m = 0; m < 4; m++) sv[m] = make_float2(0.f, 0.f);
#pragma unroll
        for (int c2 = 0; c2 < 16; c2++) {
            float4 wv0 = *(float4*)&wsm[wl][c2][0];   // broadcast
            float4 wv1 = *(float4*)&wsm[wl][c2][4];
            float2 wa = make_float2(wv0.x, wv0.y), wb = make_float2(wv0.z, wv0.w);
            float2 bb = make_float2(wv1.x, wv1.y), w2 = make_float2(wv1.z, wv1.w);
#pragma unroll
            for (int m = 0; m < 4; m++) {
                float2 h = ffma2(xi[m], wa, bb);
                h = ffma2(xj[m], wb, h);
                h.x = fmaxf(h.x, 0.f); h.y = fmaxf(h.y, 0.f);
                sv[m] = ffma2(h, w2, sv[m]);
            }
        }
#pragma unroll
        for (int m = 0; m < 4; m++) {
            float tot = sv[m].x + sv[m].y + b2v;
            accs += __fdividef(1.f, 1.f + __expf(-tot));
        }
    }
#pragma unroll
    for (int off = 16; off > 0; off >>= 1)
        accs += __shfl_xor_sync(0xffffffffu, accs, off);
    if (lane == 0) g_part[p * 16 + chunk] = accs;
}

// ---------------- Kernel D: finalize ----------------
__global__ void __launch_bounds__(256) k_fin(float* __restrict__ out_scores) {
    int t = threadIdx.x;
    if (t < 240) {
        const float* b = g_part + t * 16;
        float4 v0 = *(const float4*)(b + 0);
        float4 v1 = *(const float4*)(b + 4);
        float4 v2 = *(const float4*)(b + 8);
        float4 v3 = *(const float4*)(b + 12);
        float s = (v0.x + v0.y + v0.z + v0.w) + (v1.x + v1.y + v1.z + v1.w)
                + (v2.x + v2.y + v2.z + v2.w) + (v3.x + v3.y + v3.z + v3.w);
        int pi = t / 15, r = t - pi * 15;
        int pj = r + (r >= pi ? 1 : 0);
        out_scores[pi * 16 + pj] = s * (1.f / 8192.f);
    }
    if (t < 16) out_scores[t * 17] = 0.f;
}

// ---------------- launch ----------------
extern "C" void kernel_launch(void* const* d_in, const int* in_sizes, int n_in,
                              void* d_out, int out_size) {
    const float* data = (const float*)d_in[0];
    const float* Ws1 = (const float*)d_in[1];
    const float* bs1 = (const float*)d_in[2];
    const float* Ws2 = (const float*)d_in[3];
    const float* bs2 = (const float*)d_in[4];
    const float* Ws3 = (const float*)d_in[5];
    const float* bs3 = (const float*)d_in[6];
    const float* Wm1 = (const float*)d_in[7];
    const float* bm1 = (const float*)d_in[8];
    const float* Wm2 = (const float*)d_in[9];
    const float* bm2 = (const float*)d_in[10];
    const float* Wm3 = (const float*)d_in[11];
    const float* bm3 = (const float*)d_in[12];
    const float* Wt1 = (const float*)d_in[13];
    const float* bt1 = (const float*)d_in[14];
    const float* Wt2 = (const float*)d_in[15];
    const float* bt2 = (const float*)d_in[16];

    float* out = (float*)d_out;
    float* out_adj    = out;
    float* out_pred   = out + 256;
    float* out_scores = out + 256 + 131072;

    cudaFuncSetAttribute(k_mech, cudaFuncAttributeMaxDynamicSharedMemorySize, 103488);

    k_avg<<<32, 64>>>(data);
    k_adj<<<1, 1024>>>(Ws1, bs1, Ws2, bs2, Ws3, bs3, out_adj);
    k_mech<<<dim3(32, 16), 256, 103488>>>(data, Wm1, bm1, Wm2, bm2, Wm3, bm3, out_pred);
    k_pairs<<<dim3(30, 16), 256>>>(data, Wt1, bt1, Wt2, bt2);
    k_fin<<<1, 256>>>(out_scores);
}

// round 5
// speedup vs baseline: 1.4509x; 1.4509x over previous
#include <cuda_runtime.h>
#include <math.h>

#define NV 16

// ---------------- device scratch ----------------
__device__ float g_avg[512 * 16];      // mean over batch (SEQ, NV)
__device__ float g_pm[240];            // parent_mask [v][p]
__device__ float g_hp[16];             // has_parents per v
__device__ float g_part[240 * 128];    // pair partial sums [pair][block]

// packed f32x2 FMA
union F2U { float2 f; unsigned long long u; };
__device__ __forceinline__ float2 ffma2(float2 a, float2 b, float2 c) {
    F2U au, bu, cu, du;
    au.f = a; bu.f = b; cu.f = c;
    asm("fma.rn.f32x2 %0, %1, %2, %3;" : "=l"(du.u) : "l"(au.u), "l"(bu.u), "l"(cu.u));
    return du.f;
}

// ---------------- Kernel A1: avg over batch ----------------
__global__ void k_avg(const float* __restrict__ data) {
    int t = blockIdx.x * 64 + threadIdx.x;   // 2048 float4 slots
    float4 s = make_float4(0.f, 0.f, 0.f, 0.f);
#pragma unroll
    for (int b = 0; b < 16; b++) {
        float4 v = *(const float4*)(data + b * 8192 + t * 4);
        s.x += v.x; s.y += v.y; s.z += v.z; s.w += v.w;
    }
    s.x *= (1.f/16.f); s.y *= (1.f/16.f); s.z *= (1.f/16.f); s.w *= (1.f/16.f);
    *(float4*)(g_avg + t * 4) = s;
}

// ---------------- Kernel A2: cov -> corr -> MLP -> adj -> masks ----------------
__global__ void __launch_bounds__(1024) k_adj(
    const float* __restrict__ Ws1, const float* __restrict__ bs1,
    const float* __restrict__ Ws2, const float* __restrict__ bs2,
    const float* __restrict__ Ws3, const float* __restrict__ bs3,
    float* __restrict__ out_adj)
{
    __shared__ float av[8192];
    __shared__ float scratch[1024];
    __shared__ float cm[16];
    __shared__ float covs[256];
    __shared__ float corr_s[256];
    __shared__ float h1s[256];
    __shared__ float h2s[128];
    __shared__ float adj_s[256];
    __shared__ float pms[240];

    int tid = threadIdx.x;
    for (int i = tid; i < 2048; i += 1024)
        *(float4*)(av + i * 4) = *(const float4*)(g_avg + i * 4);
    __syncthreads();

    if (tid < 512) {
        int j = tid & 15, part = tid >> 4;
        float s = 0.f;
        for (int r = 0; r < 16; r++) s += av[(part * 16 + r) * 16 + j];
        scratch[tid] = s;
    }
    __syncthreads();
    if (tid < 16) {
        float s = 0.f;
        for (int part = 0; part < 32; part++) s += scratch[part * 16 + tid];
        cm[tid] = s * (1.f / 512.f);
    }
    __syncthreads();

    {
        int pair = tid >> 2, q = tid & 3;
        int i = pair >> 4, j = pair & 15;
        float ci = cm[i], cj = cm[j];
        float s = 0.f;
        for (int r = q * 128; r < q * 128 + 128; r++)
            s += (av[r * 16 + i] - ci) * (av[r * 16 + j] - cj);
        scratch[tid] = s;
    }
    __syncthreads();
    if (tid < 256)
        covs[tid] = scratch[tid*4] + scratch[tid*4+1] + scratch[tid*4+2] + scratch[tid*4+3];
    __syncthreads();
    if (tid < 256) {
        int i = tid >> 4, j = tid & 15;
        float si = sqrtf(fmaxf(covs[i * 16 + i], 0.f));
        float sj = sqrtf(fmaxf(covs[j * 16 + j], 0.f));
        float denom = si * sj;
        float c = denom > 0.f ? covs[tid] / denom : 0.f;
        c = fabsf(c);
        if (i == j) c = 0.f;
        corr_s[tid] = c;
    }
    __syncthreads();

    {
        int o = tid & 255, q = tid >> 8;
        float s = 0.f;
        for (int k = q * 64; k < q * 64 + 64; k++) s = fmaf(corr_s[k], Ws1[k * 256 + o], s);
        scratch[q * 256 + o] = s;
    }
    __syncthreads();
    if (tid < 256)
        h1s[tid] = fmaxf(scratch[tid] + scratch[256 + tid] + scratch[512 + tid] + scratch[768 + tid] + bs1[tid], 0.f);
    __syncthreads();

    {
        int o = tid & 127, q = tid >> 7;
        float s = 0.f;
        for (int k = q * 32; k < q * 32 + 32; k++) s = fmaf(h1s[k], Ws2[k * 128 + o], s);
        scratch[q * 128 + o] = s;
    }
    __syncthreads();
    if (tid < 128) {
        float s = bs2[tid];
        for (int q = 0; q < 8; q++) s += scratch[q * 128 + tid];
        h2s[tid] = fmaxf(s, 0.f);
    }
    __syncthreads();

    {
        int o = tid & 255, q = tid >> 8;
        float s = 0.f;
        for (int k = q * 32; k < q * 32 + 32; k++) s = fmaf(h2s[k], Ws3[k * 256 + o], s);
        scratch[q * 256 + o] = s;
    }
    __syncthreads();
    if (tid < 256) {
        float logit = scratch[tid] + scratch[256 + tid] + scratch[512 + tid] + scratch[768 + tid] + bs3[tid];
        float a = 1.f / (1.f + expf(-logit));
        int i = tid >> 4, j = tid & 15;
        float val = (j > i) ? a : 0.f;
        adj_s[tid] = val;
        out_adj[tid] = val;
    }
    __syncthreads();
    if (tid < 240) {
        int v = tid / 15, p = tid - v * 15;
        int g = p + (p >= v ? 1 : 0);
        float m = (adj_s[g * 16 + v] > 0.5f) ? 1.f : 0.f;
        pms[tid] = m;
        g_pm[tid] = m;
    }
    __syncthreads();
    if (tid < 16) {
        float s = 0.f;
        for (int p = 0; p < 15; p++) s += pms[tid * 15 + p];
        g_hp[tid] = (s > 0.f) ? 1.f : 0.f;
    }
}

// ---------------- Kernel B: mechanism MLP (reduction-packed FFMA2) ----------------
// grid (32,16), 256 thr (8 warps), 8 samples/warp/iter, 4 iters.
// Accumulators packed over the REDUCTION dim -> both FFMA2 operands are natural
// adjacent pairs (no duplication, no packing movs).
// smem floats:
//   W1T [128c][18]   @0      (2304)  transposed, pad18 -> conflict-free LDS.64
//   W2T [64k][130]   @2304   (8320)  transposed, pad130 -> conflict-free LDS.64
//   b1s [128]        @10624
//   b2s [64]         @10752
//   w3s [64]         @10816
//   pms [16]         @10880
//   raw  [8w][128]   @10896  (1024)
//   inXp [8w][8s][16]@11920  (1024)  masked inputs, p=15 padded 0
//   h1b  [8w][8s][132] @12944 (8448)
// total 21392 floats = 85568 B -> 2 blocks/SM
__global__ void __launch_bounds__(256, 2) k_mech(
    const float* __restrict__ data,
    const float* __restrict__ Wm1, const float* __restrict__ bm1,
    const float* __restrict__ Wm2, const float* __restrict__ bm2,
    const float* __restrict__ Wm3, const float* __restrict__ bm3,
    float* __restrict__ out_pred)
{
    extern __shared__ float sm[];
    const int v = blockIdx.y;
    float* W1T = sm;
    float* W2T = sm + 2304;
    float* b1s = sm + 10624;
    float* b2s = sm + 10752;
    float* w3s = sm + 10816;
    float* pms = sm + 10880;
    float* raw = sm + 10896;
    float* inXp = sm + 11920;
    float* h1b = sm + 12944;

    int tid = threadIdx.x;
    for (int t = tid; t < 1920; t += 256) {
        int p = t >> 7, c = t & 127;
        W1T[c * 18 + p] = Wm1[v * 1920 + t];
    }
    if (tid < 128) W1T[tid * 18 + 15] = 0.f;       // pad parent 15
    for (int t = tid; t < 8192; t += 256) {
        int j = t >> 6, k = t & 63;
        W2T[k * 130 + j] = Wm2[v * 8192 + t];
    }
    if (tid < 128) b1s[tid] = bm1[v * 128 + tid];
    if (tid < 64) { b2s[tid] = bm2[v * 64 + tid]; w3s[tid] = Wm3[v * 64 + tid]; }
    if (tid < 16) pms[tid] = (tid < 15) ? g_pm[v * 15 + tid] : 0.f;
    float hp = g_hp[v];
    float b3 = bm3[v];
    __syncthreads();

    int w = tid >> 5, lane = tid & 31;
    int sg = lane >> 4, kg = lane & 15;
    float* rawW = raw + w * 128;
    float* inW  = inXp + w * 128;
    float* h1W  = h1b + w * 1056;

    float b2r[4], w3r[4];
#pragma unroll
    for (int cc = 0; cc < 4; cc++) { b2r[cc] = b2s[kg + 16 * cc]; w3r[cc] = w3s[kg + 16 * cc]; }

    for (int it = 0; it < 4; it++) {
        int base = blockIdx.x * 256 + it * 64 + w * 8;
        {   // 8 sample rows, coalesced (all 32 lanes)
            int s = lane >> 2, q = lane & 3;
            float4 rv = *(const float4*)(data + (base + s) * 16 + q * 4);
            *(float4*)(rawW + s * 16 + q * 4) = rv;
        }
        __syncwarp();
        // masked, permuted inputs; p=15 zero pad
#pragma unroll
        for (int u = 0; u < 4; u++) {
            int idx = lane + 32 * u;
            int s = idx >> 4, p = idx & 15;
            float val = 0.f;
            if (p < 15) {
                int g = p + (p >= v ? 1 : 0);
                val = rawW[s * 16 + g] * pms[p];
            }
            inW[s * 16 + p] = val;
        }
        __syncwarp();

        // ---- h1: lane owns c = kg + 16*(cc + 4*pass), samples 4sg..4sg+3
#pragma unroll
        for (int pass = 0; pass < 2; pass++) {
            float2 acc[4][4];
#pragma unroll
            for (int cc = 0; cc < 4; cc++) {
                int c = kg + 16 * (cc + 4 * pass);
                float b = b1s[c];
#pragma unroll
                for (int ss = 0; ss < 4; ss++) acc[cc][ss] = make_float2(b, 0.f);
            }
#pragma unroll
            for (int p4 = 0; p4 < 4; p4++) {
                float2 wv0[4], wv1[4];
#pragma unroll
                for (int cc = 0; cc < 4; cc++) {
                    int c = kg + 16 * (cc + 4 * pass);
                    wv0[cc] = *(float2*)(W1T + c * 18 + p4 * 4);
                    wv1[cc] = *(float2*)(W1T + c * 18 + p4 * 4 + 2);
                }
                float4 xv[4];
#pragma unroll
                for (int ss = 0; ss < 4; ss++)
                    xv[ss] = *(float4*)(inW + (4 * sg + ss) * 16 + p4 * 4);
#pragma unroll
                for (int cc = 0; cc < 4; cc++) {
#pragma unroll
                    for (int ss = 0; ss < 4; ss++) {
                        acc[cc][ss] = ffma2(wv0[cc], make_float2(xv[ss].x, xv[ss].y), acc[cc][ss]);
                        acc[cc][ss] = ffma2(wv1[cc], make_float2(xv[ss].z, xv[ss].w), acc[cc][ss]);
                    }
                }
            }
#pragma unroll
            for (int cc = 0; cc < 4; cc++) {
                int c = kg + 16 * (cc + 4 * pass);
#pragma unroll
                for (int ss = 0; ss < 4; ss++) {
                    float h = fmaxf(acc[cc][ss].x + acc[cc][ss].y, 0.f);
                    h1W[(4 * sg + ss) * 132 + c] = h;   // conflict-free STS.32
                }
            }
        }
        __syncwarp();

        // ---- h2: lane owns k = kg + 16cc, samples 4sg..4sg+3; acc packed over j-pairs
        float2 acc2[4][4];
#pragma unroll
        for (int cc = 0; cc < 4; cc++)
#pragma unroll
            for (int ss = 0; ss < 4; ss++) acc2[cc][ss] = make_float2(b2r[cc], 0.f);
#pragma unroll 8
        for (int j4 = 0; j4 < 32; j4++) {
            float2 wv0[4], wv1[4];
#pragma unroll
            for (int cc = 0; cc < 4; cc++) {
                int k = kg + 16 * cc;
                wv0[cc] = *(float2*)(W2T + k * 130 + j4 * 4);
                wv1[cc] = *(float2*)(W2T + k * 130 + j4 * 4 + 2);
            }
            float4 hv[4];
#pragma unroll
            for (int ss = 0; ss < 4; ss++)
                hv[ss] = *(float4*)(h1W + (4 * sg + ss) * 132 + j4 * 4);
#pragma unroll
            for (int cc = 0; cc < 4; cc++) {
#pragma unroll
                for (int ss = 0; ss < 4; ss++) {
                    acc2[cc][ss] = ffma2(wv0[cc], make_float2(hv[ss].x, hv[ss].y), acc2[cc][ss]);
                    acc2[cc][ss] = ffma2(wv1[cc], make_float2(hv[ss].z, hv[ss].w), acc2[cc][ss]);
                }
            }
        }

        // ---- tail: relu, dot w3, reduce over kg lanes
        float outp[4];
#pragma unroll
        for (int ss = 0; ss < 4; ss++) {
            float s = 0.f;
#pragma unroll
            for (int cc = 0; cc < 4; cc++) {
                float h2v = fmaxf(acc2[cc][ss].x + acc2[cc][ss].y, 0.f);
                s = fmaf(h2v, w3r[cc], s);
            }
            outp[ss] = s;
        }
#pragma unroll
        for (int off = 1; off < 16; off <<= 1) {
#pragma unroll
            for (int ss = 0; ss < 4; ss++)
                outp[ss] += __shfl_xor_sync(0xffffffffu, outp[ss], off);
        }
        if (kg == 0) {
#pragma unroll
            for (int ss = 0; ss < 4; ss++) {
                int s = 4 * sg + ss;
                float pred = (hp > 0.f) ? (outp[ss] + b3) : rawW[s * 16 + v];
                out_pred[(base + s) * 16 + v] = pred;
            }
        }
        __syncwarp();
    }
}

// ---------------- Kernel C: pair scorer (4 threads/pair, 8 channels each) ----------------
// grid 128 blocks x 64 samples, 960 threads (30 warps).
__global__ void __launch_bounds__(960) k_pairs(
    const float* __restrict__ data,
    const float* __restrict__ Wt1, const float* __restrict__ bt1,
    const float* __restrict__ Wt2, const float* __restrict__ bt2)
{
    __shared__ float rows[64 * 17];
    int tid = threadIdx.x;
    int sbase = blockIdx.x * 64;
    for (int t = tid; t < 1024; t += 960) {
        int s = t >> 4, j = t & 15;
        rows[s * 17 + j] = data[(sbase + s) * 16 + j];
    }
    __syncthreads();

    int p = tid >> 2, q = tid & 3;
    int pi = p / 15, r = p - pi * 15;
    int pj = r + (r >= pi ? 1 : 0);
    int co = q * 8;
    float4 wa0 = *(const float4*)(Wt1 + p * 64 + co);
    float4 wa1 = *(const float4*)(Wt1 + p * 64 + co + 4);
    float4 wb0 = *(const float4*)(Wt1 + p * 64 + 32 + co);
    float4 wb1 = *(const float4*)(Wt1 + p * 64 + 32 + co + 4);
    float4 bb0 = *(const float4*)(bt1 + p * 32 + co);
    float4 bb1 = *(const float4*)(bt1 + p * 32 + co + 4);
    float4 w20 = *(const float4*)(Wt2 + p * 32 + co);
    float4 w21 = *(const float4*)(Wt2 + p * 32 + co + 4);
    float b2v = bt2[p];

    float accs = 0.f;
    for (int s = 0; s < 64; s++) {
        float a = rows[s * 17 + pi], b = rows[s * 17 + pj];
        float2 xi = make_float2(a, a), xj = make_float2(b, b);
        float2 sv0 = make_float2(0.f, 0.f), sv1 = make_float2(0.f, 0.f);
        float2 h;
        h = ffma2(xi, make_float2(wa0.x, wa0.y), make_float2(bb0.x, bb0.y));
        h = ffma2(xj, make_float2(wb0.x, wb0.y), h);
        h.x = fmaxf(h.x, 0.f); h.y = fmaxf(h.y, 0.f);
        sv0 = ffma2(h, make_float2(w20.x, w20.y), sv0);
        h = ffma2(xi, make_float2(wa0.z, wa0.w), make_float2(bb0.z, bb0.w));
        h = ffma2(xj, make_float2(wb0.z, wb0.w), h);
        h.x = fmaxf(h.x, 0.f); h.y = fmaxf(h.y, 0.f);
        sv1 = ffma2(h, make_float2(w20.z, w20.w), sv1);
        h = ffma2(xi, make_float2(wa1.x, wa1.y), make_float2(bb1.x, bb1.y));
        h = ffma2(xj, make_float2(wb1.x, wb1.y), h);
        h.x = fmaxf(h.x, 0.f); h.y = fmaxf(h.y, 0.f);
        sv0 = ffma2(h, make_float2(w21.x, w21.y), sv0);
        h = ffma2(xi, make_float2(wa1.z, wa1.w), make_float2(bb1.z, bb1.w));
        h = ffma2(xj, make_float2(wb1.z, wb1.w), h);
        h.x = fmaxf(h.x, 0.f); h.y = fmaxf(h.y, 0.f);
        sv1 = ffma2(h, make_float2(w21.z, w21.w), sv1);

        float sv = (sv0.x + sv0.y) + (sv1.x + sv1.y);
        sv += __shfl_xor_sync(0xffffffffu, sv, 1);
        sv += __shfl_xor_sync(0xffffffffu, sv, 2);
        float tot = sv + b2v;
        accs += __fdividef(1.f, 1.f + __expf(-tot));
    }
    if (q == 0) g_part[p * 128 + blockIdx.x] = accs;
}

// ---------------- Kernel D: finalize ----------------
__global__ void __launch_bounds__(256) k_fin(float* __restrict__ out_scores) {
    int t = threadIdx.x;
    if (t < 240) {
        const float4* b = (const float4*)(g_part + t * 128);
        float s = 0.f;
#pragma unroll
        for (int i = 0; i < 32; i++) {
            float4 v = b[i];
            s += (v.x + v.y) + (v.z + v.w);
        }
        int pi = t / 15, r = t - pi * 15;
        int pj = r + (r >= pi ? 1 : 0);
        out_scores[pi * 16 + pj] = s * (1.f / 8192.f);
    }
    if (t < 16) out_scores[t * 17] = 0.f;
}

// ---------------- launch ----------------
extern "C" void kernel_launch(void* const* d_in, const int* in_sizes, int n_in,
                              void* d_out, int out_size) {
    const float* data = (const float*)d_in[0];
    const float* Ws1 = (const float*)d_in[1];
    const float* bs1 = (const float*)d_in[2];
    const float* Ws2 = (const float*)d_in[3];
    const float* bs2 = (const float*)d_in[4];
    const float* Ws3 = (const float*)d_in[5];
    const float* bs3 = (const float*)d_in[6];
    const float* Wm1 = (const float*)d_in[7];
    const float* bm1 = (const float*)d_in[8];
    const float* Wm2 = (const float*)d_in[9];
    const float* bm2 = (const float*)d_in[10];
    const float* Wm3 = (const float*)d_in[11];
    const float* bm3 = (const float*)d_in[12];
    const float* Wt1 = (const float*)d_in[13];
    const float* bt1 = (const float*)d_in[14];
    const float* Wt2 = (const float*)d_in[15];
    const float* bt2 = (const float*)d_in[16];

    float* out = (float*)d_out;
    float* out_adj    = out;
    float* out_pred   = out + 256;
    float* out_scores = out + 256 + 131072;

    cudaFuncSetAttribute(k_mech, cudaFuncAttributeMaxDynamicSharedMemorySize, 85568);

    k_avg<<<32, 64>>>(data);
    k_adj<<<1, 1024>>>(Ws1, bs1, Ws2, bs2, Ws3, bs3, out_adj);
    k_mech<<<dim3(32, 16), 256, 85568>>>(data, Wm1, bm1, Wm2, bm2, Wm3, bm3, out_pred);
    k_pairs<<<128, 960>>>(data, Wt1, bt1, Wt2, bt2);
    k_fin<<<1, 256>>>(out_scores);
}

// round 6
// speedup vs baseline: 1.5212x; 1.0485x over previous
#include <cuda_runtime.h>
#include <math.h>

#define NV 16

// ---------------- device scratch ----------------
__device__ float g_avg[512 * 16];      // mean over batch (SEQ, NV)
__device__ float g_pm[240];            // parent_mask [v][p]
__device__ float g_hp[16];             // has_parents per v
__device__ float g_part[240 * 128];    // pair partial sums [pair][block]

// packed f32x2 FMA (still used by k_pairs)
union F2U { float2 f; unsigned long long u; };
__device__ __forceinline__ float2 ffma2(float2 a, float2 b, float2 c) {
    F2U au, bu, cu, du;
    au.f = a; bu.f = b; cu.f = c;
    asm("fma.rn.f32x2 %0, %1, %2, %3;" : "=l"(du.u) : "l"(au.u), "l"(bu.u), "l"(cu.u));
    return du.f;
}

// tf32 m16n8k8 MMA, fp32 accumulate
__device__ __forceinline__ void mma_tf32(float* d, const unsigned* a, const unsigned* b) {
    asm volatile(
        "mma.sync.aligned.m16n8k8.row.col.f32.tf32.tf32.f32 "
        "{%0,%1,%2,%3}, {%4,%5,%6,%7}, {%8,%9}, {%0,%1,%2,%3};"
        : "+f"(d[0]), "+f"(d[1]), "+f"(d[2]), "+f"(d[3])
        : "r"(a[0]), "r"(a[1]), "r"(a[2]), "r"(a[3]), "r"(b[0]), "r"(b[1]));
}

__device__ __forceinline__ unsigned hi_bits(float x) {
    return __float_as_uint(x) & 0xFFFFE000u;
}

// ---------------- Kernel A1: avg over batch ----------------
__global__ void k_avg(const float* __restrict__ data) {
    int t = blockIdx.x * 64 + threadIdx.x;
    float4 s = make_float4(0.f, 0.f, 0.f, 0.f);
#pragma unroll
    for (int b = 0; b < 16; b++) {
        float4 v = *(const float4*)(data + b * 8192 + t * 4);
        s.x += v.x; s.y += v.y; s.z += v.z; s.w += v.w;
    }
    s.x *= (1.f/16.f); s.y *= (1.f/16.f); s.z *= (1.f/16.f); s.w *= (1.f/16.f);
    *(float4*)(g_avg + t * 4) = s;
}

// ---------------- Kernel A2: cov -> corr -> MLP -> adj -> masks ----------------
__global__ void __launch_bounds__(1024) k_adj(
    const float* __restrict__ Ws1, const float* __restrict__ bs1,
    const float* __restrict__ Ws2, const float* __restrict__ bs2,
    const float* __restrict__ Ws3, const float* __restrict__ bs3,
    float* __restrict__ out_adj)
{
    __shared__ float av[8192];
    __shared__ float scratch[1024];
    __shared__ float cm[16];
    __shared__ float covs[256];
    __shared__ float corr_s[256];
    __shared__ float h1s[256];
    __shared__ float h2s[128];
    __shared__ float adj_s[256];
    __shared__ float pms[240];

    int tid = threadIdx.x;
    for (int i = tid; i < 2048; i += 1024)
        *(float4*)(av + i * 4) = *(const float4*)(g_avg + i * 4);
    __syncthreads();

    if (tid < 512) {
        int j = tid & 15, part = tid >> 4;
        float s = 0.f;
        for (int r = 0; r < 16; r++) s += av[(part * 16 + r) * 16 + j];
        scratch[tid] = s;
    }
    __syncthreads();
    if (tid < 16) {
        float s = 0.f;
        for (int part = 0; part < 32; part++) s += scratch[part * 16 + tid];
        cm[tid] = s * (1.f / 512.f);
    }
    __syncthreads();

    {
        int pair = tid >> 2, q = tid & 3;
        int i = pair >> 4, j = pair & 15;
        float ci = cm[i], cj = cm[j];
        float s = 0.f;
        for (int r = q * 128; r < q * 128 + 128; r++)
            s += (av[r * 16 + i] - ci) * (av[r * 16 + j] - cj);
        scratch[tid] = s;
    }
    __syncthreads();
    if (tid < 256)
        covs[tid] = scratch[tid*4] + scratch[tid*4+1] + scratch[tid*4+2] + scratch[tid*4+3];
    __syncthreads();
    if (tid < 256) {
        int i = tid >> 4, j = tid & 15;
        float si = sqrtf(fmaxf(covs[i * 16 + i], 0.f));
        float sj = sqrtf(fmaxf(covs[j * 16 + j], 0.f));
        float denom = si * sj;
        float c = denom > 0.f ? covs[tid] / denom : 0.f;
        c = fabsf(c);
        if (i == j) c = 0.f;
        corr_s[tid] = c;
    }
    __syncthreads();

    {
        int o = tid & 255, q = tid >> 8;
        float s = 0.f;
        for (int k = q * 64; k < q * 64 + 64; k++) s = fmaf(corr_s[k], Ws1[k * 256 + o], s);
        scratch[q * 256 + o] = s;
    }
    __syncthreads();
    if (tid < 256)
        h1s[tid] = fmaxf(scratch[tid] + scratch[256 + tid] + scratch[512 + tid] + scratch[768 + tid] + bs1[tid], 0.f);
    __syncthreads();

    {
        int o = tid & 127, q = tid >> 7;
        float s = 0.f;
        for (int k = q * 32; k < q * 32 + 32; k++) s = fmaf(h1s[k], Ws2[k * 128 + o], s);
        scratch[q * 128 + o] = s;
    }
    __syncthreads();
    if (tid < 128) {
        float s = bs2[tid];
        for (int q = 0; q < 8; q++) s += scratch[q * 128 + tid];
        h2s[tid] = fmaxf(s, 0.f);
    }
    __syncthreads();

    {
        int o = tid & 255, q = tid >> 8;
        float s = 0.f;
        for (int k = q * 32; k < q * 32 + 32; k++) s = fmaf(h2s[k], Ws3[k * 256 + o], s);
        scratch[q * 256 + o] = s;
    }
    __syncthreads();
    if (tid < 256) {
        float logit = scratch[tid] + scratch[256 + tid] + scratch[512 + tid] + scratch[768 + tid] + bs3[tid];
        float a = 1.f / (1.f + expf(-logit));
        int i = tid >> 4, j = tid & 15;
        float val = (j > i) ? a : 0.f;
        adj_s[tid] = val;
        out_adj[tid] = val;
    }
    __syncthreads();
    if (tid < 240) {
        int v = tid / 15, p = tid - v * 15;
        int g = p + (p >= v ? 1 : 0);
        float m = (adj_s[g * 16 + v] > 0.5f) ? 1.f : 0.f;
        pms[tid] = m;
        g_pm[tid] = m;
    }
    __syncthreads();
    if (tid < 16) {
        float s = 0.f;
        for (int p = 0; p < 15; p++) s += pms[tid * 15 + p];
        g_hp[tid] = (s > 0.f) ? 1.f : 0.f;
    }
}

// ---------------- Kernel B: mechanism MLP on TENSOR CORES (tf32 2x-comp) ----------------
// grid (32, 16): bx = 2-tile group (256 rows), by = v. 256 threads (8 warps).
// Warp w owns rows w*16..w*16+15 of each 128-row tile (H1 stays warp-local).
// smem float offsets:
//   W1Ph @0      [2ks][16nt][32ln][2]  (2048)
//   W1Pl @2048   (2048)
//   W2Ph @4096   [16ks][8nt][32ln][2]  (8192)
//   W2Pl @12288  (8192)
//   b1s  @20480  (128)
//   b2s  @20608  (64)
//   w3s  @20672  (64)
//   pms  @20736  (16)
//   rawv @20752  (128)
//   Xm   @20880  [128][20]  (2560)
//   H1   @23440  [128][132] (16896)
// total 40336 floats = 161344 bytes
__global__ void __launch_bounds__(256) k_mech(
    const float* __restrict__ data,
    const float* __restrict__ Wm1, const float* __restrict__ bm1,
    const float* __restrict__ Wm2, const float* __restrict__ bm2,
    const float* __restrict__ Wm3, const float* __restrict__ bm3,
    float* __restrict__ out_pred)
{
    extern __shared__ float sm[];
    const int v = blockIdx.y;
    float* W1Ph = sm;
    float* W1Pl = sm + 2048;
    float* W2Ph = sm + 4096;
    float* W2Pl = sm + 12288;
    float* b1s  = sm + 20480;
    float* b2s  = sm + 20608;
    float* w3s  = sm + 20672;
    float* pms  = sm + 20736;
    float* rawv = sm + 20752;
    float* Xm   = sm + 20880;
    float* H1   = sm + 23440;

    int tid = threadIdx.x;
    int w = tid >> 5, lane = tid & 31;
    int lq = lane & 3, lg = lane >> 2;

    // ---- prepack W1 (fragment order, hi/lo). k=15 padded zero.
    for (int idx = tid; idx < 2048; idx += 256) {
        int i = idx & 1, ln = (idx >> 1) & 31, nt = (idx >> 6) & 15, ks = idx >> 10;
        int k = ks * 8 + (ln & 3) + 4 * i;
        int n = nt * 8 + (ln >> 2);
        float val = (k < 15) ? Wm1[v * 1920 + k * 128 + n] : 0.f;
        unsigned h = hi_bits(val);
        W1Ph[idx] = __uint_as_float(h);
        W1Pl[idx] = val - __uint_as_float(h);
    }
    // ---- prepack W2
    for (int idx = tid; idx < 8192; idx += 256) {
        int i = idx & 1, ln = (idx >> 1) & 31, nt = (idx >> 6) & 7, ks = idx >> 9;
        int j = ks * 8 + (ln & 3) + 4 * i;
        int n = nt * 8 + (ln >> 2);
        float val = Wm2[v * 8192 + j * 64 + n];
        unsigned h = hi_bits(val);
        W2Ph[idx] = __uint_as_float(h);
        W2Pl[idx] = val - __uint_as_float(h);
    }
    if (tid < 128) b1s[tid] = bm1[v * 128 + tid];
    if (tid < 64) { b2s[tid] = bm2[v * 64 + tid]; w3s[tid] = Wm3[v * 64 + tid]; }
    if (tid < 16) pms[tid] = (tid < 15) ? g_pm[v * 15 + tid] : 0.f;
    float hp = g_hp[v];
    float b3 = bm3[v];

    for (int tile = 0; tile < 2; tile++) {
        __syncthreads();   // Xm/H1 reuse hazard + (first iter) weight prepack
        int row0 = blockIdx.x * 256 + tile * 128;
        // ---- build masked input Xm[128][20] and raw column v
        for (int idx = tid; idx < 2048; idx += 256) {
            int s = idx >> 4, p = idx & 15;
            float val = 0.f;
            if (p < 15) {
                int g = p + (p >= v ? 1 : 0);
                val = data[(row0 + s) * 16 + g] * pms[p];
            }
            Xm[s * 20 + p] = val;
        }
        if (tid < 128) rawv[tid] = data[(row0 + tid) * 16 + v];
        __syncthreads();

        int rA = w * 16 + lg;      // fragment row (and rA+8)

        // ======== layer 1: [16rows x 16k] @ [16k x 128n] ========
        float acc1[16][4];
#pragma unroll
        for (int nt = 0; nt < 16; nt++)
#pragma unroll
            for (int i = 0; i < 4; i++) acc1[nt][i] = 0.f;

#pragma unroll
        for (int ks = 0; ks < 2; ks++) {
            int k0 = ks * 8 + lq;
            float a0 = Xm[rA * 20 + k0];
            float a1 = Xm[(rA + 8) * 20 + k0];
            float a2 = Xm[rA * 20 + k0 + 4];
            float a3 = Xm[(rA + 8) * 20 + k0 + 4];
            unsigned ahi[4] = { hi_bits(a0), hi_bits(a1), hi_bits(a2), hi_bits(a3) };
            unsigned alo[4] = {
                __float_as_uint(a0 - __uint_as_float(ahi[0])),
                __float_as_uint(a1 - __uint_as_float(ahi[1])),
                __float_as_uint(a2 - __uint_as_float(ahi[2])),
                __float_as_uint(a3 - __uint_as_float(ahi[3])) };
#pragma unroll
            for (int nt = 0; nt < 16; nt++) {
                const unsigned* bh = (const unsigned*)(W1Ph + ((ks * 16 + nt) * 32 + lane) * 2);
                const unsigned* bl = (const unsigned*)(W1Pl + ((ks * 16 + nt) * 32 + lane) * 2);
                unsigned bhv[2] = { bh[0], bh[1] };
                unsigned blv[2] = { bl[0], bl[1] };
                mma_tf32(acc1[nt], ahi, bhv);
                mma_tf32(acc1[nt], ahi, blv);
                mma_tf32(acc1[nt], alo, bhv);
            }
        }
        // epilogue 1: bias + relu -> H1 (warp-local rows)
#pragma unroll
        for (int nt = 0; nt < 16; nt++) {
            int col = nt * 8 + 2 * lq;
            float2 bv = *(float2*)(b1s + col);
            float2 r0, r1;
            r0.x = fmaxf(acc1[nt][0] + bv.x, 0.f);
            r0.y = fmaxf(acc1[nt][1] + bv.y, 0.f);
            r1.x = fmaxf(acc1[nt][2] + bv.x, 0.f);
            r1.y = fmaxf(acc1[nt][3] + bv.y, 0.f);
            *(float2*)(H1 + rA * 132 + col) = r0;
            *(float2*)(H1 + (rA + 8) * 132 + col) = r1;
        }
        __syncwarp();

        // ======== layer 2: [16rows x 128k] @ [128k x 64n] ========
        float acc2[8][4];
#pragma unroll
        for (int nt = 0; nt < 8; nt++)
#pragma unroll
            for (int i = 0; i < 4; i++) acc2[nt][i] = 0.f;

#pragma unroll 4
        for (int ks = 0; ks < 16; ks++) {
            int k0 = ks * 8 + lq;
            float a0 = H1[rA * 132 + k0];
            float a1 = H1[(rA + 8) * 132 + k0];
            float a2 = H1[rA * 132 + k0 + 4];
            float a3 = H1[(rA + 8) * 132 + k0 + 4];
            unsigned ahi[4] = { hi_bits(a0), hi_bits(a1), hi_bits(a2), hi_bits(a3) };
            unsigned alo[4] = {
                __float_as_uint(a0 - __uint_as_float(ahi[0])),
                __float_as_uint(a1 - __uint_as_float(ahi[1])),
                __float_as_uint(a2 - __uint_as_float(ahi[2])),
                __float_as_uint(a3 - __uint_as_float(ahi[3])) };
#pragma unroll
            for (int nt = 0; nt < 8; nt++) {
                const unsigned* bh = (const unsigned*)(W2Ph + ((ks * 8 + nt) * 32 + lane) * 2);
                const unsigned* bl = (const unsigned*)(W2Pl + ((ks * 8 + nt) * 32 + lane) * 2);
                unsigned bhv[2] = { bh[0], bh[1] };
                unsigned blv[2] = { bl[0], bl[1] };
                mma_tf32(acc2[nt], ahi, bhv);
                mma_tf32(acc2[nt], ahi, blv);
                mma_tf32(acc2[nt], alo, bhv);
            }
        }

        // epilogue 2: bias + relu + dot w3, quad-reduce, write predictions
        float sA = 0.f, sB = 0.f;
#pragma unroll
        for (int nt = 0; nt < 8; nt++) {
            int col = nt * 8 + 2 * lq;
            float2 bv = *(float2*)(b2s + col);
            float2 wv = *(float2*)(w3s + col);
            sA = fmaf(fmaxf(acc2[nt][0] + bv.x, 0.f), wv.x, sA);
            sA = fmaf(fmaxf(acc2[nt][1] + bv.y, 0.f), wv.y, sA);
            sB = fmaf(fmaxf(acc2[nt][2] + bv.x, 0.f), wv.x, sB);
            sB = fmaf(fmaxf(acc2[nt][3] + bv.y, 0.f), wv.y, sB);
        }
        sA += __shfl_xor_sync(0xffffffffu, sA, 1);
        sA += __shfl_xor_sync(0xffffffffu, sA, 2);
        sB += __shfl_xor_sync(0xffffffffu, sB, 1);
        sB += __shfl_xor_sync(0xffffffffu, sB, 2);
        if (lq == 0) {
            float pA = (hp > 0.f) ? (sA + b3) : rawv[rA];
            float pB = (hp > 0.f) ? (sB + b3) : rawv[rA + 8];
            out_pred[(row0 + rA) * 16 + v] = pA;
            out_pred[(row0 + rA + 8) * 16 + v] = pB;
        }
    }
}

// ---------------- Kernel C: pair scorer (4 threads/pair, 8 channels each) ----------------
__global__ void __launch_bounds__(960) k_pairs(
    const float* __restrict__ data,
    const float* __restrict__ Wt1, const float* __restrict__ bt1,
    const float* __restrict__ Wt2, const float* __restrict__ bt2)
{
    __shared__ float rows[64 * 17];
    int tid = threadIdx.x;
    int sbase = blockIdx.x * 64;
    for (int t = tid; t < 1024; t += 960) {
        int s = t >> 4, j = t & 15;
        rows[s * 17 + j] = data[(sbase + s) * 16 + j];
    }
    __syncthreads();

    int p = tid >> 2, q = tid & 3;
    int pi = p / 15, r = p - pi * 15;
    int pj = r + (r >= pi ? 1 : 0);
    int co = q * 8;
    float4 wa0 = *(const float4*)(Wt1 + p * 64 + co);
    float4 wa1 = *(const float4*)(Wt1 + p * 64 + co + 4);
    float4 wb0 = *(const float4*)(Wt1 + p * 64 + 32 + co);
    float4 wb1 = *(const float4*)(Wt1 + p * 64 + 32 + co + 4);
    float4 bb0 = *(const float4*)(bt1 + p * 32 + co);
    float4 bb1 = *(const float4*)(bt1 + p * 32 + co + 4);
    float4 w20 = *(const float4*)(Wt2 + p * 32 + co);
    float4 w21 = *(const float4*)(Wt2 + p * 32 + co + 4);
    float b2v = bt2[p];

    float accs = 0.f;
    for (int s = 0; s < 64; s++) {
        float a = rows[s * 17 + pi], b = rows[s * 17 + pj];
        float2 xi = make_float2(a, a), xj = make_float2(b, b);
        float2 sv0 = make_float2(0.f, 0.f), sv1 = make_float2(0.f, 0.f);
        float2 h;
        h = ffma2(xi, make_float2(wa0.x, wa0.y), make_float2(bb0.x, bb0.y));
        h = ffma2(xj, make_float2(wb0.x, wb0.y), h);
        h.x = fmaxf(h.x, 0.f); h.y = fmaxf(h.y, 0.f);
        sv0 = ffma2(h, make_float2(w20.x, w20.y), sv0);
        h = ffma2(xi, make_float2(wa0.z, wa0.w), make_float2(bb0.z, bb0.w));
        h = ffma2(xj, make_float2(wb0.z, wb0.w), h);
        h.x = fmaxf(h.x, 0.f); h.y = fmaxf(h.y, 0.f);
        sv1 = ffma2(h, make_float2(w20.z, w20.w), sv1);
        h = ffma2(xi, make_float2(wa1.x, wa1.y), make_float2(bb1.x, bb1.y));
        h = ffma2(xj, make_float2(wb1.x, wb1.y), h);
        h.x = fmaxf(h.x, 0.f); h.y = fmaxf(h.y, 0.f);
        sv0 = ffma2(h, make_float2(w21.x, w21.y), sv0);
        h = ffma2(xi, make_float2(wa1.z, wa1.w), make_float2(bb1.z, bb1.w));
        h = ffma2(xj, make_float2(wb1.z, wb1.w), h);
        h.x = fmaxf(h.x, 0.f); h.y = fmaxf(h.y, 0.f);
        sv1 = ffma2(h, make_float2(w21.z, w21.w), sv1);

        float sv = (sv0.x + sv0.y) + (sv1.x + sv1.y);
        sv += __shfl_xor_sync(0xffffffffu, sv, 1);
        sv += __shfl_xor_sync(0xffffffffu, sv, 2);
        float tot = sv + b2v;
        accs += __fdividef(1.f, 1.f + __expf(-tot));
    }
    if (q == 0) g_part[p * 128 + blockIdx.x] = accs;
}

// ---------------- Kernel D: finalize ----------------
__global__ void __launch_bounds__(256) k_fin(float* __restrict__ out_scores) {
    int t = threadIdx.x;
    if (t < 240) {
        const float4* b = (const float4*)(g_part + t * 128);
        float s = 0.f;
#pragma unroll
        for (int i = 0; i < 32; i++) {
            float4 v = b[i];
            s += (v.x + v.y) + (v.z + v.w);
        }
        int pi = t / 15, r = t - pi * 15;
        int pj = r + (r >= pi ? 1 : 0);
        out_scores[pi * 16 + pj] = s * (1.f / 8192.f);
    }
    if (t < 16) out_scores[t * 17] = 0.f;
}

// ---------------- launch ----------------
extern "C" void kernel_launch(void* const* d_in, const int* in_sizes, int n_in,
                              void* d_out, int out_size) {
    const float* data = (const float*)d_in[0];
    const float* Ws1 = (const float*)d_in[1];
    const float* bs1 = (const float*)d_in[2];
    const float* Ws2 = (const float*)d_in[3];
    const float* bs2 = (const float*)d_in[4];
    const float* Ws3 = (const float*)d_in[5];
    const float* bs3 = (const float*)d_in[6];
    const float* Wm1 = (const float*)d_in[7];
    const float* bm1 = (const float*)d_in[8];
    const float* Wm2 = (const float*)d_in[9];
    const float* bm2 = (const float*)d_in[10];
    const float* Wm3 = (const float*)d_in[11];
    const float* bm3 = (const float*)d_in[12];
    const float* Wt1 = (const float*)d_in[13];
    const float* bt1 = (const float*)d_in[14];
    const float* Wt2 = (const float*)d_in[15];
    const float* bt2 = (const float*)d_in[16];

    float* out = (float*)d_out;
    float* out_adj    = out;
    float* out_pred   = out + 256;
    float* out_scores = out + 256 + 131072;

    cudaFuncSetAttribute(k_mech, cudaFuncAttributeMaxDynamicSharedMemorySize, 161344);

    k_avg<<<32, 64>>>(data);
    k_adj<<<1, 1024>>>(Ws1, bs1, Ws2, bs2, Ws3, bs3, out_adj);
    k_mech<<<dim3(32, 16), 256, 161344>>>(data, Wm1, bm1, Wm2, bm2, Wm3, bm3, out_pred);
    k_pairs<<<128, 960>>>(data, Wt1, bt1, Wt2, bt2);
    k_fin<<<1, 256>>>(out_scores);
}

// round 7
// speedup vs baseline: 1.8456x; 1.2132x over previous
#include <cuda_runtime.h>
#include <cuda_bf16.h>
#include <math.h>

#define NV 16

// ---------------- device scratch ----------------
__device__ float g_avg[512 * 16];
__device__ float g_pm[240];
__device__ float g_hp[16];
__device__ float g_part[240 * 128];
__device__ unsigned g_wpack[16 * 10240];   // per-v packed bf16 hi/lo weight fragments

// packed f32x2 FMA (k_pairs)
union F2U { float2 f; unsigned long long u; };
__device__ __forceinline__ float2 ffma2(float2 a, float2 b, float2 c) {
    F2U au, bu, cu, du;
    au.f = a; bu.f = b; cu.f = c;
    asm("fma.rn.f32x2 %0, %1, %2, %3;" : "=l"(du.u) : "l"(au.u), "l"(bu.u), "l"(cu.u));
    return du.f;
}

// bf16 m16n8k16 MMA, fp32 accumulate
__device__ __forceinline__ void mma_bf16(float* d, const unsigned* a, const unsigned* b) {
    asm volatile(
        "mma.sync.aligned.m16n8k16.row.col.f32.bf16.bf16.f32 "
        "{%0,%1,%2,%3}, {%4,%5,%6,%7}, {%8,%9}, {%0,%1,%2,%3};"
        : "+f"(d[0]), "+f"(d[1]), "+f"(d[2]), "+f"(d[3])
        : "r"(a[0]), "r"(a[1]), "r"(a[2]), "r"(a[3]), "r"(b[0]), "r"(b[1]));
}

__device__ __forceinline__ unsigned pack2bf(float a, float b) {
    __nv_bfloat162 h = __floats2bfloat162_rn(a, b);
    return *reinterpret_cast<unsigned*>(&h);
}
__device__ __forceinline__ float bfround(float x) {
    return __bfloat162float(__float2bfloat16_rn(x));
}

// ---------------- Kernel P: one-time weight prepack ----------------
// g_wpack[v] layout (u32): W1P [part2][nt16][lane32][r2] = 2048 ; then
//                          W2P [part2][ks8][nt8][lane32][r2] = 8192
__global__ void __launch_bounds__(256) k_pack(
    const float* __restrict__ Wm1, const float* __restrict__ Wm2)
{
    int v = blockIdx.x, tid = threadIdx.x;
    unsigned* dst = g_wpack + v * 10240;
    for (int idx = tid; idx < 2048; idx += 256) {
        int part = idx >> 10, rem = idx & 1023;
        int nt = rem >> 6, lane = (rem >> 1) & 31, r = rem & 1;
        int lg = lane >> 2, lq = lane & 3;
        int n = nt * 8 + lg, kp = lq + 4 * r;
        int k0 = 2 * kp, k1 = 2 * kp + 1;
        float w0 = (k0 < 15) ? Wm1[v * 1920 + k0 * 128 + n] : 0.f;
        float w1 = (k1 < 15) ? Wm1[v * 1920 + k1 * 128 + n] : 0.f;
        if (part == 0) dst[idx] = pack2bf(w0, w1);
        else dst[idx] = pack2bf(w0 - bfround(w0), w1 - bfround(w1));
    }
    for (int idx = tid; idx < 8192; idx += 256) {
        int part = idx >> 12, rem = idx & 4095;
        int ks = rem >> 9, nt = (rem >> 6) & 7, lane = (rem >> 1) & 31, r = rem & 1;
        int lg = lane >> 2, lq = lane & 3;
        int n = nt * 8 + lg, kp = ks * 8 + lq + 4 * r;
        int k0 = 2 * kp, k1 = 2 * kp + 1;
        float w0 = Wm2[v * 8192 + k0 * 64 + n];
        float w1 = Wm2[v * 8192 + k1 * 64 + n];
        if (part == 0) dst[2048 + idx] = pack2bf(w0, w1);
        else dst[2048 + idx] = pack2bf(w0 - bfround(w0), w1 - bfround(w1));
    }
}

// ---------------- Kernel A1: avg over batch ----------------
__global__ void k_avg(const float* __restrict__ data) {
    int t = blockIdx.x * 64 + threadIdx.x;
    float4 s = make_float4(0.f, 0.f, 0.f, 0.f);
#pragma unroll
    for (int b = 0; b < 16; b++) {
        float4 v = *(const float4*)(data + b * 8192 + t * 4);
        s.x += v.x; s.y += v.y; s.z += v.z; s.w += v.w;
    }
    s.x *= (1.f/16.f); s.y *= (1.f/16.f); s.z *= (1.f/16.f); s.w *= (1.f/16.f);
    *(float4*)(g_avg + t * 4) = s;
}

// ---------------- Kernel A2: cov -> corr -> MLP -> adj -> masks ----------------
__global__ void __launch_bounds__(1024) k_adj(
    const float* __restrict__ Ws1, const float* __restrict__ bs1,
    const float* __restrict__ Ws2, const float* __restrict__ bs2,
    const float* __restrict__ Ws3, const float* __restrict__ bs3,
    float* __restrict__ out_adj)
{
    __shared__ float av[8192];
    __shared__ float scratch[1024];
    __shared__ float cm[16];
    __shared__ float covs[256];
    __shared__ float corr_s[256];
    __shared__ float h1s[256];
    __shared__ float h2s[128];
    __shared__ float adj_s[256];
    __shared__ float pms[240];

    int tid = threadIdx.x;
    for (int i = tid; i < 2048; i += 1024)
        *(float4*)(av + i * 4) = *(const float4*)(g_avg + i * 4);
    __syncthreads();

    if (tid < 512) {
        int j = tid & 15, part = tid >> 4;
        float s = 0.f;
        for (int r = 0; r < 16; r++) s += av[(part * 16 + r) * 16 + j];
        scratch[tid] = s;
    }
    __syncthreads();
    if (tid < 16) {
        float s = 0.f;
        for (int part = 0; part < 32; part++) s += scratch[part * 16 + tid];
        cm[tid] = s * (1.f / 512.f);
    }
    __syncthreads();

    {
        int pair = tid >> 2, q = tid & 3;
        int i = pair >> 4, j = pair & 15;
        float ci = cm[i], cj = cm[j];
        float s = 0.f;
        for (int r = q * 128; r < q * 128 + 128; r++)
            s += (av[r * 16 + i] - ci) * (av[r * 16 + j] - cj);
        scratch[tid] = s;
    }
    __syncthreads();
    if (tid < 256)
        covs[tid] = scratch[tid*4] + scratch[tid*4+1] + scratch[tid*4+2] + scratch[tid*4+3];
    __syncthreads();
    if (tid < 256) {
        int i = tid >> 4, j = tid & 15;
        float si = sqrtf(fmaxf(covs[i * 16 + i], 0.f));
        float sj = sqrtf(fmaxf(covs[j * 16 + j], 0.f));
        float denom = si * sj;
        float c = denom > 0.f ? covs[tid] / denom : 0.f;
        c = fabsf(c);
        if (i == j) c = 0.f;
        corr_s[tid] = c;
    }
    __syncthreads();

    {
        int o = tid & 255, q = tid >> 8;
        float s = 0.f;
        for (int k = q * 64; k < q * 64 + 64; k++) s = fmaf(corr_s[k], Ws1[k * 256 + o], s);
        scratch[q * 256 + o] = s;
    }
    __syncthreads();
    if (tid < 256)
        h1s[tid] = fmaxf(scratch[tid] + scratch[256 + tid] + scratch[512 + tid] + scratch[768 + tid] + bs1[tid], 0.f);
    __syncthreads();

    {
        int o = tid & 127, q = tid >> 7;
        float s = 0.f;
        for (int k = q * 32; k < q * 32 + 32; k++) s = fmaf(h1s[k], Ws2[k * 128 + o], s);
        scratch[q * 128 + o] = s;
    }
    __syncthreads();
    if (tid < 128) {
        float s = bs2[tid];
        for (int q = 0; q < 8; q++) s += scratch[q * 128 + tid];
        h2s[tid] = fmaxf(s, 0.f);
    }
    __syncthreads();

    {
        int o = tid & 255, q = tid >> 8;
        float s = 0.f;
        for (int k = q * 32; k < q * 32 + 32; k++) s = fmaf(h2s[k], Ws3[k * 256 + o], s);
        scratch[q * 256 + o] = s;
    }
    __syncthreads();
    if (tid < 256) {
        float logit = scratch[tid] + scratch[256 + tid] + scratch[512 + tid] + scratch[768 + tid] + bs3[tid];
        float a = 1.f / (1.f + expf(-logit));
        int i = tid >> 4, j = tid & 15;
        float val = (j > i) ? a : 0.f;
        adj_s[tid] = val;
        out_adj[tid] = val;
    }
    __syncthreads();
    if (tid < 240) {
        int v = tid / 15, p = tid - v * 15;
        int g = p + (p >= v ? 1 : 0);
        float m = (adj_s[g * 16 + v] > 0.5f) ? 1.f : 0.f;
        pms[tid] = m;
        g_pm[tid] = m;
    }
    __syncthreads();
    if (tid < 16) {
        float s = 0.f;
        for (int p = 0; p < 15; p++) s += pms[tid * 15 + p];
        g_hp[tid] = (s > 0.f) ? 1.f : 0.f;
    }
}

// ---------------- Kernel B: mechanism MLP (bf16 HMMA, 3-term comp) ----------------
// grid (8, 16): bx owns 1024 rows (8 tiles of 128), by = v. 256 thr (8 warps).
// Warp w owns rows w*16..w*16+15 of each tile. One wave (128 blocks).
// smem (u32/float words):
//   W1s  2048 @0      [part][nt16][lane][2]
//   W2s  8192 @2048   [part][ks8][nt8][lane][2]
//   b1s  128  @10240
//   b2s  64   @10368
//   w3s  64   @10432
//   pms  16   @10496
//   rawv 128  @10512
//   Xh   1152 @10640  [128][9]  (8 kpairs + pad)
//   Xl   1152 @11792
//   H1h  8448 @12944  [128][66] (64 kpairs + pad)
//   H1l  8448 @21392
// total 29840 words = 119360 B
__global__ void __launch_bounds__(256) k_mech(
    const float* __restrict__ data,
    const float* __restrict__ bm1,
    const float* __restrict__ bm2,
    const float* __restrict__ Wm3, const float* __restrict__ bm3,
    float* __restrict__ out_pred)
{
    extern __shared__ float sm[];
    const int v = blockIdx.y;
    unsigned* Wp  = (unsigned*)sm;            // W1s+W2s contiguous (10240 u32)
    float* b1s  = sm + 10240;
    float* b2s  = sm + 10368;
    float* w3s  = sm + 10432;
    float* pms  = sm + 10496;
    float* rawv = sm + 10512;
    unsigned* Xh  = (unsigned*)(sm + 10640);
    unsigned* Xl  = (unsigned*)(sm + 11792);
    unsigned* H1h = (unsigned*)(sm + 12944);
    unsigned* H1l = (unsigned*)(sm + 21392);

    int tid = threadIdx.x;
    int w = tid >> 5, lane = tid & 31;
    int lq = lane & 3, lg = lane >> 2;

    // copy packed weights (coalesced float4)
    {
        const float4* src = (const float4*)(g_wpack + v * 10240);
        float4* dst = (float4*)Wp;
        for (int i = tid; i < 2560; i += 256) dst[i] = src[i];
    }
    if (tid < 128) b1s[tid] = bm1[v * 128 + tid];
    if (tid < 64) { b2s[tid] = bm2[v * 64 + tid]; w3s[tid] = Wm3[v * 64 + tid]; }
    if (tid < 16) pms[tid] = (tid < 15) ? g_pm[v * 15 + tid] : 0.f;
    float hp = g_hp[v];
    float b3 = bm3[v];

    const unsigned* W1s = Wp;
    const unsigned* W2s = Wp + 2048;
    int rA = w * 16 + lg;

    for (int tile = 0; tile < 8; tile++) {
        __syncthreads();
        int row0 = blockIdx.x * 1024 + tile * 128;
        // build masked, split input Xh/Xl [128][9] and raw column v
        for (int idx = tid; idx < 1024; idx += 256) {
            int row = idx >> 3, kp = idx & 7;
            int p0 = 2 * kp, p1 = 2 * kp + 1;
            const float* drow = data + (row0 + row) * 16;
            float v0 = 0.f, v1 = 0.f;
            v0 = drow[p0 + (p0 >= v ? 1 : 0)] * pms[p0];
            if (p1 < 15) v1 = drow[p1 + (p1 >= v ? 1 : 0)] * pms[p1];
            Xh[row * 9 + kp] = pack2bf(v0, v1);
            Xl[row * 9 + kp] = pack2bf(v0 - bfround(v0), v1 - bfround(v1));
        }
        if (tid < 128) rawv[tid] = data[(row0 + tid) * 16 + v];
        __syncthreads();

        // ======== layer 1: [16 x 16] @ [16 x 128], K=16 in one MMA step ========
        unsigned ahi[4], alo[4];
        ahi[0] = Xh[rA * 9 + lq];           ahi[1] = Xh[(rA + 8) * 9 + lq];
        ahi[2] = Xh[rA * 9 + lq + 4];       ahi[3] = Xh[(rA + 8) * 9 + lq + 4];
        alo[0] = Xl[rA * 9 + lq];           alo[1] = Xl[(rA + 8) * 9 + lq];
        alo[2] = Xl[rA * 9 + lq + 4];       alo[3] = Xl[(rA + 8) * 9 + lq + 4];

        float acc1[16][4];
#pragma unroll
        for (int nt = 0; nt < 16; nt++)
#pragma unroll
            for (int i = 0; i < 4; i++) acc1[nt][i] = 0.f;
#pragma unroll
        for (int nt = 0; nt < 16; nt++) {
            const unsigned* bh = W1s + (nt * 32 + lane) * 2;
            const unsigned* bl = W1s + 1024 + (nt * 32 + lane) * 2;
            unsigned bhv[2] = { bh[0], bh[1] };
            unsigned blv[2] = { bl[0], bl[1] };
            mma_bf16(acc1[nt], ahi, bhv);
            mma_bf16(acc1[nt], ahi, blv);
            mma_bf16(acc1[nt], alo, bhv);
        }
        // epilogue 1: bias + relu -> split bf16 pairs -> H1h/H1l (warp-local rows)
#pragma unroll
        for (int nt = 0; nt < 16; nt++) {
            float2 bv = *(float2*)(b1s + nt * 8 + 2 * lq);
            int cp = nt * 4 + lq;
            float a0 = fmaxf(acc1[nt][0] + bv.x, 0.f);
            float a1 = fmaxf(acc1[nt][1] + bv.y, 0.f);
            float b0 = fmaxf(acc1[nt][2] + bv.x, 0.f);
            float b1 = fmaxf(acc1[nt][3] + bv.y, 0.f);
            H1h[rA * 66 + cp] = pack2bf(a0, a1);
            H1l[rA * 66 + cp] = pack2bf(a0 - bfround(a0), a1 - bfround(a1));
            H1h[(rA + 8) * 66 + cp] = pack2bf(b0, b1);
            H1l[(rA + 8) * 66 + cp] = pack2bf(b0 - bfround(b0), b1 - bfround(b1));
        }
        __syncwarp();

        // ======== layer 2: [16 x 128] @ [128 x 64], 8 K-steps ========
        float acc2[8][4];
#pragma unroll
        for (int nt = 0; nt < 8; nt++)
#pragma unroll
            for (int i = 0; i < 4; i++) acc2[nt][i] = 0.f;
#pragma unroll
        for (int ks = 0; ks < 8; ks++) {
            unsigned a2hi[4], a2lo[4];
            a2hi[0] = H1h[rA * 66 + ks * 8 + lq];
            a2hi[1] = H1h[(rA + 8) * 66 + ks * 8 + lq];
            a2hi[2] = H1h[rA * 66 + ks * 8 + lq + 4];
            a2hi[3] = H1h[(rA + 8) * 66 + ks * 8 + lq + 4];
            a2lo[0] = H1l[rA * 66 + ks * 8 + lq];
            a2lo[1] = H1l[(rA + 8) * 66 + ks * 8 + lq];
            a2lo[2] = H1l[rA * 66 + ks * 8 + lq + 4];
            a2lo[3] = H1l[(rA + 8) * 66 + ks * 8 + lq + 4];
#pragma unroll
            for (int nt = 0; nt < 8; nt++) {
                const unsigned* bh = W2s + (ks * 256 + nt * 32 + lane) * 2;
                const unsigned* bl = W2s + 4096 + (ks * 256 + nt * 32 + lane) * 2;
                unsigned bhv[2] = { bh[0], bh[1] };
                unsigned blv[2] = { bl[0], bl[1] };
                mma_bf16(acc2[nt], a2hi, bhv);
                mma_bf16(acc2[nt], a2hi, blv);
                mma_bf16(acc2[nt], a2lo, bhv);
            }
        }

        // epilogue 2: bias + relu + dot w3, quad-reduce, write
        float sA = 0.f, sB = 0.f;
#pragma unroll
        for (int nt = 0; nt < 8; nt++) {
            float2 bv = *(float2*)(b2s + nt * 8 + 2 * lq);
            float2 wv = *(float2*)(w3s + nt * 8 + 2 * lq);
            sA = fmaf(fmaxf(acc2[nt][0] + bv.x, 0.f), wv.x, sA);
            sA = fmaf(fmaxf(acc2[nt][1] + bv.y, 0.f), wv.y, sA);
            sB = fmaf(fmaxf(acc2[nt][2] + bv.x, 0.f), wv.x, sB);
            sB = fmaf(fmaxf(acc2[nt][3] + bv.y, 0.f), wv.y, sB);
        }
        sA += __shfl_xor_sync(0xffffffffu, sA, 1);
        sA += __shfl_xor_sync(0xffffffffu, sA, 2);
        sB += __shfl_xor_sync(0xffffffffu, sB, 1);
        sB += __shfl_xor_sync(0xffffffffu, sB, 2);
        if (lq == 0) {
            float pA = (hp > 0.f) ? (sA + b3) : rawv[rA];
            float pB = (hp > 0.f) ? (sB + b3) : rawv[rA + 8];
            out_pred[(row0 + rA) * 16 + v] = pA;
            out_pred[(row0 + rA + 8) * 16 + v] = pB;
        }
    }
}

// ---------------- Kernel C: pair scorer (4 thr/pair, ILP-2 samples) ----------------
__global__ void __launch_bounds__(960) k_pairs(
    const float* __restrict__ data,
    const float* __restrict__ Wt1, const float* __restrict__ bt1,
    const float* __restrict__ Wt2, const float* __restrict__ bt2)
{
    __shared__ float rows[64 * 17];
    int tid = threadIdx.x;
    int sbase = blockIdx.x * 64;
    for (int t = tid; t < 1024; t += 960) {
        int s = t >> 4, j = t & 15;
        rows[s * 17 + j] = data[(sbase + s) * 16 + j];
    }
    __syncthreads();

    int p = tid >> 2, q = tid & 3;
    int pi = p / 15, r = p - pi * 15;
    int pj = r + (r >= pi ? 1 : 0);
    int co = q * 8;
    float4 wa0 = *(const float4*)(Wt1 + p * 64 + co);
    float4 wa1 = *(const float4*)(Wt1 + p * 64 + co + 4);
    float4 wb0 = *(const float4*)(Wt1 + p * 64 + 32 + co);
    float4 wb1 = *(const float4*)(Wt1 + p * 64 + 32 + co + 4);
    float4 bb0 = *(const float4*)(bt1 + p * 32 + co);
    float4 bb1 = *(const float4*)(bt1 + p * 32 + co + 4);
    float4 w20 = *(const float4*)(Wt2 + p * 32 + co);
    float4 w21 = *(const float4*)(Wt2 + p * 32 + co + 4);
    float b2v = bt2[p];

    float accs = 0.f;
    for (int s = 0; s < 64; s += 2) {
        float aX = rows[s * 17 + pi],       bX = rows[s * 17 + pj];
        float aY = rows[(s+1) * 17 + pi],   bY = rows[(s+1) * 17 + pj];
        float2 xiX = make_float2(aX, aX), xjX = make_float2(bX, bX);
        float2 xiY = make_float2(aY, aY), xjY = make_float2(bY, bY);
        float2 sv0X = make_float2(0.f, 0.f), sv1X = make_float2(0.f, 0.f);
        float2 sv0Y = make_float2(0.f, 0.f), sv1Y = make_float2(0.f, 0.f);
        float2 h;
        // chain X + Y interleaved (independent)
        h = ffma2(xiX, make_float2(wa0.x, wa0.y), make_float2(bb0.x, bb0.y));
        h = ffma2(xjX, make_float2(wb0.x, wb0.y), h);
        h.x = fmaxf(h.x, 0.f); h.y = fmaxf(h.y, 0.f);
        sv0X = ffma2(h, make_float2(w20.x, w20.y), sv0X);
        h = ffma2(xiY, make_float2(wa0.x, wa0.y), make_float2(bb0.x, bb0.y));
        h = ffma2(xjY, make_float2(wb0.x, wb0.y), h);
        h.x = fmaxf(h.x, 0.f); h.y = fmaxf(h.y, 0.f);
        sv0Y = ffma2(h, make_float2(w20.x, w20.y), sv0Y);

        h = ffma2(xiX, make_float2(wa0.z, wa0.w), make_float2(bb0.z, bb0.w));
        h = ffma2(xjX, make_float2(wb0.z, wb0.w), h);
        h.x = fmaxf(h.x, 0.f); h.y = fmaxf(h.y, 0.f);
        sv1X = ffma2(h, make_float2(w20.z, w20.w), sv1X);
        h = ffma2(xiY, make_float2(wa0.z, wa0.w), make_float2(bb0.z, bb0.w));
        h = ffma2(xjY, make_float2(wb0.z, wb0.w), h);
        h.x = fmaxf(h.x, 0.f); h.y = fmaxf(h.y, 0.f);
        sv1Y = ffma2(h, make_float2(w20.z, w20.w), sv1Y);

        h = ffma2(xiX, make_float2(wa1.x, wa1.y), make_float2(bb1.x, bb1.y));
        h = ffma2(xjX, make_float2(wb1.x, wb1.y), h);
        h.x = fmaxf(h.x, 0.f); h.y = fmaxf(h.y, 0.f);
        sv0X = ffma2(h, make_float2(w21.x, w21.y), sv0X);
        h = ffma2(xiY, make_float2(wa1.x, wa1.y), make_float2(bb1.x, bb1.y));
        h = ffma2(xjY, make_float2(wb1.x, wb1.y), h);
        h.x = fmaxf(h.x, 0.f); h.y = fmaxf(h.y, 0.f);
        sv0Y = ffma2(h, make_float2(w21.x, w21.y), sv0Y);

        h = ffma2(xiX, make_float2(wa1.z, wa1.w), make_float2(bb1.z, bb1.w));
        h = ffma2(xjX, make_float2(wb1.z, wb1.w), h);
        h.x = fmaxf(h.x, 0.f); h.y = fmaxf(h.y, 0.f);
        sv1X = ffma2(h, make_float2(w21.z, w21.w), sv1X);
        h = ffma2(xiY, make_float2(wa1.z, wa1.w), make_float2(bb1.z, bb1.w));
        h = ffma2(xjY, make_float2(wb1.z, wb1.w), h);
        h.x = fmaxf(h.x, 0.f); h.y = fmaxf(h.y, 0.f);
        sv1Y = ffma2(h, make_float2(w21.z, w21.w), sv1Y);

        float svX = (sv0X.x + sv0X.y) + (sv1X.x + sv1X.y);
        float svY = (sv0Y.x + sv0Y.y) + (sv1Y.x + sv1Y.y);
        svX += __shfl_xor_sync(0xffffffffu, svX, 1);
        svY += __shfl_xor_sync(0xffffffffu, svY, 1);
        svX += __shfl_xor_sync(0xffffffffu, svX, 2);
        svY += __shfl_xor_sync(0xffffffffu, svY, 2);
        float sgX = __fdividef(1.f, 1.f + __expf(-(svX + b2v)));
        float sgY = __fdividef(1.f, 1.f + __expf(-(svY + b2v)));
        accs += sgX;
        accs += sgY;
    }
    if (q == 0) g_part[p * 128 + blockIdx.x] = accs;
}

// ---------------- Kernel D: finalize ----------------
__global__ void __launch_bounds__(256) k_fin(float* __restrict__ out_scores) {
    int t = threadIdx.x;
    if (t < 240) {
        const float4* b = (const float4*)(g_part + t * 128);
        float s = 0.f;
#pragma unroll
        for (int i = 0; i < 32; i++) {
            float4 v = b[i];
            s += (v.x + v.y) + (v.z + v.w);
        }
        int pi = t / 15, r = t - pi * 15;
        int pj = r + (r >= pi ? 1 : 0);
        out_scores[pi * 16 + pj] = s * (1.f / 8192.f);
    }
    if (t < 16) out_scores[t * 17] = 0.f;
}

// ---------------- launch ----------------
extern "C" void kernel_launch(void* const* d_in, const int* in_sizes, int n_in,
                              void* d_out, int out_size) {
    const float* data = (const float*)d_in[0];
    const float* Ws1 = (const float*)d_in[1];
    const float* bs1 = (const float*)d_in[2];
    const float* Ws2 = (const float*)d_in[3];
    const float* bs2 = (const float*)d_in[4];
    const float* Ws3 = (const float*)d_in[5];
    const float* bs3 = (const float*)d_in[6];
    const float* Wm1 = (const float*)d_in[7];
    const float* bm1 = (const float*)d_in[8];
    const float* Wm2 = (const float*)d_in[9];
    const float* bm2 = (const float*)d_in[10];
    const float* Wm3 = (const float*)d_in[11];
    const float* bm3 = (const float*)d_in[12];
    const float* Wt1 = (const float*)d_in[13];
    const float* bt1 = (const float*)d_in[14];
    const float* Wt2 = (const float*)d_in[15];
    const float* bt2 = (const float*)d_in[16];

    float* out = (float*)d_out;
    float* out_adj    = out;
    float* out_pred   = out + 256;
    float* out_scores = out + 256 + 131072;

    cudaFuncSetAttribute(k_mech, cudaFuncAttributeMaxDynamicSharedMemorySize, 119360);

    k_pack<<<16, 256>>>(Wm1, Wm2);
    k_avg<<<32, 64>>>(data);
    k_adj<<<1, 1024>>>(Ws1, bs1, Ws2, bs2, Ws3, bs3, out_adj);
    k_mech<<<dim3(8, 16), 256, 119360>>>(data, bm1, bm2, Wm3, bm3, out_pred);
    k_pairs<<<128, 960>>>(data, Wt1, bt1, Wt2, bt2);
    k_fin<<<1, 256>>>(out_scores);
}

// round 8
// speedup vs baseline: 2.1571x; 1.1688x over previous
#include <cuda_runtime.h>
#include <cuda_bf16.h>
#include <math.h>

#define NV 16

// ---------------- device scratch ----------------
__device__ float g_avg[512 * 16];
__device__ float g_pm[240];
__device__ float g_hp[16];
__device__ float g_part[240 * 128];
__device__ unsigned g_wpack[16 * 10240];   // per-v packed bf16 hi/lo weight fragments

// packed f32x2 FMA (k_pairs)
union F2U { float2 f; unsigned long long u; };
__device__ __forceinline__ float2 ffma2(float2 a, float2 b, float2 c) {
    F2U au, bu, cu, du;
    au.f = a; bu.f = b; cu.f = c;
    asm("fma.rn.f32x2 %0, %1, %2, %3;" : "=l"(du.u) : "l"(au.u), "l"(bu.u), "l"(cu.u));
    return du.f;
}

// bf16 m16n8k16 MMA, fp32 accumulate
__device__ __forceinline__ void mma_bf16(float* d, const unsigned* a, const unsigned* b) {
    asm volatile(
        "mma.sync.aligned.m16n8k16.row.col.f32.bf16.bf16.f32 "
        "{%0,%1,%2,%3}, {%4,%5,%6,%7}, {%8,%9}, {%0,%1,%2,%3};"
        : "+f"(d[0]), "+f"(d[1]), "+f"(d[2]), "+f"(d[3])
        : "r"(a[0]), "r"(a[1]), "r"(a[2]), "r"(a[3]), "r"(b[0]), "r"(b[1]));
}

__device__ __forceinline__ unsigned pack2bf(float a, float b) {
    __nv_bfloat162 h = __floats2bfloat162_rn(a, b);
    return *reinterpret_cast<unsigned*>(&h);
}
__device__ __forceinline__ float bfround(float x) {
    return __bfloat162float(__float2bfloat16_rn(x));
}

// ---------------- Kernel P: one-time weight prepack (64 blocks) ----------------
// g_wpack[v]: W1P [part2][nt16][lane32][r2] = 2048 u32 ; W2P [part2][ks8][nt8][lane32][r2] = 8192 u32
__global__ void __launch_bounds__(256) k_pack(
    const float* __restrict__ Wm1, const float* __restrict__ Wm2)
{
    int v = blockIdx.x >> 2, quarter = blockIdx.x & 3, tid = threadIdx.x;
    unsigned* dst = g_wpack + v * 10240;
    for (int idx = quarter * 512 + tid; idx < quarter * 512 + 512; idx += 256) {
        int part = idx >> 10, rem = idx & 1023;
        int nt = rem >> 6, lane = (rem >> 1) & 31, r = rem & 1;
        int lg = lane >> 2, lq = lane & 3;
        int n = nt * 8 + lg, kp = lq + 4 * r;
        int k0 = 2 * kp, k1 = 2 * kp + 1;
        float w0 = (k0 < 15) ? Wm1[v * 1920 + k0 * 128 + n] : 0.f;
        float w1 = (k1 < 15) ? Wm1[v * 1920 + k1 * 128 + n] : 0.f;
        if (part == 0) dst[idx] = pack2bf(w0, w1);
        else dst[idx] = pack2bf(w0 - bfround(w0), w1 - bfround(w1));
    }
    for (int idx = quarter * 2048 + tid; idx < quarter * 2048 + 2048; idx += 256) {
        int part = idx >> 12, rem = idx & 4095;
        int ks = rem >> 9, nt = (rem >> 6) & 7, lane = (rem >> 1) & 31, r = rem & 1;
        int lg = lane >> 2, lq = lane & 3;
        int n = nt * 8 + lg, kp = ks * 8 + lq + 4 * r;
        int k0 = 2 * kp, k1 = 2 * kp + 1;
        float w0 = Wm2[v * 8192 + k0 * 64 + n];
        float w1 = Wm2[v * 8192 + k1 * 64 + n];
        if (part == 0) dst[2048 + idx] = pack2bf(w0, w1);
        else dst[2048 + idx] = pack2bf(w0 - bfround(w0), w1 - bfround(w1));
    }
}

// ---------------- Kernel A1: avg over batch ----------------
__global__ void k_avg(const float* __restrict__ data) {
    int t = blockIdx.x * 64 + threadIdx.x;
    float4 s = make_float4(0.f, 0.f, 0.f, 0.f);
#pragma unroll
    for (int b = 0; b < 16; b++) {
        float4 v = *(const float4*)(data + b * 8192 + t * 4);
        s.x += v.x; s.y += v.y; s.z += v.z; s.w += v.w;
    }
    s.x *= (1.f/16.f); s.y *= (1.f/16.f); s.z *= (1.f/16.f); s.w *= (1.f/16.f);
    *(float4*)(g_avg + t * 4) = s;
}

// ---------------- Kernel A2: cov -> corr -> MLP -> adj -> masks ----------------
__global__ void __launch_bounds__(1024) k_adj(
    const float* __restrict__ Ws1, const float* __restrict__ bs1,
    const float* __restrict__ Ws2, const float* __restrict__ bs2,
    const float* __restrict__ Ws3, const float* __restrict__ bs3,
    float* __restrict__ out_adj)
{
    __shared__ float av[8192];
    __shared__ float scratch[1024];
    __shared__ float cm[16];
    __shared__ float covs[256];
    __shared__ float corr_s[256];
    __shared__ float h1s[256];
    __shared__ float h2s[128];
    __shared__ float adj_s[256];
    __shared__ float pms[240];

    int tid = threadIdx.x;
    for (int i = tid; i < 2048; i += 1024)
        *(float4*)(av + i * 4) = *(const float4*)(g_avg + i * 4);
    __syncthreads();

    if (tid < 512) {
        int j = tid & 15, part = tid >> 4;
        float s = 0.f;
        for (int r = 0; r < 16; r++) s += av[(part * 16 + r) * 16 + j];
        scratch[tid] = s;
    }
    __syncthreads();
    if (tid < 16) {
        float s = 0.f;
        for (int part = 0; part < 32; part++) s += scratch[part * 16 + tid];
        cm[tid] = s * (1.f / 512.f);
    }
    __syncthreads();

    {
        int pair = tid >> 2, q = tid & 3;
        int i = pair >> 4, j = pair & 15;
        float ci = cm[i], cj = cm[j];
        float s = 0.f;
        for (int r = q * 128; r < q * 128 + 128; r++)
            s += (av[r * 16 + i] - ci) * (av[r * 16 + j] - cj);
        scratch[tid] = s;
    }
    __syncthreads();
    if (tid < 256)
        covs[tid] = scratch[tid*4] + scratch[tid*4+1] + scratch[tid*4+2] + scratch[tid*4+3];
    __syncthreads();
    if (tid < 256) {
        int i = tid >> 4, j = tid & 15;
        float si = sqrtf(fmaxf(covs[i * 16 + i], 0.f));
        float sj = sqrtf(fmaxf(covs[j * 16 + j], 0.f));
        float denom = si * sj;
        float c = denom > 0.f ? covs[tid] / denom : 0.f;
        c = fabsf(c);
        if (i == j) c = 0.f;
        corr_s[tid] = c;
    }
    __syncthreads();

    {
        int o = tid & 255, q = tid >> 8;
        float s = 0.f;
        for (int k = q * 64; k < q * 64 + 64; k++) s = fmaf(corr_s[k], Ws1[k * 256 + o], s);
        scratch[q * 256 + o] = s;
    }
    __syncthreads();
    if (tid < 256)
        h1s[tid] = fmaxf(scratch[tid] + scratch[256 + tid] + scratch[512 + tid] + scratch[768 + tid] + bs1[tid], 0.f);
    __syncthreads();

    {
        int o = tid & 127, q = tid >> 7;
        float s = 0.f;
        for (int k = q * 32; k < q * 32 + 32; k++) s = fmaf(h1s[k], Ws2[k * 128 + o], s);
        scratch[q * 128 + o] = s;
    }
    __syncthreads();
    if (tid < 128) {
        float s = bs2[tid];
        for (int q = 0; q < 8; q++) s += scratch[q * 128 + tid];
        h2s[tid] = fmaxf(s, 0.f);
    }
    __syncthreads();

    {
        int o = tid & 255, q = tid >> 8;
        float s = 0.f;
        for (int k = q * 32; k < q * 32 + 32; k++) s = fmaf(h2s[k], Ws3[k * 256 + o], s);
        scratch[q * 256 + o] = s;
    }
    __syncthreads();
    if (tid < 256) {
        float logit = scratch[tid] + scratch[256 + tid] + scratch[512 + tid] + scratch[768 + tid] + bs3[tid];
        float a = 1.f / (1.f + expf(-logit));
        int i = tid >> 4, j = tid & 15;
        float val = (j > i) ? a : 0.f;
        adj_s[tid] = val;
        out_adj[tid] = val;
    }
    __syncthreads();
    if (tid < 240) {
        int v = tid / 15, p = tid - v * 15;
        int g = p + (p >= v ? 1 : 0);
        float m = (adj_s[g * 16 + v] > 0.5f) ? 1.f : 0.f;
        pms[tid] = m;
        g_pm[tid] = m;
    }
    __syncthreads();
    if (tid < 16) {
        float s = 0.f;
        for (int p = 0; p < 15; p++) s += pms[tid * 15 + p];
        g_hp[tid] = (s > 0.f) ? 1.f : 0.f;
    }
}

// ---------------- Kernel B: mechanism MLP (bf16 HMMA, fragment passthrough) ----------------
// grid (16, 16): bx owns 512 rows (4 tiles of 128), by = v. 256 thr (8 warps), 2 blocks/SM.
// Layer1 D-fragments convert IN REGISTERS to layer2 A-fragments (no H1 smem).
// smem words: Wp 10240 @0 | b1s 128 @10240 | b2s 64 @10368 | w3s 64 @10432
//             pms 16 @10496 | rawv 128 @10512 | Xh 1152 @10640 | Xl 1152 @11792
// total 12944 words = 51776 B
__global__ void __launch_bounds__(256, 2) k_mech(
    const float* __restrict__ data,
    const float* __restrict__ bm1,
    const float* __restrict__ bm2,
    const float* __restrict__ Wm3, const float* __restrict__ bm3,
    float* __restrict__ out_pred)
{
    extern __shared__ float sm[];
    const int v = blockIdx.y;
    unsigned* Wp  = (unsigned*)sm;
    float* b1s  = sm + 10240;
    float* b2s  = sm + 10368;
    float* w3s  = sm + 10432;
    float* pms  = sm + 10496;
    float* rawv = sm + 10512;
    unsigned* Xh  = (unsigned*)(sm + 10640);
    unsigned* Xl  = (unsigned*)(sm + 11792);

    int tid = threadIdx.x;
    int w = tid >> 5, lane = tid & 31;
    int lq = lane & 3, lg = lane >> 2;

    {
        const float4* src = (const float4*)(g_wpack + v * 10240);
        float4* dst = (float4*)Wp;
        for (int i = tid; i < 2560; i += 256) dst[i] = src[i];
    }
    if (tid < 128) b1s[tid] = bm1[v * 128 + tid];
    if (tid < 64) { b2s[tid] = bm2[v * 64 + tid]; w3s[tid] = Wm3[v * 64 + tid]; }
    if (tid < 16) pms[tid] = (tid < 15) ? g_pm[v * 15 + tid] : 0.f;
    float hp = g_hp[v];
    float b3 = bm3[v];

    const unsigned* W1s = Wp;
    const unsigned* W2s = Wp + 2048;
    int rA = w * 16 + lg;

    for (int tile = 0; tile < 4; tile++) {
        __syncthreads();
        int row0 = blockIdx.x * 512 + tile * 128;
        // build masked, split input Xh/Xl [128][9] and raw column v
        for (int idx = tid; idx < 1024; idx += 256) {
            int row = idx >> 3, kp = idx & 7;
            int p0 = 2 * kp, p1 = 2 * kp + 1;
            const float* drow = data + (row0 + row) * 16;
            float v0 = 0.f, v1 = 0.f;
            v0 = drow[p0 + (p0 >= v ? 1 : 0)] * pms[p0];
            if (p1 < 15) v1 = drow[p1 + (p1 >= v ? 1 : 0)] * pms[p1];
            Xh[row * 9 + kp] = pack2bf(v0, v1);
            Xl[row * 9 + kp] = pack2bf(v0 - bfround(v0), v1 - bfround(v1));
        }
        if (tid < 128) rawv[tid] = data[(row0 + tid) * 16 + v];
        __syncthreads();

        // layer-1 A fragments (rows rA, rA+8; K=16)
        unsigned ahi[4], alo[4];
        ahi[0] = Xh[rA * 9 + lq];           ahi[1] = Xh[(rA + 8) * 9 + lq];
        ahi[2] = Xh[rA * 9 + lq + 4];       ahi[3] = Xh[(rA + 8) * 9 + lq + 4];
        alo[0] = Xl[rA * 9 + lq];           alo[1] = Xl[(rA + 8) * 9 + lq];
        alo[2] = Xl[rA * 9 + lq + 4];       alo[3] = Xl[(rA + 8) * 9 + lq + 4];

        float acc2[8][4];
#pragma unroll
        for (int nt = 0; nt < 8; nt++)
#pragma unroll
            for (int i = 0; i < 4; i++) acc2[nt][i] = 0.f;

#pragma unroll
        for (int ks = 0; ks < 8; ks++) {
            // ---- layer 1 for nt = 2ks, 2ks+1 (6 MMAs)
            float acc1a[4] = {0.f, 0.f, 0.f, 0.f};
            float acc1b[4] = {0.f, 0.f, 0.f, 0.f};
            {
                int nt0 = 2 * ks, nt1 = 2 * ks + 1;
                const unsigned* bh0 = W1s + (nt0 * 32 + lane) * 2;
                const unsigned* bl0 = W1s + 1024 + (nt0 * 32 + lane) * 2;
                const unsigned* bh1 = W1s + (nt1 * 32 + lane) * 2;
                const unsigned* bl1 = W1s + 1024 + (nt1 * 32 + lane) * 2;
                unsigned bh0v[2] = { bh0[0], bh0[1] }, bl0v[2] = { bl0[0], bl0[1] };
                unsigned bh1v[2] = { bh1[0], bh1[1] }, bl1v[2] = { bl1[0], bl1[1] };
                mma_bf16(acc1a, ahi, bh0v);
                mma_bf16(acc1b, ahi, bh1v);
                mma_bf16(acc1a, ahi, bl0v);
                mma_bf16(acc1b, ahi, bl1v);
                mma_bf16(acc1a, alo, bh0v);
                mma_bf16(acc1b, alo, bh1v);
            }
            // ---- register epilogue -> layer-2 A fragments for this ks
            unsigned a2hi[4], a2lo[4];
            {
                float2 bva = *(float2*)(b1s + (2 * ks) * 8 + 2 * lq);
                float2 bvb = *(float2*)(b1s + (2 * ks + 1) * 8 + 2 * lq);
                float h0 = fmaxf(acc1a[0] + bva.x, 0.f);
                float h1 = fmaxf(acc1a[1] + bva.y, 0.f);
                float h2 = fmaxf(acc1a[2] + bva.x, 0.f);
                float h3 = fmaxf(acc1a[3] + bva.y, 0.f);
                float h4 = fmaxf(acc1b[0] + bvb.x, 0.f);
                float h5 = fmaxf(acc1b[1] + bvb.y, 0.f);
                float h6 = fmaxf(acc1b[2] + bvb.x, 0.f);
                float h7 = fmaxf(acc1b[3] + bvb.y, 0.f);
                a2hi[0] = pack2bf(h0, h1);
                a2hi[1] = pack2bf(h2, h3);
                a2hi[2] = pack2bf(h4, h5);
                a2hi[3] = pack2bf(h6, h7);
                a2lo[0] = pack2bf(h0 - bfround(h0), h1 - bfround(h1));
                a2lo[1] = pack2bf(h2 - bfround(h2), h3 - bfround(h3));
                a2lo[2] = pack2bf(h4 - bfround(h4), h5 - bfround(h5));
                a2lo[3] = pack2bf(h6 - bfround(h6), h7 - bfround(h7));
            }
            // ---- layer 2: 8 nt x 3 MMAs
#pragma unroll
            for (int nt = 0; nt < 8; nt++) {
                const unsigned* bh = W2s + (ks * 256 + nt * 32 + lane) * 2;
                const unsigned* bl = W2s + 4096 + (ks * 256 + nt * 32 + lane) * 2;
                unsigned bhv[2] = { bh[0], bh[1] };
                unsigned blv[2] = { bl[0], bl[1] };
                mma_bf16(acc2[nt], a2hi, bhv);
                mma_bf16(acc2[nt], a2hi, blv);
                mma_bf16(acc2[nt], a2lo, bhv);
            }
        }

        // epilogue 2: bias + relu + dot w3, quad-reduce, write
        float sA = 0.f, sB = 0.f;
#pragma unroll
        for (int nt = 0; nt < 8; nt++) {
            float2 bv = *(float2*)(b2s + nt * 8 + 2 * lq);
            float2 wv = *(float2*)(w3s + nt * 8 + 2 * lq);
            sA = fmaf(fmaxf(acc2[nt][0] + bv.x, 0.f), wv.x, sA);
            sA = fmaf(fmaxf(acc2[nt][1] + bv.y, 0.f), wv.y, sA);
            sB = fmaf(fmaxf(acc2[nt][2] + bv.x, 0.f), wv.x, sB);
            sB = fmaf(fmaxf(acc2[nt][3] + bv.y, 0.f), wv.y, sB);
        }
        sA += __shfl_xor_sync(0xffffffffu, sA, 1);
        sA += __shfl_xor_sync(0xffffffffu, sA, 2);
        sB += __shfl_xor_sync(0xffffffffu, sB, 1);
        sB += __shfl_xor_sync(0xffffffffu, sB, 2);
        if (lq == 0) {
            float pA = (hp > 0.f) ? (sA + b3) : rawv[rA];
            float pB = (hp > 0.f) ? (sB + b3) : rawv[rA + 8];
            out_pred[(row0 + rA) * 16 + v] = pA;
            out_pred[(row0 + rA + 8) * 16 + v] = pB;
        }
    }
}

// ---------------- Kernel C: pair scorer (4 thr/pair, ILP-2 samples) ----------------
__global__ void __launch_bounds__(960) k_pairs(
    const float* __restrict__ data,
    const float* __restrict__ Wt1, const float* __restrict__ bt1,
    const float* __restrict__ Wt2, const float* __restrict__ bt2)
{
    __shared__ float rows[64 * 17];
    int tid = threadIdx.x;
    int sbase = blockIdx.x * 64;
    for (int t = tid; t < 1024; t += 960) {
        int s = t >> 4, j = t & 15;
        rows[s * 17 + j] = data[(sbase + s) * 16 + j];
    }
    __syncthreads();

    int p = tid >> 2, q = tid & 3;
    int pi = p / 15, r = p - pi * 15;
    int pj = r + (r >= pi ? 1 : 0);
    int co = q * 8;
    float4 wa0 = *(const float4*)(Wt1 + p * 64 + co);
    float4 wa1 = *(const float4*)(Wt1 + p * 64 + co + 4);
    float4 wb0 = *(const float4*)(Wt1 + p * 64 + 32 + co);
    float4 wb1 = *(const float4*)(Wt1 + p * 64 + 32 + co + 4);
    float4 bb0 = *(const float4*)(bt1 + p * 32 + co);
    float4 bb1 = *(const float4*)(bt1 + p * 32 + co + 4);
    float4 w20 = *(const float4*)(Wt2 + p * 32 + co);
    float4 w21 = *(const float4*)(Wt2 + p * 32 + co + 4);
    float b2v = bt2[p];

    float accs = 0.f;
    for (int s = 0; s < 64; s += 2) {
        float aX = rows[s * 17 + pi],       bX = rows[s * 17 + pj];
        float aY = rows[(s+1) * 17 + pi],   bY = rows[(s+1) * 17 + pj];
        float2 xiX = make_float2(aX, aX), xjX = make_float2(bX, bX);
        float2 xiY = make_float2(aY, aY), xjY = make_float2(bY, bY);
        float2 sv0X = make_float2(0.f, 0.f), sv1X = make_float2(0.f, 0.f);
        float2 sv0Y = make_float2(0.f, 0.f), sv1Y = make_float2(0.f, 0.f);
        float2 h;
        h = ffma2(xiX, make_float2(wa0.x, wa0.y), make_float2(bb0.x, bb0.y));
        h = ffma2(xjX, make_float2(wb0.x, wb0.y), h);
        h.x = fmaxf(h.x, 0.f); h.y = fmaxf(h.y, 0.f);
        sv0X = ffma2(h, make_float2(w20.x, w20.y), sv0X);
        h = ffma2(xiY, make_float2(wa0.x, wa0.y), make_float2(bb0.x, bb0.y));
        h = ffma2(xjY, make_float2(wb0.x, wb0.y), h);
        h.x = fmaxf(h.x, 0.f); h.y = fmaxf(h.y, 0.f);
        sv0Y = ffma2(h, make_float2(w20.x, w20.y), sv0Y);

        h = ffma2(xiX, make_float2(wa0.z, wa0.w), make_float2(bb0.z, bb0.w));
        h = ffma2(xjX, make_float2(wb0.z, wb0.w), h);
        h.x = fmaxf(h.x, 0.f); h.y = fmaxf(h.y, 0.f);
        sv1X = ffma2(h, make_float2(w20.z, w20.w), sv1X);
        h = ffma2(xiY, make_float2(wa0.z, wa0.w), make_float2(bb0.z, bb0.w));
        h = ffma2(xjY, make_float2(wb0.z, wb0.w), h);
        h.x = fmaxf(h.x, 0.f); h.y = fmaxf(h.y, 0.f);
        sv1Y = ffma2(h, make_float2(w20.z, w20.w), sv1Y);

        h = ffma2(xiX, make_float2(wa1.x, wa1.y), make_float2(bb1.x, bb1.y));
        h = ffma2(xjX, make_float2(wb1.x, wb1.y), h);
        h.x = fmaxf(h.x, 0.f); h.y = fmaxf(h.y, 0.f);
        sv0X = ffma2(h, make_float2(w21.x, w21.y), sv0X);
        h = ffma2(xiY, make_float2(wa1.x, wa1.y), make_float2(bb1.x, bb1.y));
        h = ffma2(xjY, make_float2(wb1.x, wb1.y), h);
        h.x = fmaxf(h.x, 0.f); h.y = fmaxf(h.y, 0.f);
        sv0Y = ffma2(h, make_float2(w21.x, w21.y), sv0Y);

        h = ffma2(xiX, make_float2(wa1.z, wa1.w), make_float2(bb1.z, bb1.w));
        h = ffma2(xjX, make_float2(wb1.z, wb1.w), h);
        h.x = fmaxf(h.x, 0.f); h.y = fmaxf(h.y, 0.f);
        sv1X = ffma2(h, make_float2(w21.z, w21.w), sv1X);
        h = ffma2(xiY, make_float2(wa1.z, wa1.w), make_float2(bb1.z, bb1.w));
        h = ffma2(xjY, make_float2(wb1.z, wb1.w), h);
        h.x = fmaxf(h.x, 0.f); h.y = fmaxf(h.y, 0.f);
        sv1Y = ffma2(h, make_float2(w21.z, w21.w), sv1Y);

        float svX = (sv0X.x + sv0X.y) + (sv1X.x + sv1X.y);
        float svY = (sv0Y.x + sv0Y.y) + (sv1Y.x + sv1Y.y);
        svX += __shfl_xor_sync(0xffffffffu, svX, 1);
        svY += __shfl_xor_sync(0xffffffffu, svY, 1);
        svX += __shfl_xor_sync(0xffffffffu, svX, 2);
        svY += __shfl_xor_sync(0xffffffffu, svY, 2);
        float sgX = __fdividef(1.f, 1.f + __expf(-(svX + b2v)));
        float sgY = __fdividef(1.f, 1.f + __expf(-(svY + b2v)));
        accs += sgX;
        accs += sgY;
    }
    if (q == 0) g_part[p * 128 + blockIdx.x] = accs;
}

// ---------------- Kernel D: finalize ----------------
__global__ void __launch_bounds__(256) k_fin(float* __restrict__ out_scores) {
    int t = threadIdx.x;
    if (t < 240) {
        const float4* b = (const float4*)(g_part + t * 128);
        float s = 0.f;
#pragma unroll
        for (int i = 0; i < 32; i++) {
            float4 v = b[i];
            s += (v.x + v.y) + (v.z + v.w);
        }
        int pi = t / 15, r = t - pi * 15;
        int pj = r + (r >= pi ? 1 : 0);
        out_scores[pi * 16 + pj] = s * (1.f / 8192.f);
    }
    if (t < 16) out_scores[t * 17] = 0.f;
}

// ---------------- launch ----------------
extern "C" void kernel_launch(void* const* d_in, const int* in_sizes, int n_in,
                              void* d_out, int out_size) {
    const float* data = (const float*)d_in[0];
    const float* Ws1 = (const float*)d_in[1];
    const float* bs1 = (const float*)d_in[2];
    const float* Ws2 = (const float*)d_in[3];
    const float* bs2 = (const float*)d_in[4];
    const float* Ws3 = (const float*)d_in[5];
    const float* bs3 = (const float*)d_in[6];
    const float* Wm1 = (const float*)d_in[7];
    const float* bm1 = (const float*)d_in[8];
    const float* Wm2 = (const float*)d_in[9];
    const float* bm2 = (const float*)d_in[10];
    const float* Wm3 = (const float*)d_in[11];
    const float* bm3 = (const float*)d_in[12];
    const float* Wt1 = (const float*)d_in[13];
    const float* bt1 = (const float*)d_in[14];
    const float* Wt2 = (const float*)d_in[15];
    const float* bt2 = (const float*)d_in[16];

    float* out = (float*)d_out;
    float* out_adj    = out;
    float* out_pred   = out + 256;
    float* out_scores = out + 256 + 131072;

    cudaFuncSetAttribute(k_mech, cudaFuncAttributeMaxDynamicSharedMemorySize, 51776);

    k_pack<<<64, 256>>>(Wm1, Wm2);
    k_avg<<<32, 64>>>(data);
    k_adj<<<1, 1024>>>(Ws1, bs1, Ws2, bs2, Ws3, bs3, out_adj);
    k_mech<<<dim3(16, 16), 256, 51776>>>(data, bm1, bm2, Wm3, bm3, out_pred);
    k_pairs<<<128, 960>>>(data, Wt1, bt1, Wt2, bt2);
    k_fin<<<1, 256>>>(out_scores);
}

// round 9
// speedup vs baseline: 2.7674x; 1.2829x over previous
#include <cuda_runtime.h>
#include <cuda_bf16.h>
#include <math.h>

#define NV 16

// ---------------- device scratch ----------------
__device__ float g_pm[240];
__device__ float g_hp[16];
__device__ float g_part[240 * 128];
__device__ unsigned g_wpack[16 * 10240];
__device__ float g_gram[32 * 256];     // per-block Gram partials
__device__ float g_colsum[32 * 16];    // per-block column-sum partials

// packed f32x2 FMA (k_pairs)
union F2U { float2 f; unsigned long long u; };
__device__ __forceinline__ float2 ffma2(float2 a, float2 b, float2 c) {
    F2U au, bu, cu, du;
    au.f = a; bu.f = b; cu.f = c;
    asm("fma.rn.f32x2 %0, %1, %2, %3;" : "=l"(du.u) : "l"(au.u), "l"(bu.u), "l"(cu.u));
    return du.f;
}

// bf16 m16n8k16 MMA, fp32 accumulate
__device__ __forceinline__ void mma_bf16(float* d, const unsigned* a, const unsigned* b) {
    asm volatile(
        "mma.sync.aligned.m16n8k16.row.col.f32.bf16.bf16.f32 "
        "{%0,%1,%2,%3}, {%4,%5,%6,%7}, {%8,%9}, {%0,%1,%2,%3};"
        : "+f"(d[0]), "+f"(d[1]), "+f"(d[2]), "+f"(d[3])
        : "r"(a[0]), "r"(a[1]), "r"(a[2]), "r"(a[3]), "r"(b[0]), "r"(b[1]));
}

__device__ __forceinline__ unsigned pack2bf(float a, float b) {
    __nv_bfloat162 h = __floats2bfloat162_rn(a, b);
    return *reinterpret_cast<unsigned*>(&h);
}
__device__ __forceinline__ float bfround(float x) {
    return __bfloat162float(__float2bfloat16_rn(x));
}

// ---------------- Kernel P: weight prepack (blocks 0-63) + avg/Gram (blocks 64-95) ----------------
__global__ void __launch_bounds__(256) k_prep(
    const float* __restrict__ Wm1, const float* __restrict__ Wm2,
    const float* __restrict__ data)
{
    int bid = blockIdx.x, tid = threadIdx.x;
    if (bid < 64) {
        int v = bid >> 2, quarter = bid & 3;
        unsigned* dst = g_wpack + v * 10240;
        for (int idx = quarter * 512 + tid; idx < quarter * 512 + 512; idx += 256) {
            int part = idx >> 10, rem = idx & 1023;
            int nt = rem >> 6, lane = (rem >> 1) & 31, r = rem & 1;
            int lg = lane >> 2, lq = lane & 3;
            int n = nt * 8 + lg, kp = lq + 4 * r;
            int k0 = 2 * kp, k1 = 2 * kp + 1;
            float w0 = (k0 < 15) ? Wm1[v * 1920 + k0 * 128 + n] : 0.f;
            float w1 = (k1 < 15) ? Wm1[v * 1920 + k1 * 128 + n] : 0.f;
            if (part == 0) dst[idx] = pack2bf(w0, w1);
            else dst[idx] = pack2bf(w0 - bfround(w0), w1 - bfround(w1));
        }
        for (int idx = quarter * 2048 + tid; idx < quarter * 2048 + 2048; idx += 256) {
            int part = idx >> 12, rem = idx & 4095;
            int ks = rem >> 9, nt = (rem >> 6) & 7, lane = (rem >> 1) & 31, r = rem & 1;
            int lg = lane >> 2, lq = lane & 3;
            int n = nt * 8 + lg, kp = ks * 8 + lq + 4 * r;
            int k0 = 2 * kp, k1 = 2 * kp + 1;
            float w0 = Wm2[v * 8192 + k0 * 64 + n];
            float w1 = Wm2[v * 8192 + k1 * 64 + n];
            if (part == 0) dst[2048 + idx] = pack2bf(w0, w1);
            else dst[2048 + idx] = pack2bf(w0 - bfround(w0), w1 - bfround(w1));
        }
    } else {
        // avg over batch for 16 seq-rows, then local Gram + colsum partials
        __shared__ float avs[256];     // [16 rows][16 vars]
        int q = bid - 64;
        float s = 0.f;
#pragma unroll
        for (int b = 0; b < 16; b++) s += data[b * 8192 + q * 256 + tid];
        avs[tid] = s * (1.f / 16.f);
        __syncthreads();
        int i = tid >> 4, j = tid & 15;
        float g = 0.f;
#pragma unroll
        for (int r = 0; r < 16; r++) g += avs[r * 16 + i] * avs[r * 16 + j];
        g_gram[q * 256 + tid] = g;
        if (tid < 16) {
            float cs = 0.f;
#pragma unroll
            for (int r = 0; r < 16; r++) cs += avs[r * 16 + tid];
            g_colsum[q * 16 + tid] = cs;
        }
    }
}

// ---------------- Kernel A: corr -> MLP -> adj -> masks ----------------
__global__ void __launch_bounds__(1024) k_adj(
    const float* __restrict__ Ws1, const float* __restrict__ bs1,
    const float* __restrict__ Ws2, const float* __restrict__ bs2,
    const float* __restrict__ Ws3, const float* __restrict__ bs3,
    float* __restrict__ out_adj)
{
    __shared__ float scratch[1024];
    __shared__ float cm[16];
    __shared__ float covs[256];
    __shared__ float corr_s[256];
    __shared__ float h1s[256];
    __shared__ float h2s[128];
    __shared__ float adj_s[256];
    __shared__ float pms[240];

    int tid = threadIdx.x;
    // reduce Gram partials (1024 thr: 256 pairs x 4 chunks of 8)
    {
        int pr = tid & 255, q4 = tid >> 8;
        float s = 0.f;
#pragma unroll
        for (int q = q4 * 8; q < q4 * 8 + 8; q++) s += g_gram[q * 256 + pr];
        scratch[tid] = s;
    }
    if (tid < 16) {
        float s = 0.f;
#pragma unroll
        for (int q = 0; q < 32; q++) s += g_colsum[q * 16 + tid];
        cm[tid] = s * (1.f / 512.f);
    }
    __syncthreads();
    if (tid < 256) {
        float G = scratch[tid] + scratch[256 + tid] + scratch[512 + tid] + scratch[768 + tid];
        int i = tid >> 4, j = tid & 15;
        covs[tid] = G - 512.f * cm[i] * cm[j];
    }
    __syncthreads();
    if (tid < 256) {
        int i = tid >> 4, j = tid & 15;
        float si = sqrtf(fmaxf(covs[i * 16 + i], 0.f));
        float sj = sqrtf(fmaxf(covs[j * 16 + j], 0.f));
        float denom = si * sj;
        float c = denom > 0.f ? covs[tid] / denom : 0.f;
        c = fabsf(c);
        if (i == j) c = 0.f;
        corr_s[tid] = c;
    }
    __syncthreads();

    {
        int o = tid & 255, q = tid >> 8;
        float s = 0.f;
        for (int k = q * 64; k < q * 64 + 64; k++) s = fmaf(corr_s[k], Ws1[k * 256 + o], s);
        scratch[q * 256 + o] = s;
    }
    __syncthreads();
    if (tid < 256)
        h1s[tid] = fmaxf(scratch[tid] + scratch[256 + tid] + scratch[512 + tid] + scratch[768 + tid] + bs1[tid], 0.f);
    __syncthreads();

    {
        int o = tid & 127, q = tid >> 7;
        float s = 0.f;
        for (int k = q * 32; k < q * 32 + 32; k++) s = fmaf(h1s[k], Ws2[k * 128 + o], s);
        scratch[q * 128 + o] = s;
    }
    __syncthreads();
    if (tid < 128) {
        float s = bs2[tid];
        for (int q = 0; q < 8; q++) s += scratch[q * 128 + tid];
        h2s[tid] = fmaxf(s, 0.f);
    }
    __syncthreads();

    {
        int o = tid & 255, q = tid >> 8;
        float s = 0.f;
        for (int k = q * 32; k < q * 32 + 32; k++) s = fmaf(h2s[k], Ws3[k * 256 + o], s);
        scratch[q * 256 + o] = s;
    }
    __syncthreads();
    if (tid < 256) {
        float logit = scratch[tid] + scratch[256 + tid] + scratch[512 + tid] + scratch[768 + tid] + bs3[tid];
        float a = 1.f / (1.f + expf(-logit));
        int i = tid >> 4, j = tid & 15;
        float val = (j > i) ? a : 0.f;
        adj_s[tid] = val;
        out_adj[tid] = val;
    }
    __syncthreads();
    if (tid < 240) {
        int v = tid / 15, p = tid - v * 15;
        int g = p + (p >= v ? 1 : 0);
        float m = (adj_s[g * 16 + v] > 0.5f) ? 1.f : 0.f;
        pms[tid] = m;
        g_pm[tid] = m;
    }
    __syncthreads();
    if (tid < 16) {
        float s = 0.f;
        for (int p = 0; p < 15; p++) s += pms[tid * 15 + p];
        g_hp[tid] = (s > 0.f) ? 1.f : 0.f;
    }
}

// ---- k_mech helpers ----
__device__ __forceinline__ void l1_step(const unsigned* W1s, int lane, int ks,
    const unsigned* ahi, const unsigned* alo, float* a, float* b)
{
    int nt0 = 2 * ks, nt1 = nt0 + 1;
    const unsigned* bh0 = W1s + (nt0 * 32 + lane) * 2;
    const unsigned* bl0 = W1s + 1024 + (nt0 * 32 + lane) * 2;
    const unsigned* bh1 = W1s + (nt1 * 32 + lane) * 2;
    const unsigned* bl1 = W1s + 1024 + (nt1 * 32 + lane) * 2;
    unsigned bh0v[2] = { bh0[0], bh0[1] }, bl0v[2] = { bl0[0], bl0[1] };
    unsigned bh1v[2] = { bh1[0], bh1[1] }, bl1v[2] = { bl1[0], bl1[1] };
    mma_bf16(a, ahi, bh0v);
    mma_bf16(b, ahi, bh1v);
    mma_bf16(a, ahi, bl0v);
    mma_bf16(b, ahi, bl1v);
    mma_bf16(a, alo, bh0v);
    mma_bf16(b, alo, bh1v);
}

__device__ __forceinline__ void l1_epi(const float* b1s, int lq, int ks,
    const float* a, const float* b, unsigned* a2hi, unsigned* a2lo)
{
    float2 bva = *(const float2*)(b1s + (2 * ks) * 8 + 2 * lq);
    float2 bvb = *(const float2*)(b1s + (2 * ks + 1) * 8 + 2 * lq);
    float h0 = fmaxf(a[0] + bva.x, 0.f), h1 = fmaxf(a[1] + bva.y, 0.f);
    float h2 = fmaxf(a[2] + bva.x, 0.f), h3 = fmaxf(a[3] + bva.y, 0.f);
    float h4 = fmaxf(b[0] + bvb.x, 0.f), h5 = fmaxf(b[1] + bvb.y, 0.f);
    float h6 = fmaxf(b[2] + bvb.x, 0.f), h7 = fmaxf(b[3] + bvb.y, 0.f);
    a2hi[0] = pack2bf(h0, h1);
    a2hi[1] = pack2bf(h2, h3);
    a2hi[2] = pack2bf(h4, h5);
    a2hi[3] = pack2bf(h6, h7);
    a2lo[0] = pack2bf(h0 - bfround(h0), h1 - bfround(h1));
    a2lo[1] = pack2bf(h2 - bfround(h2), h3 - bfround(h3));
    a2lo[2] = pack2bf(h4 - bfround(h4), h5 - bfround(h5));
    a2lo[3] = pack2bf(h6 - bfround(h6), h7 - bfround(h7));
}

// ---------------- Kernel B: mechanism MLP (bf16 HMMA, pipelined passthrough) ----------------
// grid (16, 16), 256 thr (8 warps), 2 blocks/SM, 4 tiles of 128 rows per block.
// smem words: Wp 10240 | b1s 128 @10240 | b2s 64 @10368 | w3s 64 @10432
//             pms 16 @10496 | rawv 128 @10512 | Xh 1152 @10640 | Xl 1152 @11792 = 51776 B
__global__ void __launch_bounds__(256, 2) k_mech(
    const float* __restrict__ data,
    const float* __restrict__ bm1,
    const float* __restrict__ bm2,
    const float* __restrict__ Wm3, const float* __restrict__ bm3,
    float* __restrict__ out_pred)
{
    extern __shared__ float sm[];
    const int v = blockIdx.y;
    unsigned* Wp  = (unsigned*)sm;
    float* b1s  = sm + 10240;
    float* b2s  = sm + 10368;
    float* w3s  = sm + 10432;
    float* pms  = sm + 10496;
    float* rawv = sm + 10512;
    unsigned* Xh  = (unsigned*)(sm + 10640);
    unsigned* Xl  = (unsigned*)(sm + 11792);

    int tid = threadIdx.x;
    int w = tid >> 5, lane = tid & 31;
    int lq = lane & 3, lg = lane >> 2;

    {
        const float4* src = (const float4*)(g_wpack + v * 10240);
        float4* dst = (float4*)Wp;
        for (int i = tid; i < 2560; i += 256) dst[i] = src[i];
    }
    if (tid < 128) b1s[tid] = bm1[v * 128 + tid];
    if (tid < 64) { b2s[tid] = bm2[v * 64 + tid]; w3s[tid] = Wm3[v * 64 + tid]; }
    if (tid < 16) pms[tid] = (tid < 15) ? g_pm[v * 15 + tid] : 0.f;
    float hp = g_hp[v];
    float b3 = bm3[v];

    const unsigned* W1s = Wp;
    const unsigned* W2s = Wp + 2048;
    int rA = w * 16 + lg;

    for (int tile = 0; tile < 4; tile++) {
        __syncthreads();
        int row0 = blockIdx.x * 512 + tile * 128;
        for (int idx = tid; idx < 1024; idx += 256) {
            int row = idx >> 3, kp = idx & 7;
            int p0 = 2 * kp, p1 = 2 * kp + 1;
            const float* drow = data + (row0 + row) * 16;
            float v0 = 0.f, v1 = 0.f;
            v0 = drow[p0 + (p0 >= v ? 1 : 0)] * pms[p0];
            if (p1 < 15) v1 = drow[p1 + (p1 >= v ? 1 : 0)] * pms[p1];
            Xh[row * 9 + kp] = pack2bf(v0, v1);
            Xl[row * 9 + kp] = pack2bf(v0 - bfround(v0), v1 - bfround(v1));
        }
        if (tid < 128) rawv[tid] = data[(row0 + tid) * 16 + v];
        __syncthreads();

        unsigned ahi[4], alo[4];
        ahi[0] = Xh[rA * 9 + lq];           ahi[1] = Xh[(rA + 8) * 9 + lq];
        ahi[2] = Xh[rA * 9 + lq + 4];       ahi[3] = Xh[(rA + 8) * 9 + lq + 4];
        alo[0] = Xl[rA * 9 + lq];           alo[1] = Xl[(rA + 8) * 9 + lq];
        alo[2] = Xl[rA * 9 + lq + 4];       alo[3] = Xl[(rA + 8) * 9 + lq + 4];

        float acc2[8][4];
#pragma unroll
        for (int nt = 0; nt < 8; nt++)
#pragma unroll
            for (int i = 0; i < 4; i++) acc2[nt][i] = 0.f;

        // prologue: layer-1 for ks=0
        unsigned c2hi[4], c2lo[4];
        {
            float a1[4] = {0.f, 0.f, 0.f, 0.f}, b1r[4] = {0.f, 0.f, 0.f, 0.f};
            l1_step(W1s, lane, 0, ahi, alo, a1, b1r);
            l1_epi(b1s, lq, 0, a1, b1r, c2hi, c2lo);
        }
#pragma unroll
        for (int ks = 0; ks < 8; ks++) {
            // start layer-1 for ks+1 (independent — interleaves with L2 below)
            float n1a[4] = {0.f, 0.f, 0.f, 0.f}, n1b[4] = {0.f, 0.f, 0.f, 0.f};
            if (ks < 7) l1_step(W1s, lane, ks + 1, ahi, alo, n1a, n1b);
            // layer-2 for ks with current fragments
#pragma unroll
            for (int nt = 0; nt < 8; nt++) {
                const unsigned* bh = W2s + (ks * 256 + nt * 32 + lane) * 2;
                const unsigned* bl = W2s + 4096 + (ks * 256 + nt * 32 + lane) * 2;
                unsigned bhv[2] = { bh[0], bh[1] };
                unsigned blv[2] = { bl[0], bl[1] };
                mma_bf16(acc2[nt], c2hi, bhv);
                mma_bf16(acc2[nt], c2hi, blv);
                mma_bf16(acc2[nt], c2lo, bhv);
            }
            if (ks < 7) l1_epi(b1s, lq, ks + 1, n1a, n1b, c2hi, c2lo);
        }

        // epilogue 2: bias + relu + dot w3, quad-reduce, write
        float sA = 0.f, sB = 0.f;
#pragma unroll
        for (int nt = 0; nt < 8; nt++) {
            float2 bv = *(const float2*)(b2s + nt * 8 + 2 * lq);
            float2 wv = *(const float2*)(w3s + nt * 8 + 2 * lq);
            sA = fmaf(fmaxf(acc2[nt][0] + bv.x, 0.f), wv.x, sA);
            sA = fmaf(fmaxf(acc2[nt][1] + bv.y, 0.f), wv.y, sA);
            sB = fmaf(fmaxf(acc2[nt][2] + bv.x, 0.f), wv.x, sB);
            sB = fmaf(fmaxf(acc2[nt][3] + bv.y, 0.f), wv.y, sB);
        }
        sA += __shfl_xor_sync(0xffffffffu, sA, 1);
        sA += __shfl_xor_sync(0xffffffffu, sA, 2);
        sB += __shfl_xor_sync(0xffffffffu, sB, 1);
        sB += __shfl_xor_sync(0xffffffffu, sB, 2);
        if (lq == 0) {
            float pA = (hp > 0.f) ? (sA + b3) : rawv[rA];
            float pB = (hp > 0.f) ? (sB + b3) : rawv[rA + 8];
            out_pred[(row0 + rA) * 16 + v] = pA;
            out_pred[(row0 + rA + 8) * 16 + v] = pB;
        }
    }
}

// ---------------- Kernel C: pair scorer (4 thr/pair, ILP-2 samples) ----------------
__global__ void __launch_bounds__(960) k_pairs(
    const float* __restrict__ data,
    const float* __restrict__ Wt1, const float* __restrict__ bt1,
    const float* __restrict__ Wt2, const float* __restrict__ bt2)
{
    __shared__ float rows[64 * 17];
    int tid = threadIdx.x;
    int sbase = blockIdx.x * 64;
    for (int t = tid; t < 1024; t += 960) {
        int s = t >> 4, j = t & 15;
        rows[s * 17 + j] = data[(sbase + s) * 16 + j];
    }
    __syncthreads();

    int p = tid >> 2, q = tid & 3;
    int pi = p / 15, r = p - pi * 15;
    int pj = r + (r >= pi ? 1 : 0);
    int co = q * 8;
    float4 wa0 = *(const float4*)(Wt1 + p * 64 + co);
    float4 wa1 = *(const float4*)(Wt1 + p * 64 + co + 4);
    float4 wb0 = *(const float4*)(Wt1 + p * 64 + 32 + co);
    float4 wb1 = *(const float4*)(Wt1 + p * 64 + 32 + co + 4);
    float4 bb0 = *(const float4*)(bt1 + p * 32 + co);
    float4 bb1 = *(const float4*)(bt1 + p * 32 + co + 4);
    float4 w20 = *(const float4*)(Wt2 + p * 32 + co);
    float4 w21 = *(const float4*)(Wt2 + p * 32 + co + 4);
    float b2v = bt2[p];

    float accs = 0.f;
    for (int s = 0; s < 64; s += 2) {
        float aX = rows[s * 17 + pi],       bX = rows[s * 17 + pj];
        float aY = rows[(s+1) * 17 + pi],   bY = rows[(s+1) * 17 + pj];
        float2 xiX = make_float2(aX, aX), xjX = make_float2(bX, bX);
        float2 xiY = make_float2(aY, aY), xjY = make_float2(bY, bY);
        float2 sv0X = make_float2(0.f, 0.f), sv1X = make_float2(0.f, 0.f);
        float2 sv0Y = make_float2(0.f, 0.f), sv1Y = make_float2(0.f, 0.f);
        float2 h;
        h = ffma2(xiX, make_float2(wa0.x, wa0.y), make_float2(bb0.x, bb0.y));
        h = ffma2(xjX, make_float2(wb0.x, wb0.y), h);
        h.x = fmaxf(h.x, 0.f); h.y = fmaxf(h.y, 0.f);
        sv0X = ffma2(h, make_float2(w20.x, w20.y), sv0X);
        h = ffma2(xiY, make_float2(wa0.x, wa0.y), make_float2(bb0.x, bb0.y));
        h = ffma2(xjY, make_float2(wb0.x, wb0.y), h);
        h.x = fmaxf(h.x, 0.f); h.y = fmaxf(h.y, 0.f);
        sv0Y = ffma2(h, make_float2(w20.x, w20.y), sv0Y);

        h = ffma2(xiX, make_float2(wa0.z, wa0.w), make_float2(bb0.z, bb0.w));
        h = ffma2(xjX, make_float2(wb0.z, wb0.w), h);
        h.x = fmaxf(h.x, 0.f); h.y = fmaxf(h.y, 0.f);
        sv1X = ffma2(h, make_float2(w20.z, w20.w), sv1X);
        h = ffma2(xiY, make_float2(wa0.z, wa0.w), make_float2(bb0.z, bb0.w));
        h = ffma2(xjY, make_float2(wb0.z, wb0.w), h);
        h.x = fmaxf(h.x, 0.f); h.y = fmaxf(h.y, 0.f);
        sv1Y = ffma2(h, make_float2(w20.z, w20.w), sv1Y);

        h = ffma2(xiX, make_float2(wa1.x, wa1.y), make_float2(bb1.x, bb1.y));
        h = ffma2(xjX, make_float2(wb1.x, wb1.y), h);
        h.x = fmaxf(h.x, 0.f); h.y = fmaxf(h.y, 0.f);
        sv0X = ffma2(h, make_float2(w21.x, w21.y), sv0X);
        h = ffma2(xiY, make_float2(wa1.x, wa1.y), make_float2(bb1.x, bb1.y));
        h = ffma2(xjY, make_float2(wb1.x, wb1.y), h);
        h.x = fmaxf(h.x, 0.f); h.y = fmaxf(h.y, 0.f);
        sv0Y = ffma2(h, make_float2(w21.x, w21.y), sv0Y);

        h = ffma2(xiX, make_float2(wa1.z, wa1.w), make_float2(bb1.z, bb1.w));
        h = ffma2(xjX, make_float2(wb1.z, wb1.w), h);
        h.x = fmaxf(h.x, 0.f); h.y = fmaxf(h.y, 0.f);
        sv1X = ffma2(h, make_float2(w21.z, w21.w), sv1X);
        h = ffma2(xiY, make_float2(wa1.z, wa1.w), make_float2(bb1.z, bb1.w));
        h = ffma2(xjY, make_float2(wb1.z, wb1.w), h);
        h.x = fmaxf(h.x, 0.f); h.y = fmaxf(h.y, 0.f);
        sv1Y = ffma2(h, make_float2(w21.z, w21.w), sv1Y);

        float svX = (sv0X.x + sv0X.y) + (sv1X.x + sv1X.y);
        float svY = (sv0Y.x + sv0Y.y) + (sv1Y.x + sv1Y.y);
        svX += __shfl_xor_sync(0xffffffffu, svX, 1);
        svY += __shfl_xor_sync(0xffffffffu, svY, 1);
        svX += __shfl_xor_sync(0xffffffffu, svX, 2);
        svY += __shfl_xor_sync(0xffffffffu, svY, 2);
        float sgX = __fdividef(1.f, 1.f + __expf(-(svX + b2v)));
        float sgY = __fdividef(1.f, 1.f + __expf(-(svY + b2v)));
        accs += sgX;
        accs += sgY;
    }
    if (q == 0) g_part[p * 128 + blockIdx.x] = accs;
}

// ---------------- Kernel D: finalize ----------------
__global__ void __launch_bounds__(256) k_fin(float* __restrict__ out_scores) {
    int t = threadIdx.x;
    if (t < 240) {
        const float4* b = (const float4*)(g_part + t * 128);
        float s = 0.f;
#pragma unroll
        for (int i = 0; i < 32; i++) {
            float4 v = b[i];
            s += (v.x + v.y) + (v.z + v.w);
        }
        int pi = t / 15, r = t - pi * 15;
        int pj = r + (r >= pi ? 1 : 0);
        out_scores[pi * 16 + pj] = s * (1.f / 8192.f);
    }
    if (t < 16) out_scores[t * 17] = 0.f;
}

// ---------------- launch ----------------
extern "C" void kernel_launch(void* const* d_in, const int* in_sizes, int n_in,
                              void* d_out, int out_size) {
    const float* data = (const float*)d_in[0];
    const float* Ws1 = (const float*)d_in[1];
    const float* bs1 = (const float*)d_in[2];
    const float* Ws2 = (const float*)d_in[3];
    const float* bs2 = (const float*)d_in[4];
    const float* Ws3 = (const float*)d_in[5];
    const float* bs3 = (const float*)d_in[6];
    const float* Wm1 = (const float*)d_in[7];
    const float* bm1 = (const float*)d_in[8];
    const float* Wm2 = (const float*)d_in[9];
    const float* bm2 = (const float*)d_in[10];
    const float* Wm3 = (const float*)d_in[11];
    const float* bm3 = (const float*)d_in[12];
    const float* Wt1 = (const float*)d_in[13];
    const float* bt1 = (const float*)d_in[14];
    const float* Wt2 = (const float*)d_in[15];
    const float* bt2 = (const float*)d_in[16];

    float* out = (float*)d_out;
    float* out_adj    = out;
    float* out_pred   = out + 256;
    float* out_scores = out + 256 + 131072;

    cudaFuncSetAttribute(k_mech, cudaFuncAttributeMaxDynamicSharedMemorySize, 51776);

    k_prep<<<96, 256>>>(Wm1, Wm2, data);
    k_adj<<<1, 1024>>>(Ws1, bs1, Ws2, bs2, Ws3, bs3, out_adj);
    k_pairs<<<128, 960>>>(data, Wt1, bt1, Wt2, bt2);
    k_mech<<<dim3(16, 16), 256, 51776>>>(data, bm1, bm2, Wm3, bm3, out_pred);
    k_fin<<<1, 256>>>(out_scores);
}

// round 10
// speedup vs baseline: 2.8560x; 1.0320x over previous
#include <cuda_runtime.h>
#include <cuda_bf16.h>
#include <math.h>

#define NV 16

// ---------------- device scratch ----------------
__device__ float g_pm[240];
__device__ float g_hp[16];
__device__ float g_part[240 * 128];
__device__ unsigned g_wpack[16 * 10240];
__device__ float g_gram[32 * 256];     // per-block Gram partials
__device__ float g_colsum[32 * 16];    // per-block column-sum partials

// packed f32x2 FMA (k_pairs)
union F2U { float2 f; unsigned long long u; };
__device__ __forceinline__ float2 ffma2(float2 a, float2 b, float2 c) {
    F2U au, bu, cu, du;
    au.f = a; bu.f = b; cu.f = c;
    asm("fma.rn.f32x2 %0, %1, %2, %3;" : "=l"(du.u) : "l"(au.u), "l"(bu.u), "l"(cu.u));
    return du.f;
}

// bf16 m16n8k16 MMA, fp32 accumulate
__device__ __forceinline__ void mma_bf16(float* d, const unsigned* a, const unsigned* b) {
    asm volatile(
        "mma.sync.aligned.m16n8k16.row.col.f32.bf16.bf16.f32 "
        "{%0,%1,%2,%3}, {%4,%5,%6,%7}, {%8,%9}, {%0,%1,%2,%3};"
        : "+f"(d[0]), "+f"(d[1]), "+f"(d[2]), "+f"(d[3])
        : "r"(a[0]), "r"(a[1]), "r"(a[2]), "r"(a[3]), "r"(b[0]), "r"(b[1]));
}

__device__ __forceinline__ unsigned pack2bf(float a, float b) {
    __nv_bfloat162 h = __floats2bfloat162_rn(a, b);
    return *reinterpret_cast<unsigned*>(&h);
}
__device__ __forceinline__ float bfround(float x) {
    return __bfloat162float(__float2bfloat16_rn(x));
}

// ---------------- Kernel P: weight prepack (blocks 0-63) + avg/Gram (blocks 64-95) ----------------
__global__ void __launch_bounds__(256) k_prep(
    const float* __restrict__ Wm1, const float* __restrict__ Wm2,
    const float* __restrict__ data)
{
    int bid = blockIdx.x, tid = threadIdx.x;
    if (bid < 64) {
        int v = bid >> 2, quarter = bid & 3;
        unsigned* dst = g_wpack + v * 10240;
        for (int idx = quarter * 512 + tid; idx < quarter * 512 + 512; idx += 256) {
            int part = idx >> 10, rem = idx & 1023;
            int nt = rem >> 6, lane = (rem >> 1) & 31, r = rem & 1;
            int lg = lane >> 2, lq = lane & 3;
            int n = nt * 8 + lg, kp = lq + 4 * r;
            int k0 = 2 * kp, k1 = 2 * kp + 1;
            float w0 = (k0 < 15) ? Wm1[v * 1920 + k0 * 128 + n] : 0.f;
            float w1 = (k1 < 15) ? Wm1[v * 1920 + k1 * 128 + n] : 0.f;
            if (part == 0) dst[idx] = pack2bf(w0, w1);
            else dst[idx] = pack2bf(w0 - bfround(w0), w1 - bfround(w1));
        }
        for (int idx = quarter * 2048 + tid; idx < quarter * 2048 + 2048; idx += 256) {
            int part = idx >> 12, rem = idx & 4095;
            int ks = rem >> 9, nt = (rem >> 6) & 7, lane = (rem >> 1) & 31, r = rem & 1;
            int lg = lane >> 2, lq = lane & 3;
            int n = nt * 8 + lg, kp = ks * 8 + lq + 4 * r;
            int k0 = 2 * kp, k1 = 2 * kp + 1;
            float w0 = Wm2[v * 8192 + k0 * 64 + n];
            float w1 = Wm2[v * 8192 + k1 * 64 + n];
            if (part == 0) dst[2048 + idx] = pack2bf(w0, w1);
            else dst[2048 + idx] = pack2bf(w0 - bfround(w0), w1 - bfround(w1));
        }
    } else {
        // avg over batch for 16 seq-rows, then local Gram + colsum partials
        __shared__ float avs[256];     // [16 rows][16 vars]
        int q = bid - 64;
        float s = 0.f;
#pragma unroll
        for (int b = 0; b < 16; b++) s += data[b * 8192 + q * 256 + tid];
        avs[tid] = s * (1.f / 16.f);
        __syncthreads();
        int i = tid >> 4, j = tid & 15;
        float g = 0.f;
#pragma unroll
        for (int r = 0; r < 16; r++) g += avs[r * 16 + i] * avs[r * 16 + j];
        g_gram[q * 256 + tid] = g;
        if (tid < 16) {
            float cs = 0.f;
#pragma unroll
            for (int r = 0; r < 16; r++) cs += avs[r * 16 + tid];
            g_colsum[q * 16 + tid] = cs;
        }
    }
}

// ---------------- Kernel A: corr -> MLP -> adj -> masks ----------------
__global__ void __launch_bounds__(1024) k_adj(
    const float* __restrict__ Ws1, const float* __restrict__ bs1,
    const float* __restrict__ Ws2, const float* __restrict__ bs2,
    const float* __restrict__ Ws3, const float* __restrict__ bs3,
    float* __restrict__ out_adj)
{
    __shared__ float scratch[1024];
    __shared__ float cm[16];
    __shared__ float covs[256];
    __shared__ float corr_s[256];
    __shared__ float h1s[256];
    __shared__ float h2s[128];
    __shared__ float adj_s[256];
    __shared__ float pms[240];

    int tid = threadIdx.x;
    // reduce Gram partials (1024 thr: 256 pairs x 4 chunks of 8)
    {
        int pr = tid & 255, q4 = tid >> 8;
        float s = 0.f;
#pragma unroll
        for (int q = q4 * 8; q < q4 * 8 + 8; q++) s += g_gram[q * 256 + pr];
        scratch[tid] = s;
    }
    if (tid < 16) {
        float s = 0.f;
#pragma unroll
        for (int q = 0; q < 32; q++) s += g_colsum[q * 16 + tid];
        cm[tid] = s * (1.f / 512.f);
    }
    __syncthreads();
    if (tid < 256) {
        float G = scratch[tid] + scratch[256 + tid] + scratch[512 + tid] + scratch[768 + tid];
        int i = tid >> 4, j = tid & 15;
        covs[tid] = G - 512.f * cm[i] * cm[j];
    }
    __syncthreads();
    if (tid < 256) {
        int i = tid >> 4, j = tid & 15;
        float si = sqrtf(fmaxf(covs[i * 16 + i], 0.f));
        float sj = sqrtf(fmaxf(covs[j * 16 + j], 0.f));
        float denom = si * sj;
        float c = denom > 0.f ? covs[tid] / denom : 0.f;
        c = fabsf(c);
        if (i == j) c = 0.f;
        corr_s[tid] = c;
    }
    __syncthreads();

    {
        int o = tid & 255, q = tid >> 8;
        float s = 0.f;
        for (int k = q * 64; k < q * 64 + 64; k++) s = fmaf(corr_s[k], Ws1[k * 256 + o], s);
        scratch[q * 256 + o] = s;
    }
    __syncthreads();
    if (tid < 256)
        h1s[tid] = fmaxf(scratch[tid] + scratch[256 + tid] + scratch[512 + tid] + scratch[768 + tid] + bs1[tid], 0.f);
    __syncthreads();

    {
        int o = tid & 127, q = tid >> 7;
        float s = 0.f;
        for (int k = q * 32; k < q * 32 + 32; k++) s = fmaf(h1s[k], Ws2[k * 128 + o], s);
        scratch[q * 128 + o] = s;
    }
    __syncthreads();
    if (tid < 128) {
        float s = bs2[tid];
        for (int q = 0; q < 8; q++) s += scratch[q * 128 + tid];
        h2s[tid] = fmaxf(s, 0.f);
    }
    __syncthreads();

    {
        int o = tid & 255, q = tid >> 8;
        float s = 0.f;
        for (int k = q * 32; k < q * 32 + 32; k++) s = fmaf(h2s[k], Ws3[k * 256 + o], s);
        scratch[q * 256 + o] = s;
    }
    __syncthreads();
    if (tid < 256) {
        float logit = scratch[tid] + scratch[256 + tid] + scratch[512 + tid] + scratch[768 + tid] + bs3[tid];
        float a = 1.f / (1.f + expf(-logit));
        int i = tid >> 4, j = tid & 15;
        float val = (j > i) ? a : 0.f;
        adj_s[tid] = val;
        out_adj[tid] = val;
    }
    __syncthreads();
    if (tid < 240) {
        int v = tid / 15, p = tid - v * 15;
        int g = p + (p >= v ? 1 : 0);
        float m = (adj_s[g * 16 + v] > 0.5f) ? 1.f : 0.f;
        pms[tid] = m;
        g_pm[tid] = m;
    }
    __syncthreads();
    if (tid < 16) {
        float s = 0.f;
        for (int p = 0; p < 15; p++) s += pms[tid * 15 + p];
        g_hp[tid] = (s > 0.f) ? 1.f : 0.f;
    }
}

// ---- k_mech helpers ----
__device__ __forceinline__ void l1_step(const unsigned* W1s, int lane, int ks,
    const unsigned* ahi, const unsigned* alo, float* a, float* b)
{
    int nt0 = 2 * ks, nt1 = nt0 + 1;
    const unsigned* bh0 = W1s + (nt0 * 32 + lane) * 2;
    const unsigned* bl0 = W1s + 1024 + (nt0 * 32 + lane) * 2;
    const unsigned* bh1 = W1s + (nt1 * 32 + lane) * 2;
    const unsigned* bl1 = W1s + 1024 + (nt1 * 32 + lane) * 2;
    unsigned bh0v[2] = { bh0[0], bh0[1] }, bl0v[2] = { bl0[0], bl0[1] };
    unsigned bh1v[2] = { bh1[0], bh1[1] }, bl1v[2] = { bl1[0], bl1[1] };
    mma_bf16(a, ahi, bh0v);
    mma_bf16(b, ahi, bh1v);
    mma_bf16(a, ahi, bl0v);
    mma_bf16(b, ahi, bl1v);
    mma_bf16(a, alo, bh0v);
    mma_bf16(b, alo, bh1v);
}

__device__ __forceinline__ void l1_epi(const float* b1s, int lq, int ks,
    const float* a, const float* b, unsigned* a2hi, unsigned* a2lo)
{
    float2 bva = *(const float2*)(b1s + (2 * ks) * 8 + 2 * lq);
    float2 bvb = *(const float2*)(b1s + (2 * ks + 1) * 8 + 2 * lq);
    float h0 = fmaxf(a[0] + bva.x, 0.f), h1 = fmaxf(a[1] + bva.y, 0.f);
    float h2 = fmaxf(a[2] + bva.x, 0.f), h3 = fmaxf(a[3] + bva.y, 0.f);
    float h4 = fmaxf(b[0] + bvb.x, 0.f), h5 = fmaxf(b[1] + bvb.y, 0.f);
    float h6 = fmaxf(b[2] + bvb.x, 0.f), h7 = fmaxf(b[3] + bvb.y, 0.f);
    a2hi[0] = pack2bf(h0, h1);
    a2hi[1] = pack2bf(h2, h3);
    a2hi[2] = pack2bf(h4, h5);
    a2hi[3] = pack2bf(h6, h7);
    a2lo[0] = pack2bf(h0 - bfround(h0), h1 - bfround(h1));
    a2lo[1] = pack2bf(h2 - bfround(h2), h3 - bfround(h3));
    a2lo[2] = pack2bf(h4 - bfround(h4), h5 - bfround(h5));
    a2lo[3] = pack2bf(h6 - bfround(h6), h7 - bfround(h7));
}

// ---------------- Kernel B: mechanism MLP (bf16 HMMA, pipelined passthrough) ----------------
// grid (16, 16), 256 thr (8 warps), 2 blocks/SM, 4 tiles of 128 rows per block.
// smem words: Wp 10240 | b1s 128 @10240 | b2s 64 @10368 | w3s 64 @10432
//             pms 16 @10496 | rawv 128 @10512 | Xh 1152 @10640 | Xl 1152 @11792 = 51776 B
__global__ void __launch_bounds__(256, 2) k_mech(
    const float* __restrict__ data,
    const float* __restrict__ bm1,
    const float* __restrict__ bm2,
    const float* __restrict__ Wm3, const float* __restrict__ bm3,
    float* __restrict__ out_pred)
{
    extern __shared__ float sm[];
    const int v = blockIdx.y;
    unsigned* Wp  = (unsigned*)sm;
    float* b1s  = sm + 10240;
    float* b2s  = sm + 10368;
    float* w3s  = sm + 10432;
    float* pms  = sm + 10496;
    float* rawv = sm + 10512;
    unsigned* Xh  = (unsigned*)(sm + 10640);
    unsigned* Xl  = (unsigned*)(sm + 11792);

    int tid = threadIdx.x;
    int w = tid >> 5, lane = tid & 31;
    int lq = lane & 3, lg = lane >> 2;

    {
        const float4* src = (const float4*)(g_wpack + v * 10240);
        float4* dst = (float4*)Wp;
        for (int i = tid; i < 2560; i += 256) dst[i] = src[i];
    }
    if (tid < 128) b1s[tid] = bm1[v * 128 + tid];
    if (tid < 64) { b2s[tid] = bm2[v * 64 + tid]; w3s[tid] = Wm3[v * 64 + tid]; }
    if (tid < 16) pms[tid] = (tid < 15) ? g_pm[v * 15 + tid] : 0.f;
    float hp = g_hp[v];
    float b3 = bm3[v];

    const unsigned* W1s = Wp;
    const unsigned* W2s = Wp + 2048;
    int rA = w * 16 + lg;

    for (int tile = 0; tile < 4; tile++) {
        __syncthreads();
        int row0 = blockIdx.x * 512 + tile * 128;
        for (int idx = tid; idx < 1024; idx += 256) {
            int row = idx >> 3, kp = idx & 7;
            int p0 = 2 * kp, p1 = 2 * kp + 1;
            const float* drow = data + (row0 + row) * 16;
            float v0 = 0.f, v1 = 0.f;
            v0 = drow[p0 + (p0 >= v ? 1 : 0)] * pms[p0];
            if (p1 < 15) v1 = drow[p1 + (p1 >= v ? 1 : 0)] * pms[p1];
            Xh[row * 9 + kp] = pack2bf(v0, v1);
            Xl[row * 9 + kp] = pack2bf(v0 - bfround(v0), v1 - bfround(v1));
        }
        if (tid < 128) rawv[tid] = data[(row0 + tid) * 16 + v];
        __syncthreads();

        unsigned ahi[4], alo[4];
        ahi[0] = Xh[rA * 9 + lq];           ahi[1] = Xh[(rA + 8) * 9 + lq];
        ahi[2] = Xh[rA * 9 + lq + 4];       ahi[3] = Xh[(rA + 8) * 9 + lq + 4];
        alo[0] = Xl[rA * 9 + lq];           alo[1] = Xl[(rA + 8) * 9 + lq];
        alo[2] = Xl[rA * 9 + lq + 4];       alo[3] = Xl[(rA + 8) * 9 + lq + 4];

        float acc2[8][4];
#pragma unroll
        for (int nt = 0; nt < 8; nt++)
#pragma unroll
            for (int i = 0; i < 4; i++) acc2[nt][i] = 0.f;

        // prologue: layer-1 for ks=0
        unsigned c2hi[4], c2lo[4];
        {
            float a1[4] = {0.f, 0.f, 0.f, 0.f}, b1r[4] = {0.f, 0.f, 0.f, 0.f};
            l1_step(W1s, lane, 0, ahi, alo, a1, b1r);
            l1_epi(b1s, lq, 0, a1, b1r, c2hi, c2lo);
        }
#pragma unroll
        for (int ks = 0; ks < 8; ks++) {
            // start layer-1 for ks+1 (independent — interleaves with L2 below)
            float n1a[4] = {0.f, 0.f, 0.f, 0.f}, n1b[4] = {0.f, 0.f, 0.f, 0.f};
            if (ks < 7) l1_step(W1s, lane, ks + 1, ahi, alo, n1a, n1b);
            // layer-2 for ks with current fragments
#pragma unroll
            for (int nt = 0; nt < 8; nt++) {
                const unsigned* bh = W2s + (ks * 256 + nt * 32 + lane) * 2;
                const unsigned* bl = W2s + 4096 + (ks * 256 + nt * 32 + lane) * 2;
                unsigned bhv[2] = { bh[0], bh[1] };
                unsigned blv[2] = { bl[0], bl[1] };
                mma_bf16(acc2[nt], c2hi, bhv);
                mma_bf16(acc2[nt], c2hi, blv);
                mma_bf16(acc2[nt], c2lo, bhv);
            }
            if (ks < 7) l1_epi(b1s, lq, ks + 1, n1a, n1b, c2hi, c2lo);
        }

        // epilogue 2: bias + relu + dot w3, quad-reduce, write
        float sA = 0.f, sB = 0.f;
#pragma unroll
        for (int nt = 0; nt < 8; nt++) {
            float2 bv = *(const float2*)(b2s + nt * 8 + 2 * lq);
            float2 wv = *(const float2*)(w3s + nt * 8 + 2 * lq);
            sA = fmaf(fmaxf(acc2[nt][0] + bv.x, 0.f), wv.x, sA);
            sA = fmaf(fmaxf(acc2[nt][1] + bv.y, 0.f), wv.y, sA);
            sB = fmaf(fmaxf(acc2[nt][2] + bv.x, 0.f), wv.x, sB);
            sB = fmaf(fmaxf(acc2[nt][3] + bv.y, 0.f), wv.y, sB);
        }
        sA += __shfl_xor_sync(0xffffffffu, sA, 1);
        sA += __shfl_xor_sync(0xffffffffu, sA, 2);
        sB += __shfl_xor_sync(0xffffffffu, sB, 1);
        sB += __shfl_xor_sync(0xffffffffu, sB, 2);
        if (lq == 0) {
            float pA = (hp > 0.f) ? (sA + b3) : rawv[rA];
            float pB = (hp > 0.f) ? (sB + b3) : rawv[rA + 8];
            out_pred[(row0 + rA) * 16 + v] = pA;
            out_pred[(row0 + rA + 8) * 16 + v] = pB;
        }
    }
}

// ---------------- Kernel C: pair scorer (4 thr/pair, ILP-2 samples) ----------------
__global__ void __launch_bounds__(960) k_pairs(
    const float* __restrict__ data,
    const float* __restrict__ Wt1, const float* __restrict__ bt1,
    const float* __restrict__ Wt2, const float* __restrict__ bt2)
{
    __shared__ float rows[64 * 17];
    int tid = threadIdx.x;
    int sbase = blockIdx.x * 64;
    for (int t = tid; t < 1024; t += 960) {
        int s = t >> 4, j = t & 15;
        rows[s * 17 + j] = data[(sbase + s) * 16 + j];
    }
    __syncthreads();

    int p = tid >> 2, q = tid & 3;
    int pi = p / 15, r = p - pi * 15;
    int pj = r + (r >= pi ? 1 : 0);
    int co = q * 8;
    float4 wa0 = *(const float4*)(Wt1 + p * 64 + co);
    float4 wa1 = *(const float4*)(Wt1 + p * 64 + co + 4);
    float4 wb0 = *(const float4*)(Wt1 + p * 64 + 32 + co);
    float4 wb1 = *(const float4*)(Wt1 + p * 64 + 32 + co + 4);
    float4 bb0 = *(const float4*)(bt1 + p * 32 + co);
    float4 bb1 = *(const float4*)(bt1 + p * 32 + co + 4);
    float4 w20 = *(const float4*)(Wt2 + p * 32 + co);
    float4 w21 = *(const float4*)(Wt2 + p * 32 + co + 4);
    float b2v = bt2[p];

    float accs = 0.f;
    for (int s = 0; s < 64; s += 2) {
        float aX = rows[s * 17 + pi],       bX = rows[s * 17 + pj];
        float aY = rows[(s+1) * 17 + pi],   bY = rows[(s+1) * 17 + pj];
        float2 xiX = make_float2(aX, aX), xjX = make_float2(bX, bX);
        float2 xiY = make_float2(aY, aY), xjY = make_float2(bY, bY);
        float2 sv0X = make_float2(0.f, 0.f), sv1X = make_float2(0.f, 0.f);
        float2 sv0Y = make_float2(0.f, 0.f), sv1Y = make_float2(0.f, 0.f);
        float2 h;
        h = ffma2(xiX, make_float2(wa0.x, wa0.y), make_float2(bb0.x, bb0.y));
        h = ffma2(xjX, make_float2(wb0.x, wb0.y), h);
        h.x = fmaxf(h.x, 0.f); h.y = fmaxf(h.y, 0.f);
        sv0X = ffma2(h, make_float2(w20.x, w20.y), sv0X);
        h = ffma2(xiY, make_float2(wa0.x, wa0.y), make_float2(bb0.x, bb0.y));
        h = ffma2(xjY, make_float2(wb0.x, wb0.y), h);
        h.x = fmaxf(h.x, 0.f); h.y = fmaxf(h.y, 0.f);
        sv0Y = ffma2(h, make_float2(w20.x, w20.y), sv0Y);

        h = ffma2(xiX, make_float2(wa0.z, wa0.w), make_float2(bb0.z, bb0.w));
        h = ffma2(xjX, make_float2(wb0.z, wb0.w), h);
        h.x = fmaxf(h.x, 0.f); h.y = fmaxf(h.y, 0.f);
        sv1X = ffma2(h, make_float2(w20.z, w20.w), sv1X);
        h = ffma2(xiY, make_float2(wa0.z, wa0.w), make_float2(bb0.z, bb0.w));
        h = ffma2(xjY, make_float2(wb0.z, wb0.w), h);
        h.x = fmaxf(h.x, 0.f); h.y = fmaxf(h.y, 0.f);
        sv1Y = ffma2(h, make_float2(w20.z, w20.w), sv1Y);

        h = ffma2(xiX, make_float2(wa1.x, wa1.y), make_float2(bb1.x, bb1.y));
        h = ffma2(xjX, make_float2(wb1.x, wb1.y), h);
        h.x = fmaxf(h.x, 0.f); h.y = fmaxf(h.y, 0.f);
        sv0X = ffma2(h, make_float2(w21.x, w21.y), sv0X);
        h = ffma2(xiY, make_float2(wa1.x, wa1.y), make_float2(bb1.x, bb1.y));
        h = ffma2(xjY, make_float2(wb1.x, wb1.y), h);
        h.x = fmaxf(h.x, 0.f); h.y = fmaxf(h.y, 0.f);
        sv0Y = ffma2(h, make_float2(w21.x, w21.y), sv0Y);

        h = ffma2(xiX, make_float2(wa1.z, wa1.w), make_float2(bb1.z, bb1.w));
        h = ffma2(xjX, make_float2(wb1.z, wb1.w), h);
        h.x = fmaxf(h.x, 0.f); h.y = fmaxf(h.y, 0.f);
        sv1X = ffma2(h, make_float2(w21.z, w21.w), sv1X);
        h = ffma2(xiY, make_float2(wa1.z, wa1.w), make_float2(bb1.z, bb1.w));
        h = ffma2(xjY, make_float2(wb1.z, wb1.w), h);
        h.x = fmaxf(h.x, 0.f); h.y = fmaxf(h.y, 0.f);
        sv1Y = ffma2(h, make_float2(w21.z, w21.w), sv1Y);

        float svX = (sv0X.x + sv0X.y) + (sv1X.x + sv1X.y);
        float svY = (sv0Y.x + sv0Y.y) + (sv1Y.x + sv1Y.y);
        svX += __shfl_xor_sync(0xffffffffu, svX, 1);
        svY += __shfl_xor_sync(0xffffffffu, svY, 1);
        svX += __shfl_xor_sync(0xffffffffu, svX, 2);
        svY += __shfl_xor_sync(0xffffffffu, svY, 2);
        float sgX = __fdividef(1.f, 1.f + __expf(-(svX + b2v)));
        float sgY = __fdividef(1.f, 1.f + __expf(-(svY + b2v)));
        accs += sgX;
        accs += sgY;
    }
    if (q == 0) g_part[p * 128 + blockIdx.x] = accs;
}

// ---------------- Kernel D: finalize ----------------
__global__ void __launch_bounds__(256) k_fin(float* __restrict__ out_scores) {
    int t = threadIdx.x;
    if (t < 240) {
        const float4* b = (const float4*)(g_part + t * 128);
        float s = 0.f;
#pragma unroll
        for (int i = 0; i < 32; i++) {
            float4 v = b[i];
            s += (v.x + v.y) + (v.z + v.w);
        }
        int pi = t / 15, r = t - pi * 15;
        int pj = r + (r >= pi ? 1 : 0);
        out_scores[pi * 16 + pj] = s * (1.f / 8192.f);
    }
    if (t < 16) out_scores[t * 17] = 0.f;
}

// ---------------- launch ----------------
extern "C" void kernel_launch(void* const* d_in, const int* in_sizes, int n_in,
                              void* d_out, int out_size) {
    const float* data = (const float*)d_in[0];
    const float* Ws1 = (const float*)d_in[1];
    const float* bs1 = (const float*)d_in[2];
    const float* Ws2 = (const float*)d_in[3];
    const float* bs2 = (const float*)d_in[4];
    const float* Ws3 = (const float*)d_in[5];
    const float* bs3 = (const float*)d_in[6];
    const float* Wm1 = (const float*)d_in[7];
    const float* bm1 = (const float*)d_in[8];
    const float* Wm2 = (const float*)d_in[9];
    const float* bm2 = (const float*)d_in[10];
    const float* Wm3 = (const float*)d_in[11];
    const float* bm3 = (const float*)d_in[12];
    const float* Wt1 = (const float*)d_in[13];
    const float* bt1 = (const float*)d_in[14];
    const float* Wt2 = (const float*)d_in[15];
    const float* bt2 = (const float*)d_in[16];

    float* out = (float*)d_out;
    float* out_adj    = out;
    float* out_pred   = out + 256;
    float* out_scores = out + 256 + 131072;

    cudaFuncSetAttribute(k_mech, cudaFuncAttributeMaxDynamicSharedMemorySize, 51776);

    k_prep<<<96, 256>>>(Wm1, Wm2, data);
    k_adj<<<1, 1024>>>(Ws1, bs1, Ws2, bs2, Ws3, bs3, out_adj);
    k_pairs<<<128, 960>>>(data, Wt1, bt1, Wt2, bt2);
    k_mech<<<dim3(16, 16), 256, 51776>>>(data, bm1, bm2, Wm3, bm3, out_pred);
    k_fin<<<1, 256>>>(out_scores);
}

// round 11
// speedup vs baseline: 3.5000x; 1.2255x over previous
#include <cuda_runtime.h>
#include <cuda_fp16.h>
#include <math.h>

#define NV 16

// ---------------- device scratch ----------------
__device__ float g_pm[240];
__device__ float g_hp[16];
__device__ float g_part[240 * 128];
__device__ unsigned g_wpack[16 * 5120];    // per-v fp16 fragments: W1 1024 + W2 4096
__device__ float g_gram[32 * 256];
__device__ float g_colsum[32 * 16];

// packed f32x2 FMA (pairs path)
union F2U { float2 f; unsigned long long u; };
__device__ __forceinline__ float2 ffma2(float2 a, float2 b, float2 c) {
    F2U au, bu, cu, du;
    au.f = a; bu.f = b; cu.f = c;
    asm("fma.rn.f32x2 %0, %1, %2, %3;" : "=l"(du.u) : "l"(au.u), "l"(bu.u), "l"(cu.u));
    return du.f;
}

// fp16 m16n8k16 MMA, fp32 accumulate
__device__ __forceinline__ void mma_f16(float* d, const unsigned* a, const unsigned* b) {
    asm volatile(
        "mma.sync.aligned.m16n8k16.row.col.f32.f16.f16.f32 "
        "{%0,%1,%2,%3}, {%4,%5,%6,%7}, {%8,%9}, {%0,%1,%2,%3};"
        : "+f"(d[0]), "+f"(d[1]), "+f"(d[2]), "+f"(d[3])
        : "r"(a[0]), "r"(a[1]), "r"(a[2]), "r"(a[3]), "r"(b[0]), "r"(b[1]));
}

__device__ __forceinline__ unsigned pack2h(float a, float b) {
    __half2 h = __floats2half2_rn(a, b);
    return *reinterpret_cast<unsigned*>(&h);
}
__device__ __forceinline__ float hround(float x) {
    return __half2float(__float2half_rn(x));
}

// ---------------- Kernel P: weight prepack (blocks 0-63) + avg/Gram (blocks 64-95) ----------------
__global__ void __launch_bounds__(256) k_prep(
    const float* __restrict__ Wm1, const float* __restrict__ Wm2,
    const float* __restrict__ data)
{
    int bid = blockIdx.x, tid = threadIdx.x;
    if (bid < 64) {
        int v = bid >> 2, quarter = bid & 3;
        unsigned* dst = g_wpack + v * 5120;
        // W1: 1024 u32 per v (single fp16 part), 256 per quarter
        {
            int idx = quarter * 256 + tid;
            int nt = idx >> 6, lane = (idx >> 1) & 31, r = idx & 1;
            int lg = lane >> 2, lq = lane & 3;
            int n = nt * 8 + lg, kp = lq + 4 * r;
            int k0 = 2 * kp, k1 = 2 * kp + 1;
            float w0 = (k0 < 15) ? Wm1[v * 1920 + k0 * 128 + n] : 0.f;
            float w1 = (k1 < 15) ? Wm1[v * 1920 + k1 * 128 + n] : 0.f;
            dst[idx] = pack2h(w0, w1);
        }
        // W2: 4096 u32 per v (single fp16 part), 1024 per quarter
        for (int idx = quarter * 1024 + tid; idx < quarter * 1024 + 1024; idx += 256) {
            int ks = idx >> 9, nt = (idx >> 6) & 7, lane = (idx >> 1) & 31, r = idx & 1;
            int lg = lane >> 2, lq = lane & 3;
            int n = nt * 8 + lg, kp = ks * 8 + lq + 4 * r;
            int k0 = 2 * kp, k1 = 2 * kp + 1;
            float w0 = Wm2[v * 8192 + k0 * 64 + n];
            float w1 = Wm2[v * 8192 + k1 * 64 + n];
            dst[1024 + idx] = pack2h(w0, w1);
        }
    } else {
        __shared__ float avs[256];
        int q = bid - 64;
        float s = 0.f;
#pragma unroll
        for (int b = 0; b < 16; b++) s += data[b * 8192 + q * 256 + tid];
        avs[tid] = s * (1.f / 16.f);
        __syncthreads();
        int i = tid >> 4, j = tid & 15;
        float g = 0.f;
#pragma unroll
        for (int r = 0; r < 16; r++) g += avs[r * 16 + i] * avs[r * 16 + j];
        g_gram[q * 256 + tid] = g;
        if (tid < 16) {
            float cs = 0.f;
#pragma unroll
            for (int r = 0; r < 16; r++) cs += avs[r * 16 + tid];
            g_colsum[q * 16 + tid] = cs;
        }
    }
}

// ---------------- Kernel A: corr -> MLP -> adj -> masks ----------------
__global__ void __launch_bounds__(1024) k_adj(
    const float* __restrict__ Ws1, const float* __restrict__ bs1,
    const float* __restrict__ Ws2, const float* __restrict__ bs2,
    const float* __restrict__ Ws3, const float* __restrict__ bs3,
    float* __restrict__ out_adj)
{
    __shared__ float scratch[1024];
    __shared__ float cm[16];
    __shared__ float covs[256];
    __shared__ float corr_s[256];
    __shared__ float h1s[256];
    __shared__ float h2s[128];
    __shared__ float adj_s[256];
    __shared__ float pms[240];

    int tid = threadIdx.x;
    {
        int pr = tid & 255, q4 = tid >> 8;
        float s = 0.f;
#pragma unroll
        for (int q = q4 * 8; q < q4 * 8 + 8; q++) s += g_gram[q * 256 + pr];
        scratch[tid] = s;
    }
    if (tid < 16) {
        float s = 0.f;
#pragma unroll
        for (int q = 0; q < 32; q++) s += g_colsum[q * 16 + tid];
        cm[tid] = s * (1.f / 512.f);
    }
    __syncthreads();
    if (tid < 256) {
        float G = scratch[tid] + scratch[256 + tid] + scratch[512 + tid] + scratch[768 + tid];
        int i = tid >> 4, j = tid & 15;
        covs[tid] = G - 512.f * cm[i] * cm[j];
    }
    __syncthreads();
    if (tid < 256) {
        int i = tid >> 4, j = tid & 15;
        float si = sqrtf(fmaxf(covs[i * 16 + i], 0.f));
        float sj = sqrtf(fmaxf(covs[j * 16 + j], 0.f));
        float denom = si * sj;
        float c = denom > 0.f ? covs[tid] / denom : 0.f;
        c = fabsf(c);
        if (i == j) c = 0.f;
        corr_s[tid] = c;
    }
    __syncthreads();

    {
        int o = tid & 255, q = tid >> 8;
        float s = 0.f;
        for (int k = q * 64; k < q * 64 + 64; k++) s = fmaf(corr_s[k], Ws1[k * 256 + o], s);
        scratch[q * 256 + o] = s;
    }
    __syncthreads();
    if (tid < 256)
        h1s[tid] = fmaxf(scratch[tid] + scratch[256 + tid] + scratch[512 + tid] + scratch[768 + tid] + bs1[tid], 0.f);
    __syncthreads();

    {
        int o = tid & 127, q = tid >> 7;
        float s = 0.f;
        for (int k = q * 32; k < q * 32 + 32; k++) s = fmaf(h1s[k], Ws2[k * 128 + o], s);
        scratch[q * 128 + o] = s;
    }
    __syncthreads();
    if (tid < 128) {
        float s = bs2[tid];
        for (int q = 0; q < 8; q++) s += scratch[q * 128 + tid];
        h2s[tid] = fmaxf(s, 0.f);
    }
    __syncthreads();

    {
        int o = tid & 255, q = tid >> 8;
        float s = 0.f;
        for (int k = q * 32; k < q * 32 + 32; k++) s = fmaf(h2s[k], Ws3[k * 256 + o], s);
        scratch[q * 256 + o] = s;
    }
    __syncthreads();
    if (tid < 256) {
        float logit = scratch[tid] + scratch[256 + tid] + scratch[512 + tid] + scratch[768 + tid] + bs3[tid];
        float a = 1.f / (1.f + expf(-logit));
        int i = tid >> 4, j = tid & 15;
        float val = (j > i) ? a : 0.f;
        adj_s[tid] = val;
        out_adj[tid] = val;
    }
    __syncthreads();
    if (tid < 240) {
        int v = tid / 15, p = tid - v * 15;
        int g = p + (p >= v ? 1 : 0);
        float m = (adj_s[g * 16 + v] > 0.5f) ? 1.f : 0.f;
        pms[tid] = m;
        g_pm[tid] = m;
    }
    __syncthreads();
    if (tid < 16) {
        float s = 0.f;
        for (int p = 0; p < 15; p++) s += pms[tid * 15 + p];
        g_hp[tid] = (s > 0.f) ? 1.f : 0.f;
    }
}

// ---- mech helpers (fp16, 2-term A-split) ----
__device__ __forceinline__ void l1_step(const unsigned* W1s, int lane, int ks,
    const unsigned* ahi, const unsigned* alo, float* a, float* b)
{
    int nt0 = 2 * ks, nt1 = nt0 + 1;
    const unsigned* b0p = W1s + (nt0 * 32 + lane) * 2;
    const unsigned* b1p = W1s + (nt1 * 32 + lane) * 2;
    unsigned b0v[2] = { b0p[0], b0p[1] }, b1v[2] = { b1p[0], b1p[1] };
    mma_f16(a, ahi, b0v);
    mma_f16(b, ahi, b1v);
    mma_f16(a, alo, b0v);
    mma_f16(b, alo, b1v);
}

__device__ __forceinline__ void l1_epi(const float* b1s, int lq, int ks,
    const float* a, const float* b, unsigned* a2hi, unsigned* a2lo)
{
    float2 bva = *(const float2*)(b1s + (2 * ks) * 8 + 2 * lq);
    float2 bvb = *(const float2*)(b1s + (2 * ks + 1) * 8 + 2 * lq);
    float h0 = fmaxf(a[0] + bva.x, 0.f), h1 = fmaxf(a[1] + bva.y, 0.f);
    float h2 = fmaxf(a[2] + bva.x, 0.f), h3 = fmaxf(a[3] + bva.y, 0.f);
    float h4 = fmaxf(b[0] + bvb.x, 0.f), h5 = fmaxf(b[1] + bvb.y, 0.f);
    float h6 = fmaxf(b[2] + bvb.x, 0.f), h7 = fmaxf(b[3] + bvb.y, 0.f);
    a2hi[0] = pack2h(h0, h1);
    a2hi[1] = pack2h(h2, h3);
    a2hi[2] = pack2h(h4, h5);
    a2hi[3] = pack2h(h6, h7);
    a2lo[0] = pack2h(h0 - hround(h0), h1 - hround(h1));
    a2lo[1] = pack2h(h2 - hround(h2), h3 - hround(h3));
    a2lo[2] = pack2h(h4 - hround(h4), h5 - hround(h5));
    a2lo[3] = pack2h(h6 - hround(h6), h7 - hround(h7));
}

// ---------------- Kernel M: FUSED mech (blocks 0-255) + pairs (blocks 256-767) ----------------
// mech smem (floats): Wp 5120 @0 | b1s 128 @5120 | b2s 64 @5248 | w3s 64 @5312
//   pms 16 @5376 | rawv 128 @5392 | Xh 1152 @5520 | Xl 1152 @6672 => 7824 w = 31296 B
// pairs smem: rows[64*17] = 1088 floats (overlaps Wp region)
__global__ void __launch_bounds__(256, 2) k_main(
    const float* __restrict__ data,
    const float* __restrict__ bm1, const float* __restrict__ bm2,
    const float* __restrict__ Wm3, const float* __restrict__ bm3,
    const float* __restrict__ Wt1, const float* __restrict__ bt1,
    const float* __restrict__ Wt2, const float* __restrict__ bt2,
    float* __restrict__ out_pred)
{
    extern __shared__ float sm[];
    int tid = threadIdx.x;

    if (blockIdx.x < 256) {
        // ================= MECH =================
        const int bx = blockIdx.x & 15;
        const int v = blockIdx.x >> 4;
        unsigned* Wp  = (unsigned*)sm;
        float* b1s  = sm + 5120;
        float* b2s  = sm + 5248;
        float* w3s  = sm + 5312;
        float* pms  = sm + 5376;
        float* rawv = sm + 5392;
        unsigned* Xh  = (unsigned*)(sm + 5520);
        unsigned* Xl  = (unsigned*)(sm + 6672);

        int w = tid >> 5, lane = tid & 31;
        int lq = lane & 3, lg = lane >> 2;

        {
            const float4* src = (const float4*)(g_wpack + v * 5120);
            float4* dst = (float4*)Wp;
            for (int i = tid; i < 1280; i += 256) dst[i] = src[i];
        }
        if (tid < 128) b1s[tid] = bm1[v * 128 + tid];
        if (tid < 64) { b2s[tid] = bm2[v * 64 + tid]; w3s[tid] = Wm3[v * 64 + tid]; }
        if (tid < 16) pms[tid] = (tid < 15) ? g_pm[v * 15 + tid] : 0.f;
        float hp = g_hp[v];
        float b3 = bm3[v];

        const unsigned* W1s = Wp;
        const unsigned* W2s = Wp + 1024;
        int rA = w * 16 + lg;

        for (int tile = 0; tile < 4; tile++) {
            __syncthreads();
            int row0 = bx * 512 + tile * 128;
            for (int idx = tid; idx < 1024; idx += 256) {
                int row = idx >> 3, kp = idx & 7;
                int p0 = 2 * kp, p1 = 2 * kp + 1;
                const float* drow = data + (row0 + row) * 16;
                float v0 = 0.f, v1 = 0.f;
                v0 = drow[p0 + (p0 >= v ? 1 : 0)] * pms[p0];
                if (p1 < 15) v1 = drow[p1 + (p1 >= v ? 1 : 0)] * pms[p1];
                Xh[row * 9 + kp] = pack2h(v0, v1);
                Xl[row * 9 + kp] = pack2h(v0 - hround(v0), v1 - hround(v1));
            }
            if (tid < 128) rawv[tid] = data[(row0 + tid) * 16 + v];
            __syncthreads();

            unsigned ahi[4], alo[4];
            ahi[0] = Xh[rA * 9 + lq];           ahi[1] = Xh[(rA + 8) * 9 + lq];
            ahi[2] = Xh[rA * 9 + lq + 4];       ahi[3] = Xh[(rA + 8) * 9 + lq + 4];
            alo[0] = Xl[rA * 9 + lq];           alo[1] = Xl[(rA + 8) * 9 + lq];
            alo[2] = Xl[rA * 9 + lq + 4];       alo[3] = Xl[(rA + 8) * 9 + lq + 4];

            float acc2[8][4];
#pragma unroll
            for (int nt = 0; nt < 8; nt++)
#pragma unroll
                for (int i = 0; i < 4; i++) acc2[nt][i] = 0.f;

            unsigned c2hi[4], c2lo[4];
            {
                float a1[4] = {0.f, 0.f, 0.f, 0.f}, b1r[4] = {0.f, 0.f, 0.f, 0.f};
                l1_step(W1s, lane, 0, ahi, alo, a1, b1r);
                l1_epi(b1s, lq, 0, a1, b1r, c2hi, c2lo);
            }
#pragma unroll
            for (int ks = 0; ks < 8; ks++) {
                float n1a[4] = {0.f, 0.f, 0.f, 0.f}, n1b[4] = {0.f, 0.f, 0.f, 0.f};
                if (ks < 7) l1_step(W1s, lane, ks + 1, ahi, alo, n1a, n1b);
#pragma unroll
                for (int nt = 0; nt < 8; nt++) {
                    const unsigned* bp = W2s + (ks * 256 + nt * 32 + lane) * 2;
                    unsigned bv[2] = { bp[0], bp[1] };
                    mma_f16(acc2[nt], c2hi, bv);
                    mma_f16(acc2[nt], c2lo, bv);
                }
                if (ks < 7) l1_epi(b1s, lq, ks + 1, n1a, n1b, c2hi, c2lo);
            }

            float sA = 0.f, sB = 0.f;
#pragma unroll
            for (int nt = 0; nt < 8; nt++) {
                float2 bv = *(const float2*)(b2s + nt * 8 + 2 * lq);
                float2 wv = *(const float2*)(w3s + nt * 8 + 2 * lq);
                sA = fmaf(fmaxf(acc2[nt][0] + bv.x, 0.f), wv.x, sA);
                sA = fmaf(fmaxf(acc2[nt][1] + bv.y, 0.f), wv.y, sA);
                sB = fmaf(fmaxf(acc2[nt][2] + bv.x, 0.f), wv.x, sB);
                sB = fmaf(fmaxf(acc2[nt][3] + bv.y, 0.f), wv.y, sB);
            }
            sA += __shfl_xor_sync(0xffffffffu, sA, 1);
            sA += __shfl_xor_sync(0xffffffffu, sA, 2);
            sB += __shfl_xor_sync(0xffffffffu, sB, 1);
            sB += __shfl_xor_sync(0xffffffffu, sB, 2);
            if (lq == 0) {
                float pA = (hp > 0.f) ? (sA + b3) : rawv[rA];
                float pB = (hp > 0.f) ? (sB + b3) : rawv[rA + 8];
                out_pred[(row0 + rA) * 16 + v] = pA;
                out_pred[(row0 + rA + 8) * 16 + v] = pB;
            }
        }
    } else {
        // ================= PAIRS =================
        float* rows = sm;                 // [64][17]
        int pb = blockIdx.x - 256;
        int pg = pb & 3, chunk = pb >> 2;
        int sbase = chunk * 64;
        for (int t = tid; t < 1024; t += 256) {
            int s = t >> 4, j = t & 15;
            rows[s * 17 + j] = data[(sbase + s) * 16 + j];
        }
        __syncthreads();
        if (tid < 240) {
            int p = pg * 60 + (tid >> 2), q = tid & 3;
            int pi = p / 15, r = p - pi * 15;
            int pj = r + (r >= pi ? 1 : 0);
            int co = q * 8;
            float4 wa0 = *(const float4*)(Wt1 + p * 64 + co);
            float4 wa1 = *(const float4*)(Wt1 + p * 64 + co + 4);
            float4 wb0 = *(const float4*)(Wt1 + p * 64 + 32 + co);
            float4 wb1 = *(const float4*)(Wt1 + p * 64 + 32 + co + 4);
            float4 bb0 = *(const float4*)(bt1 + p * 32 + co);
            float4 bb1 = *(const float4*)(bt1 + p * 32 + co + 4);
            float4 w20 = *(const float4*)(Wt2 + p * 32 + co);
            float4 w21 = *(const float4*)(Wt2 + p * 32 + co + 4);
            float b2v = bt2[p];

            float accs = 0.f;
            for (int s = 0; s < 64; s += 2) {
                float aX = rows[s * 17 + pi],       bX = rows[s * 17 + pj];
                float aY = rows[(s+1) * 17 + pi],   bY = rows[(s+1) * 17 + pj];
                float2 xiX = make_float2(aX, aX), xjX = make_float2(bX, bX);
                float2 xiY = make_float2(aY, aY), xjY = make_float2(bY, bY);
                float2 sv0X = make_float2(0.f, 0.f), sv1X = make_float2(0.f, 0.f);
                float2 sv0Y = make_float2(0.f, 0.f), sv1Y = make_float2(0.f, 0.f);
                float2 h;
                h = ffma2(xiX, make_float2(wa0.x, wa0.y), make_float2(bb0.x, bb0.y));
                h = ffma2(xjX, make_float2(wb0.x, wb0.y), h);
                h.x = fmaxf(h.x, 0.f); h.y = fmaxf(h.y, 0.f);
                sv0X = ffma2(h, make_float2(w20.x, w20.y), sv0X);
                h = ffma2(xiY, make_float2(wa0.x, wa0.y), make_float2(bb0.x, bb0.y));
                h = ffma2(xjY, make_float2(wb0.x, wb0.y), h);
                h.x = fmaxf(h.x, 0.f); h.y = fmaxf(h.y, 0.f);
                sv0Y = ffma2(h, make_float2(w20.x, w20.y), sv0Y);

                h = ffma2(xiX, make_float2(wa0.z, wa0.w), make_float2(bb0.z, bb0.w));
                h = ffma2(xjX, make_float2(wb0.z, wb0.w), h);
                h.x = fmaxf(h.x, 0.f); h.y = fmaxf(h.y, 0.f);
                sv1X = ffma2(h, make_float2(w20.z, w20.w), sv1X);
                h = ffma2(xiY, make_float2(wa0.z, wa0.w), make_float2(bb0.z, bb0.w));
                h = ffma2(xjY, make_float2(wb0.z, wb0.w), h);
                h.x = fmaxf(h.x, 0.f); h.y = fmaxf(h.y, 0.f);
                sv1Y = ffma2(h, make_float2(w20.z, w20.w), sv1Y);

                h = ffma2(xiX, make_float2(wa1.x, wa1.y), make_float2(bb1.x, bb1.y));
                h = ffma2(xjX, make_float2(wb1.x, wb1.y), h);
                h.x = fmaxf(h.x, 0.f); h.y = fmaxf(h.y, 0.f);
                sv0X = ffma2(h, make_float2(w21.x, w21.y), sv0X);
                h = ffma2(xiY, make_float2(wa1.x, wa1.y), make_float2(bb1.x, bb1.y));
                h = ffma2(xjY, make_float2(wb1.x, wb1.y), h);
                h.x = fmaxf(h.x, 0.f); h.y = fmaxf(h.y, 0.f);
                sv0Y = ffma2(h, make_float2(w21.x, w21.y), sv0Y);

                h = ffma2(xiX, make_float2(wa1.z, wa1.w), make_float2(bb1.z, bb1.w));
                h = ffma2(xjX, make_float2(wb1.z, wb1.w), h);
                h.x = fmaxf(h.x, 0.f); h.y = fmaxf(h.y, 0.f);
                sv1X = ffma2(h, make_float2(w21.z, w21.w), sv1X);
                h = ffma2(xiY, make_float2(wa1.z, wa1.w), make_float2(bb1.z, bb1.w));
                h = ffma2(xjY, make_float2(wb1.z, wb1.w), h);
                h.x = fmaxf(h.x, 0.f); h.y = fmaxf(h.y, 0.f);
                sv1Y = ffma2(h, make_float2(w21.z, w21.w), sv1Y);

                float svX = (sv0X.x + sv0X.y) + (sv1X.x + sv1X.y);
                float svY = (sv0Y.x + sv0Y.y) + (sv1Y.x + sv1Y.y);
                svX += __shfl_xor_sync(0xffffffffu, svX, 1);
                svY += __shfl_xor_sync(0xffffffffu, svY, 1);
                svX += __shfl_xor_sync(0xffffffffu, svX, 2);
                svY += __shfl_xor_sync(0xffffffffu, svY, 2);
                accs += __fdividef(1.f, 1.f + __expf(-(svX + b2v)));
                accs += __fdividef(1.f, 1.f + __expf(-(svY + b2v)));
            }
            if (q == 0) g_part[p * 128 + chunk] = accs;
        }
    }
}

// ---------------- Kernel D: finalize ----------------
__global__ void __launch_bounds__(256) k_fin(float* __restrict__ out_scores) {
    int t = threadIdx.x;
    if (t < 240) {
        const float4* b = (const float4*)(g_part + t * 128);
        float s = 0.f;
#pragma unroll
        for (int i = 0; i < 32; i++) {
            float4 v = b[i];
            s += (v.x + v.y) + (v.z + v.w);
        }
        int pi = t / 15, r = t - pi * 15;
        int pj = r + (r >= pi ? 1 : 0);
        out_scores[pi * 16 + pj] = s * (1.f / 8192.f);
    }
    if (t < 16) out_scores[t * 17] = 0.f;
}

// ---------------- launch ----------------
extern "C" void kernel_launch(void* const* d_in, const int* in_sizes, int n_in,
                              void* d_out, int out_size) {
    const float* data = (const float*)d_in[0];
    const float* Ws1 = (const float*)d_in[1];
    const float* bs1 = (const float*)d_in[2];
    const float* Ws2 = (const float*)d_in[3];
    const float* bs2 = (const float*)d_in[4];
    const float* Ws3 = (const float*)d_in[5];
    const float* bs3 = (const float*)d_in[6];
    const float* Wm1 = (const float*)d_in[7];
    const float* bm1 = (const float*)d_in[8];
    const float* Wm2 = (const float*)d_in[9];
    const float* bm2 = (const float*)d_in[10];
    const float* Wm3 = (const float*)d_in[11];
    const float* bm3 = (const float*)d_in[12];
    const float* Wt1 = (const float*)d_in[13];
    const float* bt1 = (const float*)d_in[14];
    const float* Wt2 = (const float*)d_in[15];
    const float* bt2 = (const float*)d_in[16];

    float* out = (float*)d_out;
    float* out_adj    = out;
    float* out_pred   = out + 256;
    float* out_scores = out + 256 + 131072;

    cudaFuncSetAttribute(k_main, cudaFuncAttributeMaxDynamicSharedMemorySize, 31296);

    k_prep<<<96, 256>>>(Wm1, Wm2, data);
    k_adj<<<1, 1024>>>(Ws1, bs1, Ws2, bs2, Ws3, bs3, out_adj);
    k_main<<<768, 256, 31296>>>(data, bm1, bm2, Wm3, bm3, Wt1, bt1, Wt2, bt2, out_pred);
    k_fin<<<1, 256>>>(out_scores);
}

// round 12
// speedup vs baseline: 3.7803x; 1.0801x over previous
#include <cuda_runtime.h>
#include <cuda_fp16.h>
#include <math.h>

#define NV 16

// ---------------- device scratch ----------------
__device__ float g_pm[240];
__device__ float g_hp[16];
__device__ float g_part[240 * 128];
__device__ unsigned g_wpack[16 * 5120];    // per-v fp16 fragments: W1 1024 + W2 4096
__device__ float g_gram[32 * 256];
__device__ float g_colsum[32 * 16];

// packed f32x2 FMA (pairs path)
union F2U { float2 f; unsigned long long u; };
__device__ __forceinline__ float2 ffma2(float2 a, float2 b, float2 c) {
    F2U au, bu, cu, du;
    au.f = a; bu.f = b; cu.f = c;
    asm("fma.rn.f32x2 %0, %1, %2, %3;" : "=l"(du.u) : "l"(au.u), "l"(bu.u), "l"(cu.u));
    return du.f;
}

// fp16 m16n8k16 MMA, fp32 accumulate
__device__ __forceinline__ void mma_f16(float* d, const unsigned* a, const unsigned* b) {
    asm volatile(
        "mma.sync.aligned.m16n8k16.row.col.f32.f16.f16.f32 "
        "{%0,%1,%2,%3}, {%4,%5,%6,%7}, {%8,%9}, {%0,%1,%2,%3};"
        : "+f"(d[0]), "+f"(d[1]), "+f"(d[2]), "+f"(d[3])
        : "r"(a[0]), "r"(a[1]), "r"(a[2]), "r"(a[3]), "r"(b[0]), "r"(b[1]));
}

__device__ __forceinline__ unsigned pack2h(float a, float b) {
    __half2 h = __floats2half2_rn(a, b);
    return *reinterpret_cast<unsigned*>(&h);
}
__device__ __forceinline__ float hround(float x) {
    return __half2float(__float2half_rn(x));
}

// ---------------- Kernel P: weight prepack (blocks 0-63) + avg/Gram (blocks 64-95) ----------------
__global__ void __launch_bounds__(256) k_prep(
    const float* __restrict__ Wm1, const float* __restrict__ Wm2,
    const float* __restrict__ data)
{
    int bid = blockIdx.x, tid = threadIdx.x;
    if (bid < 64) {
        int v = bid >> 2, quarter = bid & 3;
        unsigned* dst = g_wpack + v * 5120;
        {
            int idx = quarter * 256 + tid;
            int nt = idx >> 6, lane = (idx >> 1) & 31, r = idx & 1;
            int lg = lane >> 2, lq = lane & 3;
            int n = nt * 8 + lg, kp = lq + 4 * r;
            int k0 = 2 * kp, k1 = 2 * kp + 1;
            float w0 = (k0 < 15) ? Wm1[v * 1920 + k0 * 128 + n] : 0.f;
            float w1 = (k1 < 15) ? Wm1[v * 1920 + k1 * 128 + n] : 0.f;
            dst[idx] = pack2h(w0, w1);
        }
        for (int idx = quarter * 1024 + tid; idx < quarter * 1024 + 1024; idx += 256) {
            int ks = idx >> 9, nt = (idx >> 6) & 7, lane = (idx >> 1) & 31, r = idx & 1;
            int lg = lane >> 2, lq = lane & 3;
            int n = nt * 8 + lg, kp = ks * 8 + lq + 4 * r;
            int k0 = 2 * kp, k1 = 2 * kp + 1;
            float w0 = Wm2[v * 8192 + k0 * 64 + n];
            float w1 = Wm2[v * 8192 + k1 * 64 + n];
            dst[1024 + idx] = pack2h(w0, w1);
        }
    } else {
        __shared__ float avs[256];
        int q = bid - 64;
        float s = 0.f;
#pragma unroll
        for (int b = 0; b < 16; b++) s += data[b * 8192 + q * 256 + tid];
        avs[tid] = s * (1.f / 16.f);
        __syncthreads();
        int i = tid >> 4, j = tid & 15;
        float g = 0.f;
#pragma unroll
        for (int r = 0; r < 16; r++) g += avs[r * 16 + i] * avs[r * 16 + j];
        g_gram[q * 256 + tid] = g;
        if (tid < 16) {
            float cs = 0.f;
#pragma unroll
            for (int r = 0; r < 16; r++) cs += avs[r * 16 + tid];
            g_colsum[q * 16 + tid] = cs;
        }
    }
}

// ---------------- Kernel A: corr -> MLP -> adj -> masks ----------------
__global__ void __launch_bounds__(1024) k_adj(
    const float* __restrict__ Ws1, const float* __restrict__ bs1,
    const float* __restrict__ Ws2, const float* __restrict__ bs2,
    const float* __restrict__ Ws3, const float* __restrict__ bs3,
    float* __restrict__ out_adj)
{
    __shared__ float scratch[1024];
    __shared__ float cm[16];
    __shared__ float covs[256];
    __shared__ float corr_s[256];
    __shared__ float h1s[256];
    __shared__ float h2s[128];
    __shared__ float adj_s[256];
    __shared__ float pms[240];

    int tid = threadIdx.x;
    {
        int pr = tid & 255, q4 = tid >> 8;
        float s = 0.f;
#pragma unroll
        for (int q = q4 * 8; q < q4 * 8 + 8; q++) s += g_gram[q * 256 + pr];
        scratch[tid] = s;
    }
    if (tid < 16) {
        float s = 0.f;
#pragma unroll
        for (int q = 0; q < 32; q++) s += g_colsum[q * 16 + tid];
        cm[tid] = s * (1.f / 512.f);
    }
    __syncthreads();
    if (tid < 256) {
        float G = scratch[tid] + scratch[256 + tid] + scratch[512 + tid] + scratch[768 + tid];
        int i = tid >> 4, j = tid & 15;
        covs[tid] = G - 512.f * cm[i] * cm[j];
    }
    __syncthreads();
    if (tid < 256) {
        int i = tid >> 4, j = tid & 15;
        float si = sqrtf(fmaxf(covs[i * 16 + i], 0.f));
        float sj = sqrtf(fmaxf(covs[j * 16 + j], 0.f));
        float denom = si * sj;
        float c = denom > 0.f ? covs[tid] / denom : 0.f;
        c = fabsf(c);
        if (i == j) c = 0.f;
        corr_s[tid] = c;
    }
    __syncthreads();

    {
        int o = tid & 255, q = tid >> 8;
        float s = 0.f;
        for (int k = q * 64; k < q * 64 + 64; k++) s = fmaf(corr_s[k], Ws1[k * 256 + o], s);
        scratch[q * 256 + o] = s;
    }
    __syncthreads();
    if (tid < 256)
        h1s[tid] = fmaxf(scratch[tid] + scratch[256 + tid] + scratch[512 + tid] + scratch[768 + tid] + bs1[tid], 0.f);
    __syncthreads();

    {
        int o = tid & 127, q = tid >> 7;
        float s = 0.f;
        for (int k = q * 32; k < q * 32 + 32; k++) s = fmaf(h1s[k], Ws2[k * 128 + o], s);
        scratch[q * 128 + o] = s;
    }
    __syncthreads();
    if (tid < 128) {
        float s = bs2[tid];
        for (int q = 0; q < 8; q++) s += scratch[q * 128 + tid];
        h2s[tid] = fmaxf(s, 0.f);
    }
    __syncthreads();

    {
        int o = tid & 255, q = tid >> 8;
        float s = 0.f;
        for (int k = q * 32; k < q * 32 + 32; k++) s = fmaf(h2s[k], Ws3[k * 256 + o], s);
        scratch[q * 256 + o] = s;
    }
    __syncthreads();
    if (tid < 256) {
        float logit = scratch[tid] + scratch[256 + tid] + scratch[512 + tid] + scratch[768 + tid] + bs3[tid];
        float a = 1.f / (1.f + expf(-logit));
        int i = tid >> 4, j = tid & 15;
        float val = (j > i) ? a : 0.f;
        adj_s[tid] = val;
        out_adj[tid] = val;
    }
    __syncthreads();
    if (tid < 240) {
        int v = tid / 15, p = tid - v * 15;
        int g = p + (p >= v ? 1 : 0);
        float m = (adj_s[g * 16 + v] > 0.5f) ? 1.f : 0.f;
        pms[tid] = m;
        g_pm[tid] = m;
    }
    __syncthreads();
    if (tid < 16) {
        float s = 0.f;
        for (int p = 0; p < 15; p++) s += pms[tid * 15 + p];
        g_hp[tid] = (s > 0.f) ? 1.f : 0.f;
    }
}

// ---- mech helpers (fp16, 2-term A-split) ----
__device__ __forceinline__ void l1_step(const unsigned* W1s, int lane, int ks,
    const unsigned* ahi, const unsigned* alo, float* a, float* b)
{
    int nt0 = 2 * ks, nt1 = nt0 + 1;
    const unsigned* b0p = W1s + (nt0 * 32 + lane) * 2;
    const unsigned* b1p = W1s + (nt1 * 32 + lane) * 2;
    unsigned b0v[2] = { b0p[0], b0p[1] }, b1v[2] = { b1p[0], b1p[1] };
    mma_f16(a, ahi, b0v);
    mma_f16(b, ahi, b1v);
    mma_f16(a, alo, b0v);
    mma_f16(b, alo, b1v);
}

__device__ __forceinline__ void l1_epi(const float* b1s, int lq, int ks,
    const float* a, const float* b, unsigned* a2hi, unsigned* a2lo)
{
    float2 bva = *(const float2*)(b1s + (2 * ks) * 8 + 2 * lq);
    float2 bvb = *(const float2*)(b1s + (2 * ks + 1) * 8 + 2 * lq);
    float h0 = fmaxf(a[0] + bva.x, 0.f), h1 = fmaxf(a[1] + bva.y, 0.f);
    float h2 = fmaxf(a[2] + bva.x, 0.f), h3 = fmaxf(a[3] + bva.y, 0.f);
    float h4 = fmaxf(b[0] + bvb.x, 0.f), h5 = fmaxf(b[1] + bvb.y, 0.f);
    float h6 = fmaxf(b[2] + bvb.x, 0.f), h7 = fmaxf(b[3] + bvb.y, 0.f);
    a2hi[0] = pack2h(h0, h1);
    a2hi[1] = pack2h(h2, h3);
    a2hi[2] = pack2h(h4, h5);
    a2hi[3] = pack2h(h6, h7);
    a2lo[0] = pack2h(h0 - hround(h0), h1 - hround(h1));
    a2lo[1] = pack2h(h2 - hround(h2), h3 - hround(h3));
    a2lo[2] = pack2h(h4 - hround(h4), h5 - hround(h5));
    a2lo[3] = pack2h(h6 - hround(h6), h7 - hround(h7));
}

// ---------------- Kernel M: FUSED mech (blocks 0-255) + pairs (blocks 256-767) ----------------
__global__ void __launch_bounds__(256, 2) k_main(
    const float* __restrict__ data,
    const float* __restrict__ bm1, const float* __restrict__ bm2,
    const float* __restrict__ Wm3, const float* __restrict__ bm3,
    const float* __restrict__ Wt1, const float* __restrict__ bt1,
    const float* __restrict__ Wt2, const float* __restrict__ bt2,
    float* __restrict__ out_pred)
{
    extern __shared__ float sm[];
    int tid = threadIdx.x;

    if (blockIdx.x < 256) {
        // ================= MECH =================
        const int bx = blockIdx.x & 15;
        const int v = blockIdx.x >> 4;
        unsigned* Wp  = (unsigned*)sm;
        float* b1s  = sm + 5120;
        float* b2s  = sm + 5248;
        float* w3s  = sm + 5312;
        float* pms  = sm + 5376;
        float* rawv = sm + 5392;
        unsigned* Xh  = (unsigned*)(sm + 5520);
        unsigned* Xl  = (unsigned*)(sm + 6672);

        int w = tid >> 5, lane = tid & 31;
        int lq = lane & 3, lg = lane >> 2;

        {
            const float4* src = (const float4*)(g_wpack + v * 5120);
            float4* dst = (float4*)Wp;
            for (int i = tid; i < 1280; i += 256) dst[i] = src[i];
        }
        if (tid < 128) b1s[tid] = bm1[v * 128 + tid];
        if (tid < 64) { b2s[tid] = bm2[v * 64 + tid]; w3s[tid] = Wm3[v * 64 + tid]; }
        if (tid < 16) pms[tid] = (tid < 15) ? g_pm[v * 15 + tid] : 0.f;
        float hp = g_hp[v];
        float b3 = bm3[v];

        const unsigned* W1s = Wp;
        const unsigned* W2s = Wp + 1024;
        int rA = w * 16 + lg;

        for (int tile = 0; tile < 4; tile++) {
            __syncthreads();
            int row0 = bx * 512 + tile * 128;
            for (int idx = tid; idx < 1024; idx += 256) {
                int row = idx >> 3, kp = idx & 7;
                int p0 = 2 * kp, p1 = 2 * kp + 1;
                const float* drow = data + (row0 + row) * 16;
                float v0 = 0.f, v1 = 0.f;
                v0 = drow[p0 + (p0 >= v ? 1 : 0)] * pms[p0];
                if (p1 < 15) v1 = drow[p1 + (p1 >= v ? 1 : 0)] * pms[p1];
                Xh[row * 9 + kp] = pack2h(v0, v1);
                Xl[row * 9 + kp] = pack2h(v0 - hround(v0), v1 - hround(v1));
            }
            if (tid < 128) rawv[tid] = data[(row0 + tid) * 16 + v];
            __syncthreads();

            unsigned ahi[4], alo[4];
            ahi[0] = Xh[rA * 9 + lq];           ahi[1] = Xh[(rA + 8) * 9 + lq];
            ahi[2] = Xh[rA * 9 + lq + 4];       ahi[3] = Xh[(rA + 8) * 9 + lq + 4];
            alo[0] = Xl[rA * 9 + lq];           alo[1] = Xl[(rA + 8) * 9 + lq];
            alo[2] = Xl[rA * 9 + lq + 4];       alo[3] = Xl[(rA + 8) * 9 + lq + 4];

            float acc2[8][4];
#pragma unroll
            for (int nt = 0; nt < 8; nt++)
#pragma unroll
                for (int i = 0; i < 4; i++) acc2[nt][i] = 0.f;

            unsigned c2hi[4], c2lo[4];
            {
                float a1[4] = {0.f, 0.f, 0.f, 0.f}, b1r[4] = {0.f, 0.f, 0.f, 0.f};
                l1_step(W1s, lane, 0, ahi, alo, a1, b1r);
                l1_epi(b1s, lq, 0, a1, b1r, c2hi, c2lo);
            }
#pragma unroll
            for (int ks = 0; ks < 8; ks++) {
                float n1a[4] = {0.f, 0.f, 0.f, 0.f}, n1b[4] = {0.f, 0.f, 0.f, 0.f};
                if (ks < 7) l1_step(W1s, lane, ks + 1, ahi, alo, n1a, n1b);
#pragma unroll
                for (int nt = 0; nt < 8; nt++) {
                    const unsigned* bp = W2s + (ks * 256 + nt * 32 + lane) * 2;
                    unsigned bv[2] = { bp[0], bp[1] };
                    mma_f16(acc2[nt], c2hi, bv);
                    mma_f16(acc2[nt], c2lo, bv);
                }
                if (ks < 7) l1_epi(b1s, lq, ks + 1, n1a, n1b, c2hi, c2lo);
            }

            float sA = 0.f, sB = 0.f;
#pragma unroll
            for (int nt = 0; nt < 8; nt++) {
                float2 bv = *(const float2*)(b2s + nt * 8 + 2 * lq);
                float2 wv = *(const float2*)(w3s + nt * 8 + 2 * lq);
                sA = fmaf(fmaxf(acc2[nt][0] + bv.x, 0.f), wv.x, sA);
                sA = fmaf(fmaxf(acc2[nt][1] + bv.y, 0.f), wv.y, sA);
                sB = fmaf(fmaxf(acc2[nt][2] + bv.x, 0.f), wv.x, sB);
                sB = fmaf(fmaxf(acc2[nt][3] + bv.y, 0.f), wv.y, sB);
            }
            sA += __shfl_xor_sync(0xffffffffu, sA, 1);
            sA += __shfl_xor_sync(0xffffffffu, sA, 2);
            sB += __shfl_xor_sync(0xffffffffu, sB, 1);
            sB += __shfl_xor_sync(0xffffffffu, sB, 2);
            if (lq == 0) {
                float pA = (hp > 0.f) ? (sA + b3) : rawv[rA];
                float pB = (hp > 0.f) ? (sB + b3) : rawv[rA + 8];
                out_pred[(row0 + rA) * 16 + v] = pA;
                out_pred[(row0 + rA + 8) * 16 + v] = pB;
            }
        }
    } else {
        // ================= PAIRS =================
        float* rows = sm;                 // [64][17]
        int pb = blockIdx.x - 256;
        int pg = pb & 3, chunk = pb >> 2;
        int sbase = chunk * 64;
        for (int t = tid; t < 1024; t += 256) {
            int s = t >> 4, j = t & 15;
            rows[s * 17 + j] = data[(sbase + s) * 16 + j];
        }
        __syncthreads();
        if (tid < 240) {
            int p = pg * 60 + (tid >> 2), q = tid & 3;
            int pi = p / 15, r = p - pi * 15;
            int pj = r + (r >= pi ? 1 : 0);
            int co = q * 8;
            float4 wa0 = *(const float4*)(Wt1 + p * 64 + co);
            float4 wa1 = *(const float4*)(Wt1 + p * 64 + co + 4);
            float4 wb0 = *(const float4*)(Wt1 + p * 64 + 32 + co);
            float4 wb1 = *(const float4*)(Wt1 + p * 64 + 32 + co + 4);
            float4 bb0 = *(const float4*)(bt1 + p * 32 + co);
            float4 bb1 = *(const float4*)(bt1 + p * 32 + co + 4);
            float4 w20 = *(const float4*)(Wt2 + p * 32 + co);
            float4 w21 = *(const float4*)(Wt2 + p * 32 + co + 4);
            float b2v = bt2[p];

            float accs = 0.f;
            for (int s = 0; s < 64; s += 2) {
                float aX = rows[s * 17 + pi],       bX = rows[s * 17 + pj];
                float aY = rows[(s+1) * 17 + pi],   bY = rows[(s+1) * 17 + pj];
                float2 xiX = make_float2(aX, aX), xjX = make_float2(bX, bX);
                float2 xiY = make_float2(aY, aY), xjY = make_float2(bY, bY);
                float2 sv0X = make_float2(0.f, 0.f), sv1X = make_float2(0.f, 0.f);
                float2 sv0Y = make_float2(0.f, 0.f), sv1Y = make_float2(0.f, 0.f);
                float2 h;
                h = ffma2(xiX, make_float2(wa0.x, wa0.y), make_float2(bb0.x, bb0.y));
                h = ffma2(xjX, make_float2(wb0.x, wb0.y), h);
                h.x = fmaxf(h.x, 0.f); h.y = fmaxf(h.y, 0.f);
                sv0X = ffma2(h, make_float2(w20.x, w20.y), sv0X);
                h = ffma2(xiY, make_float2(wa0.x, wa0.y), make_float2(bb0.x, bb0.y));
                h = ffma2(xjY, make_float2(wb0.x, wb0.y), h);
                h.x = fmaxf(h.x, 0.f); h.y = fmaxf(h.y, 0.f);
                sv0Y = ffma2(h, make_float2(w20.x, w20.y), sv0Y);

                h = ffma2(xiX, make_float2(wa0.z, wa0.w), make_float2(bb0.z, bb0.w));
                h = ffma2(xjX, make_float2(wb0.z, wb0.w), h);
                h.x = fmaxf(h.x, 0.f); h.y = fmaxf(h.y, 0.f);
                sv1X = ffma2(h, make_float2(w20.z, w20.w), sv1X);
                h = ffma2(xiY, make_float2(wa0.z, wa0.w), make_float2(bb0.z, bb0.w));
                h = ffma2(xjY, make_float2(wb0.z, wb0.w), h);
                h.x = fmaxf(h.x, 0.f); h.y = fmaxf(h.y, 0.f);
                sv1Y = ffma2(h, make_float2(w20.z, w20.w), sv1Y);

                h = ffma2(xiX, make_float2(wa1.x, wa1.y), make_float2(bb1.x, bb1.y));
                h = ffma2(xjX, make_float2(wb1.x, wb1.y), h);
                h.x = fmaxf(h.x, 0.f); h.y = fmaxf(h.y, 0.f);
                sv0X = ffma2(h, make_float2(w21.x, w21.y), sv0X);
                h = ffma2(xiY, make_float2(wa1.x, wa1.y), make_float2(bb1.x, bb1.y));
                h = ffma2(xjY, make_float2(wb1.x, wb1.y), h);
                h.x = fmaxf(h.x, 0.f); h.y = fmaxf(h.y, 0.f);
                sv0Y = ffma2(h, make_float2(w21.x, w21.y), sv0Y);

                h = ffma2(xiX, make_float2(wa1.z, wa1.w), make_float2(bb1.z, bb1.w));
                h = ffma2(xjX, make_float2(wb1.z, wb1.w), h);
                h.x = fmaxf(h.x, 0.f); h.y = fmaxf(h.y, 0.f);
                sv1X = ffma2(h, make_float2(w21.z, w21.w), sv1X);
                h = ffma2(xiY, make_float2(wa1.z, wa1.w), make_float2(bb1.z, bb1.w));
                h = ffma2(xjY, make_float2(wb1.z, wb1.w), h);
                h.x = fmaxf(h.x, 0.f); h.y = fmaxf(h.y, 0.f);
                sv1Y = ffma2(h, make_float2(w21.z, w21.w), sv1Y);

                float svX = (sv0X.x + sv0X.y) + (sv1X.x + sv1X.y);
                float svY = (sv0Y.x + sv0Y.y) + (sv1Y.x + sv1Y.y);
                svX += __shfl_xor_sync(0xffffffffu, svX, 1);
                svY += __shfl_xor_sync(0xffffffffu, svY, 1);
                svX += __shfl_xor_sync(0xffffffffu, svX, 2);
                svY += __shfl_xor_sync(0xffffffffu, svY, 2);
                accs += __fdividef(1.f, 1.f + __expf(-(svX + b2v)));
                accs += __fdividef(1.f, 1.f + __expf(-(svY + b2v)));
            }
            if (q == 0) g_part[p * 128 + chunk] = accs;
        }
    }
}

// ---------------- Kernel D: finalize (30 blocks, warp-per-pair, coalesced) ----------------
__global__ void __launch_bounds__(256) k_fin(float* __restrict__ out_scores) {
    int w = threadIdx.x >> 5, lane = threadIdx.x & 31;
    int p = blockIdx.x * 8 + w;     // 30 blocks * 8 warps = 240 pairs
    float s = 0.f;
#pragma unroll
    for (int i = 0; i < 4; i++) s += g_part[p * 128 + i * 32 + lane];
#pragma unroll
    for (int off = 16; off > 0; off >>= 1)
        s += __shfl_xor_sync(0xffffffffu, s, off);
    if (lane == 0) {
        int pi = p / 15, r = p - pi * 15;
        int pj = r + (r >= pi ? 1 : 0);
        out_scores[pi * 16 + pj] = s * (1.f / 8192.f);
    }
    if (blockIdx.x == 0 && w == 0 && lane < 16) out_scores[lane * 17] = 0.f;
}

// ---------------- launch ----------------
extern "C" void kernel_launch(void* const* d_in, const int* in_sizes, int n_in,
                              void* d_out, int out_size) {
    const float* data = (const float*)d_in[0];
    const float* Ws1 = (const float*)d_in[1];
    const float* bs1 = (const float*)d_in[2];
    const float* Ws2 = (const float*)d_in[3];
    const float* bs2 = (const float*)d_in[4];
    const float* Ws3 = (const float*)d_in[5];
    const float* bs3 = (const float*)d_in[6];
    const float* Wm1 = (const float*)d_in[7];
    const float* bm1 = (const float*)d_in[8];
    const float* Wm2 = (const float*)d_in[9];
    const float* bm2 = (const float*)d_in[10];
    const float* Wm3 = (const float*)d_in[11];
    const float* bm3 = (const float*)d_in[12];
    const float* Wt1 = (const float*)d_in[13];
    const float* bt1 = (const float*)d_in[14];
    const float* Wt2 = (const float*)d_in[15];
    const float* bt2 = (const float*)d_in[16];

    float* out = (float*)d_out;
    float* out_adj    = out;
    float* out_pred   = out + 256;
    float* out_scores = out + 256 + 131072;

    cudaFuncSetAttribute(k_main, cudaFuncAttributeMaxDynamicSharedMemorySize, 31296);

    k_prep<<<96, 256>>>(Wm1, Wm2, data);
    k_adj<<<1, 1024>>>(Ws1, bs1, Ws2, bs2, Ws3, bs3, out_adj);
    k_main<<<768, 256, 31296>>>(data, bm1, bm2, Wm3, bm3, Wt1, bt1, Wt2, bt2, out_pred);
    k_fin<<<30, 256>>>(out_scores);
}

// round 14
// speedup vs baseline: 3.8182x; 1.0100x over previous
#include <cuda_runtime.h>
#include <cuda_fp16.h>
#include <math.h>

#define NV 16

// ---------------- device scratch ----------------
__device__ float g_pm[240];
__device__ float g_hp[16];
__device__ float g_part[240 * 64];
__device__ unsigned g_wpack[16 * 5120];    // per-v fp16 fragments: W1 1024 + W2 4096
__device__ float g_gram[32 * 256];
__device__ float g_colsum[32 * 16];

// packed f32x2 FMA (pairs path)
union F2U { float2 f; unsigned long long u; };
__device__ __forceinline__ float2 ffma2(float2 a, float2 b, float2 c) {
    F2U au, bu, cu, du;
    au.f = a; bu.f = b; cu.f = c;
    asm("fma.rn.f32x2 %0, %1, %2, %3;" : "=l"(du.u) : "l"(au.u), "l"(bu.u), "l"(cu.u));
    return du.f;
}

// fp16 m16n8k16 MMA, fp32 accumulate
__device__ __forceinline__ void mma_f16(float* d, const unsigned* a, const unsigned* b) {
    asm volatile(
        "mma.sync.aligned.m16n8k16.row.col.f32.f16.f16.f32 "
        "{%0,%1,%2,%3}, {%4,%5,%6,%7}, {%8,%9}, {%0,%1,%2,%3};"
        : "+f"(d[0]), "+f"(d[1]), "+f"(d[2]), "+f"(d[3])
        : "r"(a[0]), "r"(a[1]), "r"(a[2]), "r"(a[3]), "r"(b[0]), "r"(b[1]));
}

__device__ __forceinline__ unsigned pack2h(float a, float b) {
    __half2 h = __floats2half2_rn(a, b);
    return *reinterpret_cast<unsigned*>(&h);
}
__device__ __forceinline__ float hround(float x) {
    return __half2float(__float2half_rn(x));
}

// ---------------- Kernel P: weight prepack (blocks 0-63) + avg/Gram (blocks 64-95) ----------------
__global__ void __launch_bounds__(256) k_prep(
    const float* __restrict__ Wm1, const float* __restrict__ Wm2,
    const float* __restrict__ data)
{
    int bid = blockIdx.x, tid = threadIdx.x;
    if (bid < 64) {
        int v = bid >> 2, quarter = bid & 3;
        unsigned* dst = g_wpack + v * 5120;
        {
            int idx = quarter * 256 + tid;
            int nt = idx >> 6, lane = (idx >> 1) & 31, r = idx & 1;
            int lg = lane >> 2, lq = lane & 3;
            int n = nt * 8 + lg, kp = lq + 4 * r;
            int k0 = 2 * kp, k1 = 2 * kp + 1;
            float w0 = (k0 < 15) ? Wm1[v * 1920 + k0 * 128 + n] : 0.f;
            float w1 = (k1 < 15) ? Wm1[v * 1920 + k1 * 128 + n] : 0.f;
            dst[idx] = pack2h(w0, w1);
        }
        for (int idx = quarter * 1024 + tid; idx < quarter * 1024 + 1024; idx += 256) {
            int ks = idx >> 9, nt = (idx >> 6) & 7, lane = (idx >> 1) & 31, r = idx & 1;
            int lg = lane >> 2, lq = lane & 3;
            int n = nt * 8 + lg, kp = ks * 8 + lq + 4 * r;
            int k0 = 2 * kp, k1 = 2 * kp + 1;
            float w0 = Wm2[v * 8192 + k0 * 64 + n];
            float w1 = Wm2[v * 8192 + k1 * 64 + n];
            dst[1024 + idx] = pack2h(w0, w1);
        }
    } else {
        __shared__ float avs[256];
        int q = bid - 64;
        float s = 0.f;
#pragma unroll
        for (int b = 0; b < 16; b++) s += data[b * 8192 + q * 256 + tid];
        avs[tid] = s * (1.f / 16.f);
        __syncthreads();
        int i = tid >> 4, j = tid & 15;
        float g = 0.f;
#pragma unroll
        for (int r = 0; r < 16; r++) g += avs[r * 16 + i] * avs[r * 16 + j];
        g_gram[q * 256 + tid] = g;
        if (tid < 16) {
            float cs = 0.f;
#pragma unroll
            for (int r = 0; r < 16; r++) cs += avs[r * 16 + tid];
            g_colsum[q * 16 + tid] = cs;
        }
    }
}

// ---------------- Kernel A: corr -> MLP -> adj -> masks ----------------
__global__ void __launch_bounds__(1024) k_adj(
    const float* __restrict__ Ws1, const float* __restrict__ bs1,
    const float* __restrict__ Ws2, const float* __restrict__ bs2,
    const float* __restrict__ Ws3, const float* __restrict__ bs3,
    float* __restrict__ out_adj)
{
    __shared__ float scratch[1024];
    __shared__ float cm[16];
    __shared__ float covs[256];
    __shared__ float corr_s[256];
    __shared__ float h1s[256];
    __shared__ float h2s[128];
    __shared__ float adj_s[256];
    __shared__ float pms[240];

    int tid = threadIdx.x;
    {
        int pr = tid & 255, q4 = tid >> 8;
        float s = 0.f;
#pragma unroll
        for (int q = q4 * 8; q < q4 * 8 + 8; q++) s += g_gram[q * 256 + pr];
        scratch[tid] = s;
    }
    if (tid < 16) {
        float s = 0.f;
#pragma unroll
        for (int q = 0; q < 32; q++) s += g_colsum[q * 16 + tid];
        cm[tid] = s * (1.f / 512.f);
    }
    __syncthreads();
    if (tid < 256) {
        float G = scratch[tid] + scratch[256 + tid] + scratch[512 + tid] + scratch[768 + tid];
        int i = tid >> 4, j = tid & 15;
        covs[tid] = G - 512.f * cm[i] * cm[j];
    }
    __syncthreads();
    if (tid < 256) {
        int i = tid >> 4, j = tid & 15;
        float si = sqrtf(fmaxf(covs[i * 16 + i], 0.f));
        float sj = sqrtf(fmaxf(covs[j * 16 + j], 0.f));
        float denom = si * sj;
        float c = denom > 0.f ? covs[tid] / denom : 0.f;
        c = fabsf(c);
        if (i == j) c = 0.f;
        corr_s[tid] = c;
    }
    __syncthreads();

    {
        int o = tid & 255, q = tid >> 8;
        float s = 0.f;
        for (int k = q * 64; k < q * 64 + 64; k++) s = fmaf(corr_s[k], Ws1[k * 256 + o], s);
        scratch[q * 256 + o] = s;
    }
    __syncthreads();
    if (tid < 256)
        h1s[tid] = fmaxf(scratch[tid] + scratch[256 + tid] + scratch[512 + tid] + scratch[768 + tid] + bs1[tid], 0.f);
    __syncthreads();

    {
        int o = tid & 127, q = tid >> 7;
        float s = 0.f;
        for (int k = q * 32; k < q * 32 + 32; k++) s = fmaf(h1s[k], Ws2[k * 128 + o], s);
        scratch[q * 128 + o] = s;
    }
    __syncthreads();
    if (tid < 128) {
        float s = bs2[tid];
        for (int q = 0; q < 8; q++) s += scratch[q * 128 + tid];
        h2s[tid] = fmaxf(s, 0.f);
    }
    __syncthreads();

    {
        int o = tid & 255, q = tid >> 8;
        float s = 0.f;
        for (int k = q * 32; k < q * 32 + 32; k++) s = fmaf(h2s[k], Ws3[k * 256 + o], s);
        scratch[q * 256 + o] = s;
    }
    __syncthreads();
    if (tid < 256) {
        float logit = scratch[tid] + scratch[256 + tid] + scratch[512 + tid] + scratch[768 + tid] + bs3[tid];
        float a = 1.f / (1.f + expf(-logit));
        int i = tid >> 4, j = tid & 15;
        float val = (j > i) ? a : 0.f;
        adj_s[tid] = val;
        out_adj[tid] = val;
    }
    __syncthreads();
    if (tid < 240) {
        int v = tid / 15, p = tid - v * 15;
        int g = p + (p >= v ? 1 : 0);
        float m = (adj_s[g * 16 + v] > 0.5f) ? 1.f : 0.f;
        pms[tid] = m;
        g_pm[tid] = m;
    }
    __syncthreads();
    if (tid < 16) {
        float s = 0.f;
        for (int p = 0; p < 15; p++) s += pms[tid * 15 + p];
        g_hp[tid] = (s > 0.f) ? 1.f : 0.f;
    }
}

// ---- mech helpers (fp16, 2-term A-split layer 1, hi-only layer 2) ----
__device__ __forceinline__ void l1_step(const unsigned* W1s, int lane, int ks,
    const unsigned* ahi, const unsigned* alo, float* a, float* b)
{
    int nt0 = 2 * ks, nt1 = nt0 + 1;
    const unsigned* b0p = W1s + (nt0 * 32 + lane) * 2;
    const unsigned* b1p = W1s + (nt1 * 32 + lane) * 2;
    unsigned b0v[2] = { b0p[0], b0p[1] }, b1v[2] = { b1p[0], b1p[1] };
    mma_f16(a, ahi, b0v);
    mma_f16(b, ahi, b1v);
    mma_f16(a, alo, b0v);
    mma_f16(b, alo, b1v);
}

__device__ __forceinline__ void l1_epi_hi(const float* b1s, int lq, int ks,
    const float* a, const float* b, unsigned* a2hi)
{
    float2 bva = *(const float2*)(b1s + (2 * ks) * 8 + 2 * lq);
    float2 bvb = *(const float2*)(b1s + (2 * ks + 1) * 8 + 2 * lq);
    float h0 = fmaxf(a[0] + bva.x, 0.f), h1 = fmaxf(a[1] + bva.y, 0.f);
    float h2 = fmaxf(a[2] + bva.x, 0.f), h3 = fmaxf(a[3] + bva.y, 0.f);
    float h4 = fmaxf(b[0] + bvb.x, 0.f), h5 = fmaxf(b[1] + bvb.y, 0.f);
    float h6 = fmaxf(b[2] + bvb.x, 0.f), h7 = fmaxf(b[3] + bvb.y, 0.f);
    a2hi[0] = pack2h(h0, h1);
    a2hi[1] = pack2h(h2, h3);
    a2hi[2] = pack2h(h4, h5);
    a2hi[3] = pack2h(h6, h7);
}

// ---------------- Kernel M: FUSED mech (blocks 0-255) + pairs (blocks 256-511) ----------------
__global__ void __launch_bounds__(256, 2) k_main(
    const float* __restrict__ data,
    const float* __restrict__ bm1, const float* __restrict__ bm2,
    const float* __restrict__ Wm3, const float* __restrict__ bm3,
    const float* __restrict__ Wt1, const float* __restrict__ bt1,
    const float* __restrict__ Wt2, const float* __restrict__ bt2,
    float* __restrict__ out_pred)
{
    extern __shared__ float sm[];
    int tid = threadIdx.x;

    if (blockIdx.x < 256) {
        // ================= MECH =================
        const int bx = blockIdx.x & 15;
        const int v = blockIdx.x >> 4;
        unsigned* Wp  = (unsigned*)sm;
        float* b1s  = sm + 5120;
        float* b2s  = sm + 5248;
        float* w3s  = sm + 5312;
        float* pms  = sm + 5376;
        float* rawv = sm + 5392;
        unsigned* Xh  = (unsigned*)(sm + 5520);
        unsigned* Xl  = (unsigned*)(sm + 6672);

        int w = tid >> 5, lane = tid & 31;
        int lq = lane & 3, lg = lane >> 2;

        {
            const float4* src = (const float4*)(g_wpack + v * 5120);
            float4* dst = (float4*)Wp;
            for (int i = tid; i < 1280; i += 256) dst[i] = src[i];
        }
        if (tid < 128) b1s[tid] = bm1[v * 128 + tid];
        if (tid < 64) { b2s[tid] = bm2[v * 64 + tid]; w3s[tid] = Wm3[v * 64 + tid]; }
        if (tid < 16) pms[tid] = (tid < 15) ? g_pm[v * 15 + tid] : 0.f;
        float hp = g_hp[v];
        float b3 = bm3[v];

        const unsigned* W1s = Wp;
        const unsigned* W2s = Wp + 1024;
        int rA = w * 16 + lg;

        for (int tile = 0; tile < 4; tile++) {
            __syncthreads();
            int row0 = bx * 512 + tile * 128;
            for (int idx = tid; idx < 1024; idx += 256) {
                int row = idx >> 3, kp = idx & 7;
                int p0 = 2 * kp, p1 = 2 * kp + 1;
                const float* drow = data + (row0 + row) * 16;
                float v0 = 0.f, v1 = 0.f;
                v0 = drow[p0 + (p0 >= v ? 1 : 0)] * pms[p0];
                if (p1 < 15) v1 = drow[p1 + (p1 >= v ? 1 : 0)] * pms[p1];
                Xh[row * 9 + kp] = pack2h(v0, v1);
                Xl[row * 9 + kp] = pack2h(v0 - hround(v0), v1 - hround(v1));
            }
            if (tid < 128) rawv[tid] = data[(row0 + tid) * 16 + v];
            __syncthreads();

            unsigned ahi[4], alo[4];
            ahi[0] = Xh[rA * 9 + lq];           ahi[1] = Xh[(rA + 8) * 9 + lq];
            ahi[2] = Xh[rA * 9 + lq + 4];       ahi[3] = Xh[(rA + 8) * 9 + lq + 4];
            alo[0] = Xl[rA * 9 + lq];           alo[1] = Xl[(rA + 8) * 9 + lq];
            alo[2] = Xl[rA * 9 + lq + 4];       alo[3] = Xl[(rA + 8) * 9 + lq + 4];

            float acc2[8][4];
#pragma unroll
            for (int nt = 0; nt < 8; nt++)
#pragma unroll
                for (int i = 0; i < 4; i++) acc2[nt][i] = 0.f;

            unsigned c2hi[4];
            {
                float a1[4] = {0.f, 0.f, 0.f, 0.f}, b1r[4] = {0.f, 0.f, 0.f, 0.f};
                l1_step(W1s, lane, 0, ahi, alo, a1, b1r);
                l1_epi_hi(b1s, lq, 0, a1, b1r, c2hi);
            }
#pragma unroll
            for (int ks = 0; ks < 8; ks++) {
                float n1a[4] = {0.f, 0.f, 0.f, 0.f}, n1b[4] = {0.f, 0.f, 0.f, 0.f};
                if (ks < 7) l1_step(W1s, lane, ks + 1, ahi, alo, n1a, n1b);
#pragma unroll
                for (int nt = 0; nt < 8; nt++) {
                    const unsigned* bp = W2s + (ks * 256 + nt * 32 + lane) * 2;
                    unsigned bv[2] = { bp[0], bp[1] };
                    mma_f16(acc2[nt], c2hi, bv);
                }
                if (ks < 7) l1_epi_hi(b1s, lq, ks + 1, n1a, n1b, c2hi);
            }

            float sA = 0.f, sB = 0.f;
#pragma unroll
            for (int nt = 0; nt < 8; nt++) {
                float2 bv = *(const float2*)(b2s + nt * 8 + 2 * lq);
                float2 wv = *(const float2*)(w3s + nt * 8 + 2 * lq);
                sA = fmaf(fmaxf(acc2[nt][0] + bv.x, 0.f), wv.x, sA);
                sA = fmaf(fmaxf(acc2[nt][1] + bv.y, 0.f), wv.y, sA);
                sB = fmaf(fmaxf(acc2[nt][2] + bv.x, 0.f), wv.x, sB);
                sB = fmaf(fmaxf(acc2[nt][3] + bv.y, 0.f), wv.y, sB);
            }
            sA += __shfl_xor_sync(0xffffffffu, sA, 1);
            sA += __shfl_xor_sync(0xffffffffu, sA, 2);
            sB += __shfl_xor_sync(0xffffffffu, sB, 1);
            sB += __shfl_xor_sync(0xffffffffu, sB, 2);
            if (lq == 0) {
                float pA = (hp > 0.f) ? (sA + b3) : rawv[rA];
                float pB = (hp > 0.f) ? (sB + b3) : rawv[rA + 8];
                out_pred[(row0 + rA) * 16 + v] = pA;
                out_pred[(row0 + rA + 8) * 16 + v] = pB;
            }
        }
    } else {
        // ================= PAIRS =================
        float* rows = sm;                 // [128][17]
        int pb = blockIdx.x - 256;        // 0..255
        int pg = pb & 3, chunk = pb >> 2; // 4 pair-groups x 64 chunks
        int sbase = chunk * 128;
        for (int t = tid; t < 2048; t += 256) {
            int s = t >> 4, j = t & 15;
            rows[s * 17 + j] = data[(sbase + s) * 16 + j];
        }
        __syncthreads();
        if (tid < 240) {
            int p = pg * 60 + (tid >> 2), q = tid & 3;
            int pi = p / 15, r = p - pi * 15;
            int pj = r + (r >= pi ? 1 : 0);
            int co = q * 8;
            float4 wa0 = *(const float4*)(Wt1 + p * 64 + co);
            float4 wa1 = *(const float4*)(Wt1 + p * 64 + co + 4);
            float4 wb0 = *(const float4*)(Wt1 + p * 64 + 32 + co);
            float4 wb1 = *(const float4*)(Wt1 + p * 64 + 32 + co + 4);
            float4 bb0 = *(const float4*)(bt1 + p * 32 + co);
            float4 bb1 = *(const float4*)(bt1 + p * 32 + co + 4);
            float4 w20 = *(const float4*)(Wt2 + p * 32 + co);
            float4 w21 = *(const float4*)(Wt2 + p * 32 + co + 4);
            float b2v = bt2[p];

            float accs = 0.f;
            for (int s = 0; s < 128; s += 2) {
                float aX = rows[s * 17 + pi],       bX = rows[s * 17 + pj];
                float aY = rows[(s+1) * 17 + pi],   bY = rows[(s+1) * 17 + pj];
                float2 xiX = make_float2(aX, aX), xjX = make_float2(bX, bX);
                float2 xiY = make_float2(aY, aY), xjY = make_float2(bY, bY);
                float2 sv0X = make_float2(0.f, 0.f), sv1X = make_float2(0.f, 0.f);
                float2 sv0Y = make_float2(0.f, 0.f), sv1Y = make_float2(0.f, 0.f);
                float2 h;
                h = ffma2(xiX, make_float2(wa0.x, wa0.y), make_float2(bb0.x, bb0.y));
                h = ffma2(xjX, make_float2(wb0.x, wb0.y), h);
                h.x = fmaxf(h.x, 0.f); h.y = fmaxf(h.y, 0.f);
                sv0X = ffma2(h, make_float2(w20.x, w20.y), sv0X);
                h = ffma2(xiY, make_float2(wa0.x, wa0.y), make_float2(bb0.x, bb0.y));
                h = ffma2(xjY, make_float2(wb0.x, wb0.y), h);
                h.x = fmaxf(h.x, 0.f); h.y = fmaxf(h.y, 0.f);
                sv0Y = ffma2(h, make_float2(w20.x, w20.y), sv0Y);

                h = ffma2(xiX, make_float2(wa0.z, wa0.w), make_float2(bb0.z, bb0.w));
                h = ffma2(xjX, make_float2(wb0.z, wb0.w), h);
                h.x = fmaxf(h.x, 0.f); h.y = fmaxf(h.y, 0.f);
                sv1X = ffma2(h, make_float2(w20.z, w20.w), sv1X);
                h = ffma2(xiY, make_float2(wa0.z, wa0.w), make_float2(bb0.z, bb0.w));
                h = ffma2(xjY, make_float2(wb0.z, wb0.w), h);
                h.x = fmaxf(h.x, 0.f); h.y = fmaxf(h.y, 0.f);
                sv1Y = ffma2(h, make_float2(w20.z, w20.w), sv1Y);

                h = ffma2(xiX, make_float2(wa1.x, wa1.y), make_float2(bb1.x, bb1.y));
                h = ffma2(xjX, make_float2(wb1.x, wb1.y), h);
                h.x = fmaxf(h.x, 0.f); h.y = fmaxf(h.y, 0.f);
                sv0X = ffma2(h, make_float2(w21.x, w21.y), sv0X);
                h = ffma2(xiY, make_float2(wa1.x, wa1.y), make_float2(bb1.x, bb1.y));
                h = ffma2(xjY, make_float2(wb1.x, wb1.y), h);
                h.x = fmaxf(h.x, 0.f); h.y = fmaxf(h.y, 0.f);
                sv0Y = ffma2(h, make_float2(w21.x, w21.y), sv0Y);

                h = ffma2(xiX, make_float2(wa1.z, wa1.w), make_float2(bb1.z, bb1.w));
                h = ffma2(xjX, make_float2(wb1.z, wb1.w), h);
                h.x = fmaxf(h.x, 0.f); h.y = fmaxf(h.y, 0.f);
                sv1X = ffma2(h, make_float2(w21.z, w21.w), sv1X);
                h = ffma2(xiY, make_float2(wa1.z, wa1.w), make_float2(bb1.z, bb1.w));
                h = ffma2(xjY, make_float2(wb1.z, wb1.w), h);
                h.x = fmaxf(h.x, 0.f); h.y = fmaxf(h.y, 0.f);
                sv1Y = ffma2(h, make_float2(w21.z, w21.w), sv1Y);

                float svX = (sv0X.x + sv0X.y) + (sv1X.x + sv1X.y);
                float svY = (sv0Y.x + sv0Y.y) + (sv1Y.x + sv1Y.y);
                svX += __shfl_xor_sync(0xffffffffu, svX, 1);
                svY += __shfl_xor_sync(0xffffffffu, svY, 1);
                svX += __shfl_xor_sync(0xffffffffu, svX, 2);
                svY += __shfl_xor_sync(0xffffffffu, svY, 2);
                accs += __fdividef(1.f, 1.f + __expf(-(svX + b2v)));
                accs += __fdividef(1.f, 1.f + __expf(-(svY + b2v)));
            }
            if (q == 0) g_part[p * 64 + chunk] = accs;
        }
    }
}

// ---------------- Kernel D: finalize (30 blocks, warp-per-pair, coalesced) ----------------
__global__ void __launch_bounds__(256) k_fin(float* __restrict__ out_scores) {
    int w = threadIdx.x >> 5, lane = threadIdx.x & 31;
    int p = blockIdx.x * 8 + w;     // 30 blocks * 8 warps = 240 pairs
    float s = g_part[p * 64 + lane] + g_part[p * 64 + 32 + lane];
#pragma unroll
    for (int off = 16; off > 0; off >>= 1)
        s += __shfl_xor_sync(0xffffffffu, s, off);
    if (lane == 0) {
        int pi = p / 15, r = p - pi * 15;
        int pj = r + (r >= pi ? 1 : 0);
        out_scores[pi * 16 + pj] = s * (1.f / 8192.f);
    }
    if (blockIdx.x == 0 && w == 0 && lane < 16) out_scores[lane * 17] = 0.f;
}

// ---------------- launch ----------------
extern "C" void kernel_launch(void* const* d_in, const int* in_sizes, int n_in,
                              void* d_out, int out_size) {
    const float* data = (const float*)d_in[0];
    const float* Ws1 = (const float*)d_in[1];
    const float* bs1 = (const float*)d_in[2];
    const float* Ws2 = (const float*)d_in[3];
    const float* bs2 = (const float*)d_in[4];
    const float* Ws3 = (const float*)d_in[5];
    const float* bs3 = (const float*)d_in[6];
    const float* Wm1 = (const float*)d_in[7];
    const float* bm1 = (const float*)d_in[8];
    const float* Wm2 = (const float*)d_in[9];
    const float* bm2 = (const float*)d_in[10];
    const float* Wm3 = (const float*)d_in[11];
    const float* bm3 = (const float*)d_in[12];
    const float* Wt1 = (const float*)d_in[13];
    const float* bt1 = (const float*)d_in[14];
    const float* Wt2 = (const float*)d_in[15];
    const float* bt2 = (const float*)d_in[16];

    float* out = (float*)d_out;
    float* out_adj    = out;
    float* out_pred   = out + 256;
    float* out_scores = out + 256 + 131072;

    cudaFuncSetAttribute(k_main, cudaFuncAttributeMaxDynamicSharedMemorySize, 31296);

    k_prep<<<96, 256>>>(Wm1, Wm2, data);
    k_adj<<<1, 1024>>>(Ws1, bs1, Ws2, bs2, Ws3, bs3, out_adj);
    k_main<<<512, 256, 31296>>>(data, bm1, bm2, Wm3, bm3, Wt1, bt1, Wt2, bt2, out_pred);
    k_fin<<<30, 256>>>(out_scores);
}

// round 15
// speedup vs baseline: 3.8207x; 1.0007x over previous
#include <cuda_runtime.h>
#include <cuda_fp16.h>
#include <math.h>

#define NV 16

// ---------------- device scratch ----------------
__device__ float g_pm[240];
__device__ float g_hp[16];
__device__ float g_part[240 * 64];
__device__ unsigned g_wpack[16 * 5120];    // per-v fp16 fragments: W1 1024 + W2 4096
__device__ float g_gram[32 * 256];
__device__ float g_colsum[32 * 16];

// packed f32x2 FMA (pairs path)
union F2U { float2 f; unsigned long long u; };
__device__ __forceinline__ float2 ffma2(float2 a, float2 b, float2 c) {
    F2U au, bu, cu, du;
    au.f = a; bu.f = b; cu.f = c;
    asm("fma.rn.f32x2 %0, %1, %2, %3;" : "=l"(du.u) : "l"(au.u), "l"(bu.u), "l"(cu.u));
    return du.f;
}

// fp16 m16n8k16 MMA, fp32 accumulate
__device__ __forceinline__ void mma_f16(float* d, const unsigned* a, const unsigned* b) {
    asm volatile(
        "mma.sync.aligned.m16n8k16.row.col.f32.f16.f16.f32 "
        "{%0,%1,%2,%3}, {%4,%5,%6,%7}, {%8,%9}, {%0,%1,%2,%3};"
        : "+f"(d[0]), "+f"(d[1]), "+f"(d[2]), "+f"(d[3])
        : "r"(a[0]), "r"(a[1]), "r"(a[2]), "r"(a[3]), "r"(b[0]), "r"(b[1]));
}

__device__ __forceinline__ unsigned pack2h(float a, float b) {
    __half2 h = __floats2half2_rn(a, b);
    return *reinterpret_cast<unsigned*>(&h);
}
__device__ __forceinline__ float hround(float x) {
    return __half2float(__float2half_rn(x));
}

// ---------------- Kernel P: weight prepack (blocks 0-63) + avg/Gram (blocks 64-95) ----------------
__global__ void __launch_bounds__(256) k_prep(
    const float* __restrict__ Wm1, const float* __restrict__ Wm2,
    const float* __restrict__ data)
{
    int bid = blockIdx.x, tid = threadIdx.x;
    if (bid < 64) {
        int v = bid >> 2, quarter = bid & 3;
        unsigned* dst = g_wpack + v * 5120;
        {
            int idx = quarter * 256 + tid;
            int nt = idx >> 6, lane = (idx >> 1) & 31, r = idx & 1;
            int lg = lane >> 2, lq = lane & 3;
            int n = nt * 8 + lg, kp = lq + 4 * r;
            int k0 = 2 * kp, k1 = 2 * kp + 1;
            float w0 = (k0 < 15) ? Wm1[v * 1920 + k0 * 128 + n] : 0.f;
            float w1 = (k1 < 15) ? Wm1[v * 1920 + k1 * 128 + n] : 0.f;
            dst[idx] = pack2h(w0, w1);
        }
        for (int idx = quarter * 1024 + tid; idx < quarter * 1024 + 1024; idx += 256) {
            int ks = idx >> 9, nt = (idx >> 6) & 7, lane = (idx >> 1) & 31, r = idx & 1;
            int lg = lane >> 2, lq = lane & 3;
            int n = nt * 8 + lg, kp = ks * 8 + lq + 4 * r;
            int k0 = 2 * kp, k1 = 2 * kp + 1;
            float w0 = Wm2[v * 8192 + k0 * 64 + n];
            float w1 = Wm2[v * 8192 + k1 * 64 + n];
            dst[1024 + idx] = pack2h(w0, w1);
        }
    } else {
        __shared__ float avs[256];
        int q = bid - 64;
        float s = 0.f;
#pragma unroll
        for (int b = 0; b < 16; b++) s += data[b * 8192 + q * 256 + tid];
        avs[tid] = s * (1.f / 16.f);
        __syncthreads();
        int i = tid >> 4, j = tid & 15;
        float g = 0.f;
#pragma unroll
        for (int r = 0; r < 16; r++) g += avs[r * 16 + i] * avs[r * 16 + j];
        g_gram[q * 256 + tid] = g;
        if (tid < 16) {
            float cs = 0.f;
#pragma unroll
            for (int r = 0; r < 16; r++) cs += avs[r * 16 + tid];
            g_colsum[q * 16 + tid] = cs;
        }
    }
}

// ---------------- Kernel A: corr -> MLP -> adj -> masks ----------------
__global__ void __launch_bounds__(1024) k_adj(
    const float* __restrict__ Ws1, const float* __restrict__ bs1,
    const float* __restrict__ Ws2, const float* __restrict__ bs2,
    const float* __restrict__ Ws3, const float* __restrict__ bs3,
    float* __restrict__ out_adj)
{
    __shared__ float scratch[1024];
    __shared__ float cm[16];
    __shared__ float covs[256];
    __shared__ float corr_s[256];
    __shared__ float h1s[256];
    __shared__ float h2s[128];
    __shared__ float adj_s[256];
    __shared__ float pms[240];

    int tid = threadIdx.x;
    {
        int pr = tid & 255, q4 = tid >> 8;
        float s = 0.f;
#pragma unroll
        for (int q = q4 * 8; q < q4 * 8 + 8; q++) s += g_gram[q * 256 + pr];
        scratch[tid] = s;
    }
    if (tid < 16) {
        float s = 0.f;
#pragma unroll
        for (int q = 0; q < 32; q++) s += g_colsum[q * 16 + tid];
        cm[tid] = s * (1.f / 512.f);
    }
    __syncthreads();
    if (tid < 256) {
        float G = scratch[tid] + scratch[256 + tid] + scratch[512 + tid] + scratch[768 + tid];
        int i = tid >> 4, j = tid & 15;
        covs[tid] = G - 512.f * cm[i] * cm[j];
    }
    __syncthreads();
    if (tid < 256) {
        int i = tid >> 4, j = tid & 15;
        float si = sqrtf(fmaxf(covs[i * 16 + i], 0.f));
        float sj = sqrtf(fmaxf(covs[j * 16 + j], 0.f));
        float denom = si * sj;
        float c = denom > 0.f ? covs[tid] / denom : 0.f;
        c = fabsf(c);
        if (i == j) c = 0.f;
        corr_s[tid] = c;
    }
    __syncthreads();

    {
        int o = tid & 255, q = tid >> 8;
        float s = 0.f;
        for (int k = q * 64; k < q * 64 + 64; k++) s = fmaf(corr_s[k], Ws1[k * 256 + o], s);
        scratch[q * 256 + o] = s;
    }
    __syncthreads();
    if (tid < 256)
        h1s[tid] = fmaxf(scratch[tid] + scratch[256 + tid] + scratch[512 + tid] + scratch[768 + tid] + bs1[tid], 0.f);
    __syncthreads();

    {
        int o = tid & 127, q = tid >> 7;
        float s = 0.f;
        for (int k = q * 32; k < q * 32 + 32; k++) s = fmaf(h1s[k], Ws2[k * 128 + o], s);
        scratch[q * 128 + o] = s;
    }
    __syncthreads();
    if (tid < 128) {
        float s = bs2[tid];
        for (int q = 0; q < 8; q++) s += scratch[q * 128 + tid];
        h2s[tid] = fmaxf(s, 0.f);
    }
    __syncthreads();

    {
        int o = tid & 255, q = tid >> 8;
        float s = 0.f;
        for (int k = q * 32; k < q * 32 + 32; k++) s = fmaf(h2s[k], Ws3[k * 256 + o], s);
        scratch[q * 256 + o] = s;
    }
    __syncthreads();
    if (tid < 256) {
        float logit = scratch[tid] + scratch[256 + tid] + scratch[512 + tid] + scratch[768 + tid] + bs3[tid];
        float a = 1.f / (1.f + expf(-logit));
        int i = tid >> 4, j = tid & 15;
        float val = (j > i) ? a : 0.f;
        adj_s[tid] = val;
        out_adj[tid] = val;
    }
    __syncthreads();
    if (tid < 240) {
        int v = tid / 15, p = tid - v * 15;
        int g = p + (p >= v ? 1 : 0);
        float m = (adj_s[g * 16 + v] > 0.5f) ? 1.f : 0.f;
        pms[tid] = m;
        g_pm[tid] = m;
    }
    __syncthreads();
    if (tid < 16) {
        float s = 0.f;
        for (int p = 0; p < 15; p++) s += pms[tid * 15 + p];
        g_hp[tid] = (s > 0.f) ? 1.f : 0.f;
    }
}

// ---- mech helpers (fp16, 2-term A-split layer 1, hi-only layer 2) ----
__device__ __forceinline__ void l1_step(const unsigned* W1s, int lane, int ks,
    const unsigned* ahi, const unsigned* alo, float* a, float* b)
{
    int nt0 = 2 * ks, nt1 = nt0 + 1;
    const unsigned* b0p = W1s + (nt0 * 32 + lane) * 2;
    const unsigned* b1p = W1s + (nt1 * 32 + lane) * 2;
    unsigned b0v[2] = { b0p[0], b0p[1] }, b1v[2] = { b1p[0], b1p[1] };
    mma_f16(a, ahi, b0v);
    mma_f16(b, ahi, b1v);
    mma_f16(a, alo, b0v);
    mma_f16(b, alo, b1v);
}

__device__ __forceinline__ void l1_epi_hi(const float* b1s, int lq, int ks,
    const float* a, const float* b, unsigned* a2hi)
{
    float2 bva = *(const float2*)(b1s + (2 * ks) * 8 + 2 * lq);
    float2 bvb = *(const float2*)(b1s + (2 * ks + 1) * 8 + 2 * lq);
    float h0 = fmaxf(a[0] + bva.x, 0.f), h1 = fmaxf(a[1] + bva.y, 0.f);
    float h2 = fmaxf(a[2] + bva.x, 0.f), h3 = fmaxf(a[3] + bva.y, 0.f);
    float h4 = fmaxf(b[0] + bvb.x, 0.f), h5 = fmaxf(b[1] + bvb.y, 0.f);
    float h6 = fmaxf(b[2] + bvb.x, 0.f), h7 = fmaxf(b[3] + bvb.y, 0.f);
    a2hi[0] = pack2h(h0, h1);
    a2hi[1] = pack2h(h2, h3);
    a2hi[2] = pack2h(h4, h5);
    a2hi[3] = pack2h(h6, h7);
}

// ---------------- Kernel M: FUSED mech (odd blocks) + pairs (even blocks) ----------------
// Interleaved mapping: each SM's 2 resident CTAs are typically 1 mech (tensor pipe)
// + 1 pairs (fp32/MUFU pipe) -> complementary-pipe overlap instead of serial waves.
__global__ void __launch_bounds__(256, 2) k_main(
    const float* __restrict__ data,
    const float* __restrict__ bm1, const float* __restrict__ bm2,
    const float* __restrict__ Wm3, const float* __restrict__ bm3,
    const float* __restrict__ Wt1, const float* __restrict__ bt1,
    const float* __restrict__ Wt2, const float* __restrict__ bt2,
    float* __restrict__ out_pred)
{
    extern __shared__ float sm[];
    int tid = threadIdx.x;
    int role = blockIdx.x & 1;       // 0 = mech, 1 = pairs
    int sub = blockIdx.x >> 1;       // 0..255 within role

    if (role == 0) {
        // ================= MECH =================
        const int bx = sub & 15;
        const int v = sub >> 4;
        unsigned* Wp  = (unsigned*)sm;
        float* b1s  = sm + 5120;
        float* b2s  = sm + 5248;
        float* w3s  = sm + 5312;
        float* pms  = sm + 5376;
        float* rawv = sm + 5392;
        unsigned* Xh  = (unsigned*)(sm + 5520);
        unsigned* Xl  = (unsigned*)(sm + 6672);

        int w = tid >> 5, lane = tid & 31;
        int lq = lane & 3, lg = lane >> 2;

        {
            const float4* src = (const float4*)(g_wpack + v * 5120);
            float4* dst = (float4*)Wp;
            for (int i = tid; i < 1280; i += 256) dst[i] = src[i];
        }
        if (tid < 128) b1s[tid] = bm1[v * 128 + tid];
        if (tid < 64) { b2s[tid] = bm2[v * 64 + tid]; w3s[tid] = Wm3[v * 64 + tid]; }
        if (tid < 16) pms[tid] = (tid < 15) ? g_pm[v * 15 + tid] : 0.f;
        float hp = g_hp[v];
        float b3 = bm3[v];

        const unsigned* W1s = Wp;
        const unsigned* W2s = Wp + 1024;
        int rA = w * 16 + lg;

        for (int tile = 0; tile < 4; tile++) {
            __syncthreads();
            int row0 = bx * 512 + tile * 128;
            for (int idx = tid; idx < 1024; idx += 256) {
                int row = idx >> 3, kp = idx & 7;
                int p0 = 2 * kp, p1 = 2 * kp + 1;
                const float* drow = data + (row0 + row) * 16;
                float v0 = 0.f, v1 = 0.f;
                v0 = drow[p0 + (p0 >= v ? 1 : 0)] * pms[p0];
                if (p1 < 15) v1 = drow[p1 + (p1 >= v ? 1 : 0)] * pms[p1];
                Xh[row * 9 + kp] = pack2h(v0, v1);
                Xl[row * 9 + kp] = pack2h(v0 - hround(v0), v1 - hround(v1));
            }
            if (tid < 128) rawv[tid] = data[(row0 + tid) * 16 + v];
            __syncthreads();

            unsigned ahi[4], alo[4];
            ahi[0] = Xh[rA * 9 + lq];           ahi[1] = Xh[(rA + 8) * 9 + lq];
            ahi[2] = Xh[rA * 9 + lq + 4];       ahi[3] = Xh[(rA + 8) * 9 + lq + 4];
            alo[0] = Xl[rA * 9 + lq];           alo[1] = Xl[(rA + 8) * 9 + lq];
            alo[2] = Xl[rA * 9 + lq + 4];       alo[3] = Xl[(rA + 8) * 9 + lq + 4];

            float acc2[8][4];
#pragma unroll
            for (int nt = 0; nt < 8; nt++)
#pragma unroll
                for (int i = 0; i < 4; i++) acc2[nt][i] = 0.f;

            unsigned c2hi[4];
            {
                float a1[4] = {0.f, 0.f, 0.f, 0.f}, b1r[4] = {0.f, 0.f, 0.f, 0.f};
                l1_step(W1s, lane, 0, ahi, alo, a1, b1r);
                l1_epi_hi(b1s, lq, 0, a1, b1r, c2hi);
            }
#pragma unroll
            for (int ks = 0; ks < 8; ks++) {
                float n1a[4] = {0.f, 0.f, 0.f, 0.f}, n1b[4] = {0.f, 0.f, 0.f, 0.f};
                if (ks < 7) l1_step(W1s, lane, ks + 1, ahi, alo, n1a, n1b);
#pragma unroll
                for (int nt = 0; nt < 8; nt++) {
                    const unsigned* bp = W2s + (ks * 256 + nt * 32 + lane) * 2;
                    unsigned bv[2] = { bp[0], bp[1] };
                    mma_f16(acc2[nt], c2hi, bv);
                }
                if (ks < 7) l1_epi_hi(b1s, lq, ks + 1, n1a, n1b, c2hi);
            }

            float sA = 0.f, sB = 0.f;
#pragma unroll
            for (int nt = 0; nt < 8; nt++) {
                float2 bv = *(const float2*)(b2s + nt * 8 + 2 * lq);
                float2 wv = *(const float2*)(w3s + nt * 8 + 2 * lq);
                sA = fmaf(fmaxf(acc2[nt][0] + bv.x, 0.f), wv.x, sA);
                sA = fmaf(fmaxf(acc2[nt][1] + bv.y, 0.f), wv.y, sA);
                sB = fmaf(fmaxf(acc2[nt][2] + bv.x, 0.f), wv.x, sB);
                sB = fmaf(fmaxf(acc2[nt][3] + bv.y, 0.f), wv.y, sB);
            }
            sA += __shfl_xor_sync(0xffffffffu, sA, 1);
            sA += __shfl_xor_sync(0xffffffffu, sA, 2);
            sB += __shfl_xor_sync(0xffffffffu, sB, 1);
            sB += __shfl_xor_sync(0xffffffffu, sB, 2);
            if (lq == 0) {
                float pA = (hp > 0.f) ? (sA + b3) : rawv[rA];
                float pB = (hp > 0.f) ? (sB + b3) : rawv[rA + 8];
                out_pred[(row0 + rA) * 16 + v] = pA;
                out_pred[(row0 + rA + 8) * 16 + v] = pB;
            }
        }
    } else {
        // ================= PAIRS =================
        float* rows = sm;                 // [128][17]
        int pg = sub & 3, chunk = sub >> 2; // 4 pair-groups x 64 chunks
        int sbase = chunk * 128;
        for (int t = tid; t < 2048; t += 256) {
            int s = t >> 4, j = t & 15;
            rows[s * 17 + j] = data[(sbase + s) * 16 + j];
        }
        __syncthreads();
        if (tid < 240) {
            int p = pg * 60 + (tid >> 2), q = tid & 3;
            int pi = p / 15, r = p - pi * 15;
            int pj = r + (r >= pi ? 1 : 0);
            int co = q * 8;
            float4 wa0 = *(const float4*)(Wt1 + p * 64 + co);
            float4 wa1 = *(const float4*)(Wt1 + p * 64 + co + 4);
            float4 wb0 = *(const float4*)(Wt1 + p * 64 + 32 + co);
            float4 wb1 = *(const float4*)(Wt1 + p * 64 + 32 + co + 4);
            float4 bb0 = *(const float4*)(bt1 + p * 32 + co);
            float4 bb1 = *(const float4*)(bt1 + p * 32 + co + 4);
            float4 w20 = *(const float4*)(Wt2 + p * 32 + co);
            float4 w21 = *(const float4*)(Wt2 + p * 32 + co + 4);
            float b2v = bt2[p];

            float accs = 0.f;
            for (int s = 0; s < 128; s += 2) {
                float aX = rows[s * 17 + pi],       bX = rows[s * 17 + pj];
                float aY = rows[(s+1) * 17 + pi],   bY = rows[(s+1) * 17 + pj];
                float2 xiX = make_float2(aX, aX), xjX = make_float2(bX, bX);
                float2 xiY = make_float2(aY, aY), xjY = make_float2(bY, bY);
                float2 sv0X = make_float2(0.f, 0.f), sv1X = make_float2(0.f, 0.f);
                float2 sv0Y = make_float2(0.f, 0.f), sv1Y = make_float2(0.f, 0.f);
                float2 h;
                h = ffma2(xiX, make_float2(wa0.x, wa0.y), make_float2(bb0.x, bb0.y));
                h = ffma2(xjX, make_float2(wb0.x, wb0.y), h);
                h.x = fmaxf(h.x, 0.f); h.y = fmaxf(h.y, 0.f);
                sv0X = ffma2(h, make_float2(w20.x, w20.y), sv0X);
                h = ffma2(xiY, make_float2(wa0.x, wa0.y), make_float2(bb0.x, bb0.y));
                h = ffma2(xjY, make_float2(wb0.x, wb0.y), h);
                h.x = fmaxf(h.x, 0.f); h.y = fmaxf(h.y, 0.f);
                sv0Y = ffma2(h, make_float2(w20.x, w20.y), sv0Y);

                h = ffma2(xiX, make_float2(wa0.z, wa0.w), make_float2(bb0.z, bb0.w));
                h = ffma2(xjX, make_float2(wb0.z, wb0.w), h);
                h.x = fmaxf(h.x, 0.f); h.y = fmaxf(h.y, 0.f);
                sv1X = ffma2(h, make_float2(w20.z, w20.w), sv1X);
                h = ffma2(xiY, make_float2(wa0.z, wa0.w), make_float2(bb0.z, bb0.w));
                h = ffma2(xjY, make_float2(wb0.z, wb0.w), h);
                h.x = fmaxf(h.x, 0.f); h.y = fmaxf(h.y, 0.f);
                sv1Y = ffma2(h, make_float2(w20.z, w20.w), sv1Y);

                h = ffma2(xiX, make_float2(wa1.x, wa1.y), make_float2(bb1.x, bb1.y));
                h = ffma2(xjX, make_float2(wb1.x, wb1.y), h);
                h.x = fmaxf(h.x, 0.f); h.y = fmaxf(h.y, 0.f);
                sv0X = ffma2(h, make_float2(w21.x, w21.y), sv0X);
                h = ffma2(xiY, make_float2(wa1.x, wa1.y), make_float2(bb1.x, bb1.y));
                h = ffma2(xjY, make_float2(wb1.x, wb1.y), h);
                h.x = fmaxf(h.x, 0.f); h.y = fmaxf(h.y, 0.f);
                sv0Y = ffma2(h, make_float2(w21.x, w21.y), sv0Y);

                h = ffma2(xiX, make_float2(wa1.z, wa1.w), make_float2(bb1.z, bb1.w));
                h = ffma2(xjX, make_float2(wb1.z, wb1.w), h);
                h.x = fmaxf(h.x, 0.f); h.y = fmaxf(h.y, 0.f);
                sv1X = ffma2(h, make_float2(w21.z, w21.w), sv1X);
                h = ffma2(xiY, make_float2(wa1.z, wa1.w), make_float2(bb1.z, bb1.w));
                h = ffma2(xjY, make_float2(wb1.z, wb1.w), h);
                h.x = fmaxf(h.x, 0.f); h.y = fmaxf(h.y, 0.f);
                sv1Y = ffma2(h, make_float2(w21.z, w21.w), sv1Y);

                float svX = (sv0X.x + sv0X.y) + (sv1X.x + sv1X.y);
                float svY = (sv0Y.x + sv0Y.y) + (sv1Y.x + sv1Y.y);
                svX += __shfl_xor_sync(0xffffffffu, svX, 1);
                svY += __shfl_xor_sync(0xffffffffu, svY, 1);
                svX += __shfl_xor_sync(0xffffffffu, svX, 2);
                svY += __shfl_xor_sync(0xffffffffu, svY, 2);
                accs += __fdividef(1.f, 1.f + __expf(-(svX + b2v)));
                accs += __fdividef(1.f, 1.f + __expf(-(svY + b2v)));
            }
            if (q == 0) g_part[p * 64 + chunk] = accs;
        }
    }
}

// ---------------- Kernel D: finalize (30 blocks, warp-per-pair, coalesced) ----------------
__global__ void __launch_bounds__(256) k_fin(float* __restrict__ out_scores) {
    int w = threadIdx.x >> 5, lane = threadIdx.x & 31;
    int p = blockIdx.x * 8 + w;     // 30 blocks * 8 warps = 240 pairs
    float s = g_part[p * 64 + lane] + g_part[p * 64 + 32 + lane];
#pragma unroll
    for (int off = 16; off > 0; off >>= 1)
        s += __shfl_xor_sync(0xffffffffu, s, off);
    if (lane == 0) {
        int pi = p / 15, r = p - pi * 15;
        int pj = r + (r >= pi ? 1 : 0);
        out_scores[pi * 16 + pj] = s * (1.f / 8192.f);
    }
    if (blockIdx.x == 0 && w == 0 && lane < 16) out_scores[lane * 17] = 0.f;
}

// ---------------- launch ----------------
extern "C" void kernel_launch(void* const* d_in, const int* in_sizes, int n_in,
                              void* d_out, int out_size) {
    const float* data = (const float*)d_in[0];
    const float* Ws1 = (const float*)d_in[1];
    const float* bs1 = (const float*)d_in[2];
    const float* Ws2 = (const float*)d_in[3];
    const float* bs2 = (const float*)d_in[4];
    const float* Ws3 = (const float*)d_in[5];
    const float* bs3 = (const float*)d_in[6];
    const float* Wm1 = (const float*)d_in[7];
    const float* bm1 = (const float*)d_in[8];
    const float* Wm2 = (const float*)d_in[9];
    const float* bm2 = (const float*)d_in[10];
    const float* Wm3 = (const float*)d_in[11];
    const float* bm3 = (const float*)d_in[12];
    const float* Wt1 = (const float*)d_in[13];
    const float* bt1 = (const float*)d_in[14];
    const float* Wt2 = (const float*)d_in[15];
    const float* bt2 = (const float*)d_in[16];

    float* out = (float*)d_out;
    float* out_adj    = out;
    float* out_pred   = out + 256;
    float* out_scores = out + 256 + 131072;

    cudaFuncSetAttribute(k_main, cudaFuncAttributeMaxDynamicSharedMemorySize, 31296);

    k_prep<<<96, 256>>>(Wm1, Wm2, data);
    k_adj<<<1, 1024>>>(Ws1, bs1, Ws2, bs2, Ws3, bs3, out_adj);
    k_main<<<512, 256, 31296>>>(data, bm1, bm2, Wm3, bm3, Wt1, bt1, Wt2, bt2, out_pred);
    k_fin<<<30, 256>>>(out_scores);
}

// round 16
// speedup vs baseline: 4.1785x; 1.0936x over previous
#include <cuda_runtime.h>
#include <cuda_fp16.h>
#include <math.h>

#define NV 16

// ---------------- device scratch ----------------
__device__ float g_pm[240];
__device__ float g_hp[16];
__device__ float g_part[240 * 4];
__device__ unsigned g_wpack[16 * 5120];    // per-v fp16 fragments: W1 1024 + W2 4096
__device__ float g_gram[32 * 256];
__device__ float g_colsum[32 * 16];

// packed f32x2 FMA (pairs path)
union F2U { float2 f; unsigned long long u; };
__device__ __forceinline__ float2 ffma2(float2 a, float2 b, float2 c) {
    F2U au, bu, cu, du;
    au.f = a; bu.f = b; cu.f = c;
    asm("fma.rn.f32x2 %0, %1, %2, %3;" : "=l"(du.u) : "l"(au.u), "l"(bu.u), "l"(cu.u));
    return du.f;
}

// fp16 m16n8k16 MMA, fp32 accumulate
__device__ __forceinline__ void mma_f16(float* d, const unsigned* a, const unsigned* b) {
    asm volatile(
        "mma.sync.aligned.m16n8k16.row.col.f32.f16.f16.f32 "
        "{%0,%1,%2,%3}, {%4,%5,%6,%7}, {%8,%9}, {%0,%1,%2,%3};"
        : "+f"(d[0]), "+f"(d[1]), "+f"(d[2]), "+f"(d[3])
        : "r"(a[0]), "r"(a[1]), "r"(a[2]), "r"(a[3]), "r"(b[0]), "r"(b[1]));
}

__device__ __forceinline__ unsigned pack2h(float a, float b) {
    __half2 h = __floats2half2_rn(a, b);
    return *reinterpret_cast<unsigned*>(&h);
}
__device__ __forceinline__ float hround(float x) {
    return __half2float(__float2half_rn(x));
}

// ---------------- Kernel P: weight prepack (blocks 0-63) + avg/Gram (blocks 64-95) ----------------
__global__ void __launch_bounds__(256) k_prep(
    const float* __restrict__ Wm1, const float* __restrict__ Wm2,
    const float* __restrict__ data)
{
    int bid = blockIdx.x, tid = threadIdx.x;
    if (bid < 64) {
        int v = bid >> 2, quarter = bid & 3;
        unsigned* dst = g_wpack + v * 5120;
        {
            int idx = quarter * 256 + tid;
            int nt = idx >> 6, lane = (idx >> 1) & 31, r = idx & 1;
            int lg = lane >> 2, lq = lane & 3;
            int n = nt * 8 + lg, kp = lq + 4 * r;
            int k0 = 2 * kp, k1 = 2 * kp + 1;
            float w0 = (k0 < 15) ? Wm1[v * 1920 + k0 * 128 + n] : 0.f;
            float w1 = (k1 < 15) ? Wm1[v * 1920 + k1 * 128 + n] : 0.f;
            dst[idx] = pack2h(w0, w1);
        }
        for (int idx = quarter * 1024 + tid; idx < quarter * 1024 + 1024; idx += 256) {
            int ks = idx >> 9, nt = (idx >> 6) & 7, lane = (idx >> 1) & 31, r = idx & 1;
            int lg = lane >> 2, lq = lane & 3;
            int n = nt * 8 + lg, kp = ks * 8 + lq + 4 * r;
            int k0 = 2 * kp, k1 = 2 * kp + 1;
            float w0 = Wm2[v * 8192 + k0 * 64 + n];
            float w1 = Wm2[v * 8192 + k1 * 64 + n];
            dst[1024 + idx] = pack2h(w0, w1);
        }
    } else {
        __shared__ float avs[256];
        int q = bid - 64;
        float s = 0.f;
#pragma unroll
        for (int b = 0; b < 16; b++) s += data[b * 8192 + q * 256 + tid];
        avs[tid] = s * (1.f / 16.f);
        __syncthreads();
        int i = tid >> 4, j = tid & 15;
        float g = 0.f;
#pragma unroll
        for (int r = 0; r < 16; r++) g += avs[r * 16 + i] * avs[r * 16 + j];
        g_gram[q * 256 + tid] = g;
        if (tid < 16) {
            float cs = 0.f;
#pragma unroll
            for (int r = 0; r < 16; r++) cs += avs[r * 16 + tid];
            g_colsum[q * 16 + tid] = cs;
        }
    }
}

// ---------------- Kernel A: corr -> MLP -> adj -> masks ----------------
__global__ void __launch_bounds__(1024) k_adj(
    const float* __restrict__ Ws1, const float* __restrict__ bs1,
    const float* __restrict__ Ws2, const float* __restrict__ bs2,
    const float* __restrict__ Ws3, const float* __restrict__ bs3,
    float* __restrict__ out_adj)
{
    __shared__ float scratch[1024];
    __shared__ float cm[16];
    __shared__ float covs[256];
    __shared__ float corr_s[256];
    __shared__ float h1s[256];
    __shared__ float h2s[128];
    __shared__ float adj_s[256];
    __shared__ float pms[240];

    int tid = threadIdx.x;
    {
        int pr = tid & 255, q4 = tid >> 8;
        float s = 0.f;
#pragma unroll
        for (int q = q4 * 8; q < q4 * 8 + 8; q++) s += g_gram[q * 256 + pr];
        scratch[tid] = s;
    }
    if (tid < 16) {
        float s = 0.f;
#pragma unroll
        for (int q = 0; q < 32; q++) s += g_colsum[q * 16 + tid];
        cm[tid] = s * (1.f / 512.f);
    }
    __syncthreads();
    if (tid < 256) {
        float G = scratch[tid] + scratch[256 + tid] + scratch[512 + tid] + scratch[768 + tid];
        int i = tid >> 4, j = tid & 15;
        covs[tid] = G - 512.f * cm[i] * cm[j];
    }
    __syncthreads();
    if (tid < 256) {
        int i = tid >> 4, j = tid & 15;
        float si = sqrtf(fmaxf(covs[i * 16 + i], 0.f));
        float sj = sqrtf(fmaxf(covs[j * 16 + j], 0.f));
        float denom = si * sj;
        float c = denom > 0.f ? covs[tid] / denom : 0.f;
        c = fabsf(c);
        if (i == j) c = 0.f;
        corr_s[tid] = c;
    }
    __syncthreads();

    {
        int o = tid & 255, q = tid >> 8;
        float s = 0.f;
        for (int k = q * 64; k < q * 64 + 64; k++) s = fmaf(corr_s[k], Ws1[k * 256 + o], s);
        scratch[q * 256 + o] = s;
    }
    __syncthreads();
    if (tid < 256)
        h1s[tid] = fmaxf(scratch[tid] + scratch[256 + tid] + scratch[512 + tid] + scratch[768 + tid] + bs1[tid], 0.f);
    __syncthreads();

    {
        int o = tid & 127, q = tid >> 7;
        float s = 0.f;
        for (int k = q * 32; k < q * 32 + 32; k++) s = fmaf(h1s[k], Ws2[k * 128 + o], s);
        scratch[q * 128 + o] = s;
    }
    __syncthreads();
    if (tid < 128) {
        float s = bs2[tid];
        for (int q = 0; q < 8; q++) s += scratch[q * 128 + tid];
        h2s[tid] = fmaxf(s, 0.f);
    }
    __syncthreads();

    {
        int o = tid & 255, q = tid >> 8;
        float s = 0.f;
        for (int k = q * 32; k < q * 32 + 32; k++) s = fmaf(h2s[k], Ws3[k * 256 + o], s);
        scratch[q * 256 + o] = s;
    }
    __syncthreads();
    if (tid < 256) {
        float logit = scratch[tid] + scratch[256 + tid] + scratch[512 + tid] + scratch[768 + tid] + bs3[tid];
        float a = 1.f / (1.f + expf(-logit));
        int i = tid >> 4, j = tid & 15;
        float val = (j > i) ? a : 0.f;
        adj_s[tid] = val;
        out_adj[tid] = val;
    }
    __syncthreads();
    if (tid < 240) {
        int v = tid / 15, p = tid - v * 15;
        int g = p + (p >= v ? 1 : 0);
        float m = (adj_s[g * 16 + v] > 0.5f) ? 1.f : 0.f;
        pms[tid] = m;
        g_pm[tid] = m;
    }
    __syncthreads();
    if (tid < 16) {
        float s = 0.f;
        for (int p = 0; p < 15; p++) s += pms[tid * 15 + p];
        g_hp[tid] = (s > 0.f) ? 1.f : 0.f;
    }
}

// ---- mech helpers (fp16, 2-term A-split layer 1, hi-only layer 2) ----
__device__ __forceinline__ void l1_step(const unsigned* W1s, int lane, int ks,
    const unsigned* ahi, const unsigned* alo, float* a, float* b)
{
    int nt0 = 2 * ks, nt1 = nt0 + 1;
    const unsigned* b0p = W1s + (nt0 * 32 + lane) * 2;
    const unsigned* b1p = W1s + (nt1 * 32 + lane) * 2;
    unsigned b0v[2] = { b0p[0], b0p[1] }, b1v[2] = { b1p[0], b1p[1] };
    mma_f16(a, ahi, b0v);
    mma_f16(b, ahi, b1v);
    mma_f16(a, alo, b0v);
    mma_f16(b, alo, b1v);
}

__device__ __forceinline__ void l1_epi_hi(const float* b1s, int lq, int ks,
    const float* a, const float* b, unsigned* a2hi)
{
    float2 bva = *(const float2*)(b1s + (2 * ks) * 8 + 2 * lq);
    float2 bvb = *(const float2*)(b1s + (2 * ks + 1) * 8 + 2 * lq);
    float h0 = fmaxf(a[0] + bva.x, 0.f), h1 = fmaxf(a[1] + bva.y, 0.f);
    float h2 = fmaxf(a[2] + bva.x, 0.f), h3 = fmaxf(a[3] + bva.y, 0.f);
    float h4 = fmaxf(b[0] + bvb.x, 0.f), h5 = fmaxf(b[1] + bvb.y, 0.f);
    float h6 = fmaxf(b[2] + bvb.x, 0.f), h7 = fmaxf(b[3] + bvb.y, 0.f);
    a2hi[0] = pack2h(h0, h1);
    a2hi[1] = pack2h(h2, h3);
    a2hi[2] = pack2h(h4, h5);
    a2hi[3] = pack2h(h6, h7);
}

// ---------------- Kernel M: FUSED pairs (blocks 0-119) + mech (blocks 120-375) ----------------
// Pairs: warp-per-pair, lane-per-sample. No per-sample shfls; one warp reduce at end.
__global__ void __launch_bounds__(256, 2) k_main(
    const float* __restrict__ data,
    const float* __restrict__ bm1, const float* __restrict__ bm2,
    const float* __restrict__ Wm3, const float* __restrict__ bm3,
    const float* __restrict__ Wt1, const float* __restrict__ bt1,
    const float* __restrict__ Wt2, const float* __restrict__ bt2,
    float* __restrict__ out_pred)
{
    extern __shared__ float sm[];
    int tid = threadIdx.x;

    if (blockIdx.x < 120) {
        // ================= PAIRS (warp-per-pair) =================
        float* rows = sm;                       // [128][17] = 2176 floats
        float* wpk  = sm + 2176;                // [8 pairs][16 ch2][8] = 1024 floats
        int b = blockIdx.x;
        int squad = b / 30;                     // 0..3 -> sample range squad*2048
        int pairbase = (b - squad * 30) * 8;
        int w = tid >> 5, lane = tid & 31;

        // stage weights for 8 pairs: [pl][ch2][wa0,wa1,wb0,wb1,b0,b1,w20,w21]
        for (int idx = tid; idx < 256; idx += 256) {}
        {
            int t4 = tid * 4;                   // 1024 floats / 256 threads
#pragma unroll
            for (int u = 0; u < 4; u++) {
                int idx = t4 + u;
                int pl = idx >> 7, rem = idx & 127;
                int ch2 = rem >> 3, f = rem & 7;
                int p = pairbase + pl;
                float val;
                if (f < 2)      val = Wt1[p * 64 + 2 * ch2 + f];
                else if (f < 4) val = Wt1[p * 64 + 32 + 2 * ch2 + (f - 2)];
                else if (f < 6) val = bt1[p * 32 + 2 * ch2 + (f - 4)];
                else            val = Wt2[p * 32 + 2 * ch2 + (f - 6)];
                wpk[idx] = val;
            }
        }

        int p = pairbase + w;
        int pi = p / 15, rr = p - pi * 15;
        int pj = rr + (rr >= pi ? 1 : 0);
        float b2v = bt2[p];
        const float* wrow = wpk + w * 128;
        float accs = 0.f;

        for (int c = 0; c < 16; c++) {
            __syncthreads();                    // rows reuse + (c==0) weight staging
            int sbase = squad * 2048 + c * 128;
            // stage 128 sample rows: coalesced LDG.128, scalar STS (pad 17)
            {
                int t = tid;                    // 512 float4 tasks / 256 thr = 2 each
#pragma unroll
                for (int u = 0; u < 2; u++) {
                    int s = t >> 2, q = t & 3;
                    float4 v = *(const float4*)(data + (sbase + s) * 16 + q * 4);
                    float* dst = rows + s * 17 + q * 4;
                    dst[0] = v.x; dst[1] = v.y; dst[2] = v.z; dst[3] = v.w;
                    t += 256;
                }
            }
            __syncthreads();

#pragma unroll
            for (int it = 0; it < 4; it++) {
                int s = it * 32 + lane;
                float xi = rows[s * 17 + pi], xj = rows[s * 17 + pj];
                float2 xi2 = make_float2(xi, xi), xj2 = make_float2(xj, xj);
                float2 sv0 = make_float2(0.f, 0.f), sv1 = make_float2(0.f, 0.f);
                float2 sv2 = make_float2(0.f, 0.f), sv3 = make_float2(0.f, 0.f);
#pragma unroll
                for (int ch2 = 0; ch2 < 16; ch2 += 4) {
#pragma unroll
                    for (int g = 0; g < 4; g++) {
                        float4 wv = *(const float4*)(wrow + (ch2 + g) * 8);       // broadcast
                        float4 bv = *(const float4*)(wrow + (ch2 + g) * 8 + 4);   // broadcast
                        float2 h = ffma2(xi2, make_float2(wv.x, wv.y), make_float2(bv.x, bv.y));
                        h = ffma2(xj2, make_float2(wv.z, wv.w), h);
                        h.x = fmaxf(h.x, 0.f); h.y = fmaxf(h.y, 0.f);
                        float2 w2 = make_float2(bv.z, bv.w);
                        if (g == 0) sv0 = ffma2(h, w2, sv0);
                        else if (g == 1) sv1 = ffma2(h, w2, sv1);
                        else if (g == 2) sv2 = ffma2(h, w2, sv2);
                        else sv3 = ffma2(h, w2, sv3);
                    }
                }
                float sv = ((sv0.x + sv0.y) + (sv1.x + sv1.y))
                         + ((sv2.x + sv2.y) + (sv3.x + sv3.y));
                accs += __fdividef(1.f, 1.f + __expf(-(sv + b2v)));
            }
        }
        // single warp reduce at the very end
#pragma unroll
        for (int off = 16; off > 0; off >>= 1)
            accs += __shfl_xor_sync(0xffffffffu, accs, off);
        if (lane == 0) g_part[p * 4 + squad] = accs;
    } else {
        // ================= MECH =================
        int sub = blockIdx.x - 120;             // 0..255
        const int bx = sub & 15;
        const int v = sub >> 4;
        unsigned* Wp  = (unsigned*)sm;
        float* b1s  = sm + 5120;
        float* b2s  = sm + 5248;
        float* w3s  = sm + 5312;
        float* pms  = sm + 5376;
        float* rawv = sm + 5392;
        unsigned* Xh  = (unsigned*)(sm + 5520);
        unsigned* Xl  = (unsigned*)(sm + 6672);

        int w = tid >> 5, lane = tid & 31;
        int lq = lane & 3, lg = lane >> 2;

        {
            const float4* src = (const float4*)(g_wpack + v * 5120);
            float4* dst = (float4*)Wp;
            for (int i = tid; i < 1280; i += 256) dst[i] = src[i];
        }
        if (tid < 128) b1s[tid] = bm1[v * 128 + tid];
        if (tid < 64) { b2s[tid] = bm2[v * 64 + tid]; w3s[tid] = Wm3[v * 64 + tid]; }
        if (tid < 16) pms[tid] = (tid < 15) ? g_pm[v * 15 + tid] : 0.f;
        float hp = g_hp[v];
        float b3 = bm3[v];

        const unsigned* W1s = Wp;
        const unsigned* W2s = Wp + 1024;
        int rA = w * 16 + lg;

        for (int tile = 0; tile < 4; tile++) {
            __syncthreads();
            int row0 = bx * 512 + tile * 128;
            for (int idx = tid; idx < 1024; idx += 256) {
                int row = idx >> 3, kp = idx & 7;
                int p0 = 2 * kp, p1 = 2 * kp + 1;
                const float* drow = data + (row0 + row) * 16;
                float v0 = 0.f, v1 = 0.f;
                v0 = drow[p0 + (p0 >= v ? 1 : 0)] * pms[p0];
                if (p1 < 15) v1 = drow[p1 + (p1 >= v ? 1 : 0)] * pms[p1];
                Xh[row * 9 + kp] = pack2h(v0, v1);
                Xl[row * 9 + kp] = pack2h(v0 - hround(v0), v1 - hround(v1));
            }
            if (tid < 128) rawv[tid] = data[(row0 + tid) * 16 + v];
            __syncthreads();

            unsigned ahi[4], alo[4];
            ahi[0] = Xh[rA * 9 + lq];           ahi[1] = Xh[(rA + 8) * 9 + lq];
            ahi[2] = Xh[rA * 9 + lq + 4];       ahi[3] = Xh[(rA + 8) * 9 + lq + 4];
            alo[0] = Xl[rA * 9 + lq];           alo[1] = Xl[(rA + 8) * 9 + lq];
            alo[2] = Xl[rA * 9 + lq + 4];       alo[3] = Xl[(rA + 8) * 9 + lq + 4];

            float acc2[8][4];
#pragma unroll
            for (int nt = 0; nt < 8; nt++)
#pragma unroll
                for (int i = 0; i < 4; i++) acc2[nt][i] = 0.f;

            unsigned c2hi[4];
            {
                float a1[4] = {0.f, 0.f, 0.f, 0.f}, b1r[4] = {0.f, 0.f, 0.f, 0.f};
                l1_step(W1s, lane, 0, ahi, alo, a1, b1r);
                l1_epi_hi(b1s, lq, 0, a1, b1r, c2hi);
            }
#pragma unroll
            for (int ks = 0; ks < 8; ks++) {
                float n1a[4] = {0.f, 0.f, 0.f, 0.f}, n1b[4] = {0.f, 0.f, 0.f, 0.f};
                if (ks < 7) l1_step(W1s, lane, ks + 1, ahi, alo, n1a, n1b);
#pragma unroll
                for (int nt = 0; nt < 8; nt++) {
                    const unsigned* bp = W2s + (ks * 256 + nt * 32 + lane) * 2;
                    unsigned bv[2] = { bp[0], bp[1] };
                    mma_f16(acc2[nt], c2hi, bv);
                }
                if (ks < 7) l1_epi_hi(b1s, lq, ks + 1, n1a, n1b, c2hi);
            }

            float sA = 0.f, sB = 0.f;
#pragma unroll
            for (int nt = 0; nt < 8; nt++) {
                float2 bv = *(const float2*)(b2s + nt * 8 + 2 * lq);
                float2 wv = *(const float2*)(w3s + nt * 8 + 2 * lq);
                sA = fmaf(fmaxf(acc2[nt][0] + bv.x, 0.f), wv.x, sA);
                sA = fmaf(fmaxf(acc2[nt][1] + bv.y, 0.f), wv.y, sA);
                sB = fmaf(fmaxf(acc2[nt][2] + bv.x, 0.f), wv.x, sB);
                sB = fmaf(fmaxf(acc2[nt][3] + bv.y, 0.f), wv.y, sB);
            }
            sA += __shfl_xor_sync(0xffffffffu, sA, 1);
            sA += __shfl_xor_sync(0xffffffffu, sA, 2);
            sB += __shfl_xor_sync(0xffffffffu, sB, 1);
            sB += __shfl_xor_sync(0xffffffffu, sB, 2);
            if (lq == 0) {
                float pA = (hp > 0.f) ? (sA + b3) : rawv[rA];
                float pB = (hp > 0.f) ? (sB + b3) : rawv[rA + 8];
                out_pred[(row0 + rA) * 16 + v] = pA;
                out_pred[(row0 + rA + 8) * 16 + v] = pB;
            }
        }
    }
}

// ---------------- Kernel D: finalize ----------------
__global__ void __launch_bounds__(256) k_fin(float* __restrict__ out_scores) {
    int t = threadIdx.x;
    if (t < 240) {
        float4 v = *(const float4*)(g_part + t * 4);
        float s = (v.x + v.y) + (v.z + v.w);
        int pi = t / 15, r = t - pi * 15;
        int pj = r + (r >= pi ? 1 : 0);
        out_scores[pi * 16 + pj] = s * (1.f / 8192.f);
    }
    if (t < 16) out_scores[t * 17] = 0.f;
}

// ---------------- launch ----------------
extern "C" void kernel_launch(void* const* d_in, const int* in_sizes, int n_in,
                              void* d_out, int out_size) {
    const float* data = (const float*)d_in[0];
    const float* Ws1 = (const float*)d_in[1];
    const float* bs1 = (const float*)d_in[2];
    const float* Ws2 = (const float*)d_in[3];
    const float* bs2 = (const float*)d_in[4];
    const float* Ws3 = (const float*)d_in[5];
    const float* bs3 = (const float*)d_in[6];
    const float* Wm1 = (const float*)d_in[7];
    const float* bm1 = (const float*)d_in[8];
    const float* Wm2 = (const float*)d_in[9];
    const float* bm2 = (const float*)d_in[10];
    const float* Wm3 = (const float*)d_in[11];
    const float* bm3 = (const float*)d_in[12];
    const float* Wt1 = (const float*)d_in[13];
    const float* bt1 = (const float*)d_in[14];
    const float* Wt2 = (const float*)d_in[15];
    const float* bt2 = (const float*)d_in[16];

    float* out = (float*)d_out;
    float* out_adj    = out;
    float* out_pred   = out + 256;
    float* out_scores = out + 256 + 131072;

    cudaFuncSetAttribute(k_main, cudaFuncAttributeMaxDynamicSharedMemorySize, 31296);

    k_prep<<<96, 256>>>(Wm1, Wm2, data);
    k_adj<<<1, 1024>>>(Ws1, bs1, Ws2, bs2, Ws3, bs3, out_adj);
    k_main<<<376, 256, 31296>>>(data, bm1, bm2, Wm3, bm3, Wt1, bt1, Wt2, bt2, out_pred);
    k_fin<<<1, 256>>>(out_scores);
}